// round 6
// baseline (speedup 1.0000x reference)
#include <cuda_runtime.h>
#include <cuda_bf16.h>
#include <cstdint>
#include <cstddef>

// ---------------------------------------------------------------------------
// Problem constants
// ---------------------------------------------------------------------------
#define B_  2
#define S_  2048
#define D_  2048
#define H_  16
#define HD_ 128
#define M_  (B_*S_)            // 4096 rows
#define SCALE_ 0.08838834764831845f

// ---------------------------------------------------------------------------
// Scratch (__device__ globals; no allocation allowed)
// ---------------------------------------------------------------------------
__device__ __nv_bfloat16 g_xhi[(size_t)M_ * D_];
__device__ __nv_bfloat16 g_xlo[(size_t)M_ * D_];
__device__ __nv_bfloat16 g_w1hi[(size_t)3 * D_ * D_];   // Wqkv^T [6144,2048]
__device__ __nv_bfloat16 g_w1lo[(size_t)3 * D_ * D_];
__device__ __nv_bfloat16 g_w2hi[(size_t)D_ * D_];       // Wo^T [2048,2048]
__device__ __nv_bfloat16 g_w2lo[(size_t)D_ * D_];
// q/k/v in [B,H,S,HD] bf16 hi/lo (q pre-scaled by 1/sqrt(HD))
__device__ __nv_bfloat16 g_qhi[(size_t)M_ * D_];
__device__ __nv_bfloat16 g_qlo[(size_t)M_ * D_];
__device__ __nv_bfloat16 g_khi[(size_t)M_ * D_];
__device__ __nv_bfloat16 g_klo[(size_t)M_ * D_];
__device__ __nv_bfloat16 g_vhi[(size_t)M_ * D_];
__device__ __nv_bfloat16 g_vlo[(size_t)M_ * D_];
// attention output [B,S,D] bf16 hi/lo
__device__ __nv_bfloat16 g_ahi[(size_t)M_ * D_];
__device__ __nv_bfloat16 g_alo[(size_t)M_ * D_];

// ---------------------------------------------------------------------------
// Portable PTX helpers (virtual arch compute_103: no tcgen05)
// ---------------------------------------------------------------------------
__device__ __forceinline__ uint32_t smem_u32(const void* p) {
    uint32_t a;
    asm("{ .reg .u64 t; cvta.to.shared.u64 t, %1; cvt.u32.u64 %0, t; }"
        : "=r"(a) : "l"(p));
    return a;
}

#define CP16(dst_u32, src_ptr) \
    asm volatile("cp.async.cg.shared.global [%0], [%1], 16;" \
                 :: "r"(dst_u32), "l"(src_ptr) : "memory")
#define CP_COMMIT() asm volatile("cp.async.commit_group;" ::: "memory")
#define CP_WAIT(n)  asm volatile("cp.async.wait_group %0;" :: "n"(n) : "memory")

#define LDSM_X4(r0, r1, r2, r3, addr) \
    asm volatile("ldmatrix.sync.aligned.m8n8.x4.shared.b16 {%0,%1,%2,%3}, [%4];" \
                 : "=r"(r0), "=r"(r1), "=r"(r2), "=r"(r3) : "r"(addr))
#define LDSM_X4T(r0, r1, r2, r3, addr) \
    asm volatile("ldmatrix.sync.aligned.m8n8.x4.trans.shared.b16 {%0,%1,%2,%3}, [%4];" \
                 : "=r"(r0), "=r"(r1), "=r"(r2), "=r"(r3) : "r"(addr))

__device__ __forceinline__ void mma16816(float* d, const uint32_t* a,
                                         const uint32_t* b) {
    asm volatile(
        "mma.sync.aligned.m16n8k16.row.col.f32.bf16.bf16.f32 "
        "{%0,%1,%2,%3}, {%4,%5,%6,%7}, {%8,%9}, {%0,%1,%2,%3};"
        : "+f"(d[0]), "+f"(d[1]), "+f"(d[2]), "+f"(d[3])
        : "r"(a[0]), "r"(a[1]), "r"(a[2]), "r"(a[3]), "r"(b[0]), "r"(b[1]));
}

__device__ __forceinline__ void split1(float v, __nv_bfloat16& h, __nv_bfloat16& l) {
    h = __float2bfloat16(v);
    l = __float2bfloat16(v - __bfloat162float(h));
}

// pack two floats -> bf16x2 hi + bf16x2 lo(residual)
__device__ __forceinline__ void packhl(float x, float y, uint32_t& hp, uint32_t& lp) {
    __nv_bfloat162 hv = __floats2bfloat162_rn(x, y);
    float rx = x - __bfloat162float(__low2bfloat16(hv));
    float ry = y - __bfloat162float(__high2bfloat16(hv));
    __nv_bfloat162 lv = __floats2bfloat162_rn(rx, ry);
    hp = *reinterpret_cast<uint32_t*>(&hv);
    lp = *reinterpret_cast<uint32_t*>(&lv);
}

// ---------------------------------------------------------------------------
// split / transpose-split pre-passes
// ---------------------------------------------------------------------------
__global__ void split_f32(const float* __restrict__ in,
                          __nv_bfloat16* __restrict__ hi,
                          __nv_bfloat16* __restrict__ lo, int n4) {
    int i = blockIdx.x * blockDim.x + threadIdx.x;
    if (i >= n4) return;
    float4 v = *(const float4*)(in + (size_t)i * 4);
    uint32_t h0, h1, l0, l1;
    packhl(v.x, v.y, h0, l0);
    packhl(v.z, v.w, h1, l1);
    uint32_t* hp = (uint32_t*)(hi + (size_t)i * 4);
    uint32_t* lp = (uint32_t*)(lo + (size_t)i * 4);
    hp[0] = h0; hp[1] = h1;
    lp[0] = l0; lp[1] = l1;
}

__global__ void transpose_split(const float* __restrict__ W,
                                __nv_bfloat16* __restrict__ Th,
                                __nv_bfloat16* __restrict__ Tl, int K, int N) {
    __shared__ float t[32][33];
    int n0 = blockIdx.x * 32, k0 = blockIdx.y * 32;
    int tx = threadIdx.x, ty = threadIdx.y;      // (32,8)
    #pragma unroll
    for (int j = 0; j < 32; j += 8)
        t[ty + j][tx] = W[(size_t)(k0 + ty + j) * N + n0 + tx];
    __syncthreads();
    #pragma unroll
    for (int j = 0; j < 32; j += 8) {
        float v = t[tx][ty + j];
        __nv_bfloat16 h, l; split1(v, h, l);
        size_t o = (size_t)(n0 + ty + j) * K + k0 + tx;
        Th[o] = h; Tl[o] = l;
    }
}

// ---------------------------------------------------------------------------
// HMMA bf16x3 GEMM:  C = A @ Bt^T + bias.   BM=128, BN=256, BK=32,
// 8 warps (2x4), warp tile 64x64, 4-stage cp.async, XOR-swizzled smem.
// MODE 0: fp32 C epilogue.  MODE 1: qkv scatter epilogue.
// ---------------------------------------------------------------------------
#define GBK 32
// 64B rows, chunk swizzle: chunk ^= (row>>1)&3  (conflict-free LDSM + stores)
#define GSWZ(r, c) ((uint32_t)(r) * 64u + ((((uint32_t)(c) ^ (((uint32_t)(r) >> 1) & 3u))) << 4))
#define OFF_AH 0
#define OFF_AL 8192                   // 128 rows * 64B
#define OFF_BH 16384
#define OFF_BL 32768                  // B: 256 rows * 64B
#define STAGEB 49152
#define NSTAGE 4
#define GEMM_DYN_SMEM (NSTAGE * STAGEB)   // 196608

template <int MODE>
__global__ __launch_bounds__(256, 1) void gemm_bf16x3(
    const __nv_bfloat16* __restrict__ Ah, const __nv_bfloat16* __restrict__ Al,
    const __nv_bfloat16* __restrict__ Bh, const __nv_bfloat16* __restrict__ Bl,
    const float* __restrict__ bias, float* __restrict__ C,
    __nv_bfloat16* __restrict__ qh, __nv_bfloat16* __restrict__ ql,
    __nv_bfloat16* __restrict__ kh, __nv_bfloat16* __restrict__ kl,
    __nv_bfloat16* __restrict__ vh, __nv_bfloat16* __restrict__ vl,
    int M, int N, int K)
{
    extern __shared__ __align__(128) char sm[];
    const uint32_t sbase = smem_u32(sm);

    const int tid = threadIdx.x;
    const int wid = tid >> 5;
    const int lane = tid & 31;
    const int m0 = blockIdx.y * 128;
    const int n0 = blockIdx.x * 256;
    const int wm = (wid >> 2) * 64;      // 0 / 64
    const int wn = (wid & 3) * 64;       // 0/64/128/192

    // ---- producer: pointers hoisted; advance by GBK per stage ----
    const int tr = tid >> 2;             // 0..63
    const int pc = tid & 3;              // chunk 0..3
    const __nv_bfloat16* pA0h = Ah + (size_t)(m0 + tr) * K + pc * 8;
    const __nv_bfloat16* pA1h = pA0h + (size_t)64 * K;
    const __nv_bfloat16* pA0l = Al + (size_t)(m0 + tr) * K + pc * 8;
    const __nv_bfloat16* pA1l = pA0l + (size_t)64 * K;
    const __nv_bfloat16* pB0h = Bh + (size_t)(n0 + tr) * K + pc * 8;
    const __nv_bfloat16* pB0l = Bl + (size_t)(n0 + tr) * K + pc * 8;
    const uint32_t dA0 = GSWZ(tr, pc);
    const uint32_t dA1 = GSWZ(tr + 64, pc);
    const uint32_t dB0 = GSWZ(tr, pc);
    const uint32_t dB1 = GSWZ(tr + 64, pc);
    const uint32_t dB2 = GSWZ(tr + 128, pc);
    const uint32_t dB3 = GSWZ(tr + 192, pc);
    const size_t sK64 = (size_t)64 * K, sK128 = (size_t)128 * K, sK192 = (size_t)192 * K;

    auto produce = [&](int stg, int kblk) {
        uint32_t s = sbase + stg * STAGEB;
        CP16(s + OFF_AH + dA0, pA0h + kblk);
        CP16(s + OFF_AL + dA0, pA0l + kblk);
        CP16(s + OFF_AH + dA1, pA1h + kblk);
        CP16(s + OFF_AL + dA1, pA1l + kblk);
        CP16(s + OFF_BH + dB0, pB0h + kblk);
        CP16(s + OFF_BL + dB0, pB0l + kblk);
        CP16(s + OFF_BH + dB1, pB0h + sK64 + kblk);
        CP16(s + OFF_BL + dB1, pB0l + sK64 + kblk);
        CP16(s + OFF_BH + dB2, pB0h + sK128 + kblk);
        CP16(s + OFF_BL + dB2, pB0l + sK128 + kblk);
        CP16(s + OFF_BH + dB3, pB0h + sK192 + kblk);
        CP16(s + OFF_BL + dB3, pB0l + sK192 + kblk);
    };

    float acc[4][8][4];
    #pragma unroll
    for (int i = 0; i < 4; i++)
        #pragma unroll
        for (int j = 0; j < 8; j++)
            #pragma unroll
            for (int r = 0; r < 4; r++) acc[i][j][r] = 0.f;

    // per-lane LDSM smem offsets (within stage), hoisted
    uint32_t aoff[4][2], boff[4][2];
    #pragma unroll
    for (int ti = 0; ti < 4; ti++) {
        uint32_t r = wm + ti * 16 + (lane & 15);
        #pragma unroll
        for (int ks = 0; ks < 2; ks++)
            aoff[ti][ks] = GSWZ(r, ks * 2 + (lane >> 4));
    }
    #pragma unroll
    for (int pj = 0; pj < 4; pj++) {
        uint32_t r = wn + pj * 16 + (lane & 7) + ((lane >> 4) & 1) * 8;
        #pragma unroll
        for (int ks = 0; ks < 2; ks++)
            boff[pj][ks] = GSWZ(r, ks * 2 + ((lane >> 3) & 1));
    }

    auto compute = [&](int stg) {
        uint32_t s = sbase + stg * STAGEB;
        #pragma unroll
        for (int ks = 0; ks < 2; ks++) {
            uint32_t ah[4][4], al[4][4];
            #pragma unroll
            for (int ti = 0; ti < 4; ti++) {
                uint32_t ad = s + aoff[ti][ks];
                LDSM_X4(ah[ti][0], ah[ti][1], ah[ti][2], ah[ti][3], ad + OFF_AH);
                LDSM_X4(al[ti][0], al[ti][1], al[ti][2], al[ti][3], ad + OFF_AL);
            }
            #pragma unroll
            for (int pj = 0; pj < 4; pj++) {
                uint32_t bd = s + boff[pj][ks];
                uint32_t h0, h1, h2, h3, g0, g1, g2, g3;
                LDSM_X4(h0, h1, h2, h3, bd + OFF_BH);
                LDSM_X4(g0, g1, g2, g3, bd + OFF_BL);
                uint32_t bh0[2] = {h0, h1}, bh1[2] = {h2, h3};
                uint32_t bl0[2] = {g0, g1}, bl1[2] = {g2, g3};
                #pragma unroll
                for (int ti = 0; ti < 4; ti++) {
                    mma16816(acc[ti][2 * pj],     ah[ti], bh0);
                    mma16816(acc[ti][2 * pj],     ah[ti], bl0);
                    mma16816(acc[ti][2 * pj],     al[ti], bh0);
                    mma16816(acc[ti][2 * pj + 1], ah[ti], bh1);
                    mma16816(acc[ti][2 * pj + 1], ah[ti], bl1);
                    mma16816(acc[ti][2 * pj + 1], al[ti], bh1);
                }
            }
        }
    };

    const int NK = K / GBK;
    produce(0, 0); CP_COMMIT();
    produce(1, GBK); CP_COMMIT();
    produce(2, 2 * GBK); CP_COMMIT();

    for (int it = 0; it < NK; ++it) {
        CP_WAIT(2);
        __syncthreads();
        compute(it & (NSTAGE - 1));
        if (it + 3 < NK) produce((it + 3) & (NSTAGE - 1), (it + 3) * GBK);
        CP_COMMIT();
    }

    // ---- epilogue ----
    const int er = lane >> 2;
    const int ec = (lane & 3) * 2;
    if (MODE == 0) {
        #pragma unroll
        for (int tj = 0; tj < 8; tj++) {
            int col = n0 + wn + tj * 8 + ec;
            float bx = bias[col], by = bias[col + 1];
            #pragma unroll
            for (int ti = 0; ti < 4; ti++) {
                int row = m0 + wm + ti * 16 + er;
                float2 v0 = { acc[ti][tj][0] + bx, acc[ti][tj][1] + by };
                float2 v1 = { acc[ti][tj][2] + bx, acc[ti][tj][3] + by };
                *(float2*)(C + (size_t)row * N + col) = v0;
                *(float2*)(C + (size_t)(row + 8) * N + col) = v1;
            }
        }
    } else {
        // scatter into q/k/v [B,H,S,HD] bf16 hi/lo (q scaled)
        #pragma unroll
        for (int tj = 0; tj < 8; tj++) {
            int col = n0 + wn + tj * 8 + ec;
            int hh = col / 384, rem = col % 384;
            int which = rem >> 7, hd = rem & 127;
            __nv_bfloat16* dh = which == 0 ? qh : (which == 1 ? kh : vh);
            __nv_bfloat16* dl = which == 0 ? ql : (which == 1 ? kl : vl);
            float sc = which == 0 ? SCALE_ : 1.0f;
            float bx = bias[col], by = bias[col + 1];
            #pragma unroll
            for (int ti = 0; ti < 4; ti++) {
                #pragma unroll
                for (int rr = 0; rr < 2; rr++) {
                    int row = m0 + wm + ti * 16 + er + rr * 8;
                    int bb = row >> 11, ss = row & 2047;
                    size_t off = (((size_t)(bb * H_ + hh)) * S_ + ss) * HD_ + hd;
                    float vx = (acc[ti][tj][rr * 2] + bx) * sc;
                    float vy = (acc[ti][tj][rr * 2 + 1] + by) * sc;
                    uint32_t hp, lp;
                    packhl(vx, vy, hp, lp);
                    *(uint32_t*)(dh + off) = hp;
                    *(uint32_t*)(dl + off) = lp;
                }
            }
        }
    }
}

// ---------------------------------------------------------------------------
// HMMA causal flash attention, bf16x3, FA2-style register softmax.
// BQ=128 (8 warps x 16 rows), BKV=64, HD=128. Double-buffered KV via cp.async.
// ---------------------------------------------------------------------------
#define FROWB 272                      // 128 bf16 + 8 pad = 136 elems
#define FQBYTES (128 * FROWB)          // per Q array
#define FKBYTES (64 * FROWB)           // per K/V array
#define FSTGB (4 * FKBYTES)            // kh,kl,vh,vl
#define FLASH_DYN_SMEM (2 * FQBYTES + 2 * FSTGB)   // 208896 B

__global__ __launch_bounds__(256, 1) void flash_mma(
    const __nv_bfloat16* __restrict__ qh_, const __nv_bfloat16* __restrict__ ql_,
    const __nv_bfloat16* __restrict__ kh_, const __nv_bfloat16* __restrict__ kl_,
    const __nv_bfloat16* __restrict__ vh_, const __nv_bfloat16* __restrict__ vl_,
    __nv_bfloat16* __restrict__ oh_, __nv_bfloat16* __restrict__ ol_)
{
    extern __shared__ __align__(128) char fsm[];
    const uint32_t sb = smem_u32(fsm);
    const int tid = threadIdx.x, wq = tid >> 5, lane = tid & 31;
    const int bi = (int)gridDim.x - 1 - (int)blockIdx.x;   // big blocks first
    const int hh = blockIdx.y, b = blockIdx.z;
    const int q0 = bi * 128;
    const size_t bh = ((size_t)b * H_ + hh) * S_;
    const uint32_t QH = sb, QL = sb + FQBYTES;
    const uint32_t KV0 = sb + 2 * FQBYTES;

    // Q tile load (both hi/lo)
    #pragma unroll
    for (int i = 0; i < 8; i++) {
        int id = tid + i * 256;
        int r = id >> 4, c = id & 15;
        size_t src = (bh + q0 + r) * HD_ + c * 8;
        CP16(QH + r * FROWB + c * 16, qh_ + src);
        CP16(QL + r * FROWB + c * 16, ql_ + src);
    }
    auto produce = [&](int stg, int kt) {
        uint32_t s = KV0 + stg * FSTGB;
        int k0 = kt * 64;
        #pragma unroll
        for (int i = 0; i < 4; i++) {
            int id = tid + i * 256;
            int r = id >> 4, c = id & 15;
            size_t src = (bh + k0 + r) * HD_ + c * 8;
            uint32_t d = r * FROWB + c * 16;
            CP16(s + d, kh_ + src);
            CP16(s + FKBYTES + d, kl_ + src);
            CP16(s + 2 * FKBYTES + d, vh_ + src);
            CP16(s + 3 * FKBYTES + d, vl_ + src);
        }
    };

    float o[16][4];
    #pragma unroll
    for (int j = 0; j < 16; j++)
        #pragma unroll
        for (int r = 0; r < 4; r++) o[j][r] = 0.f;
    float m0 = -1e30f, m1 = -1e30f, l0 = 0.f, l1 = 0.f;

    const int er = lane >> 2, ec2 = (lane & 3) * 2;
    const uint32_t a_row = wq * 16 + (lane & 15);
    const uint32_t a_kb  = (lane >> 4) * 16;
    const uint32_t b_row = (lane & 7) + ((lane >> 4) & 1) * 8;
    const uint32_t b_kb  = ((lane >> 3) & 1) * 16;
    const uint32_t v_row = (lane & 7) + ((lane >> 3) & 1) * 8;
    const uint32_t v_cb  = ((lane >> 4) & 1) * 16;

    const int nkt = 2 * bi + 2;
    produce(0, 0);
    CP_COMMIT();

    for (int kt = 0; kt < nkt; kt++) {
        if (kt + 1 < nkt) { produce((kt + 1) & 1, kt + 1); CP_COMMIT(); CP_WAIT(1); }
        else CP_WAIT(0);
        __syncthreads();
        const uint32_t kb = KV0 + (kt & 1) * FSTGB;

        // ---- phase 1: S = Q K^T (bf16x3) ----
        float s[8][4];
        #pragma unroll
        for (int j = 0; j < 8; j++)
            #pragma unroll
            for (int r = 0; r < 4; r++) s[j][r] = 0.f;

        #pragma unroll
        for (int ks = 0; ks < 8; ks++) {
            uint32_t ah[4], al[4];
            uint32_t qa = QH + a_row * FROWB + ks * 32 + a_kb;
            LDSM_X4(ah[0], ah[1], ah[2], ah[3], qa);
            LDSM_X4(al[0], al[1], al[2], al[3], qa + FQBYTES);
            #pragma unroll
            for (int bj = 0; bj < 4; bj++) {
                uint32_t ka = kb + (bj * 16 + b_row) * FROWB + ks * 32 + b_kb;
                uint32_t h0, h1, h2, h3, g0, g1, g2, g3;
                LDSM_X4(h0, h1, h2, h3, ka);
                LDSM_X4(g0, g1, g2, g3, ka + FKBYTES);
                uint32_t bhi0[2] = {h0, h1}, bhi1[2] = {h2, h3};
                uint32_t blo0[2] = {g0, g1}, blo1[2] = {g2, g3};
                mma16816(s[2 * bj], ah, bhi0);
                mma16816(s[2 * bj], ah, blo0);
                mma16816(s[2 * bj], al, bhi0);
                mma16816(s[2 * bj + 1], ah, bhi1);
                mma16816(s[2 * bj + 1], ah, blo1);
                mma16816(s[2 * bj + 1], al, bhi1);
            }
        }

        // ---- causal mask (only last two tiles) ----
        if (kt >= 2 * bi) {
            int row0 = q0 + wq * 16 + er, row1 = row0 + 8;
            int colb = kt * 64 + ec2;
            #pragma unroll
            for (int j = 0; j < 8; j++) {
                int c0 = colb + j * 8, c1 = c0 + 1;
                if (c0 > row0) s[j][0] = -1e30f;
                if (c1 > row0) s[j][1] = -1e30f;
                if (c0 > row1) s[j][2] = -1e30f;
                if (c1 > row1) s[j][3] = -1e30f;
            }
        }

        // ---- online softmax (rows er / er+8) ----
        float mx0 = -1e30f, mx1 = -1e30f;
        #pragma unroll
        for (int j = 0; j < 8; j++) {
            mx0 = fmaxf(mx0, fmaxf(s[j][0], s[j][1]));
            mx1 = fmaxf(mx1, fmaxf(s[j][2], s[j][3]));
        }
        mx0 = fmaxf(mx0, __shfl_xor_sync(0xffffffffu, mx0, 1));
        mx0 = fmaxf(mx0, __shfl_xor_sync(0xffffffffu, mx0, 2));
        mx1 = fmaxf(mx1, __shfl_xor_sync(0xffffffffu, mx1, 1));
        mx1 = fmaxf(mx1, __shfl_xor_sync(0xffffffffu, mx1, 2));
        float mn0 = fmaxf(m0, mx0), mn1 = fmaxf(m1, mx1);
        float al0 = __expf(m0 - mn0), al1 = __expf(m1 - mn1);
        m0 = mn0; m1 = mn1;
        float sm0 = 0.f, sm1 = 0.f;
        #pragma unroll
        for (int j = 0; j < 8; j++) {
            s[j][0] = __expf(s[j][0] - m0); sm0 += s[j][0];
            s[j][1] = __expf(s[j][1] - m0); sm0 += s[j][1];
            s[j][2] = __expf(s[j][2] - m1); sm1 += s[j][2];
            s[j][3] = __expf(s[j][3] - m1); sm1 += s[j][3];
        }
        sm0 += __shfl_xor_sync(0xffffffffu, sm0, 1);
        sm0 += __shfl_xor_sync(0xffffffffu, sm0, 2);
        sm1 += __shfl_xor_sync(0xffffffffu, sm1, 1);
        sm1 += __shfl_xor_sync(0xffffffffu, sm1, 2);
        l0 = l0 * al0 + sm0;
        l1 = l1 * al1 + sm1;
        #pragma unroll
        for (int j = 0; j < 16; j++) {
            o[j][0] *= al0; o[j][1] *= al0;
            o[j][2] *= al1; o[j][3] *= al1;
        }

        // ---- phase 2: O += P V (bf16x3; V via ldmatrix.trans) ----
        const uint32_t vbase = kb + 2 * FKBYTES;
        #pragma unroll
        for (int ki = 0; ki < 4; ki++) {
            uint32_t ph[4], pl[4];
            packhl(s[2 * ki][0],     s[2 * ki][1],     ph[0], pl[0]);
            packhl(s[2 * ki][2],     s[2 * ki][3],     ph[1], pl[1]);
            packhl(s[2 * ki + 1][0], s[2 * ki + 1][1], ph[2], pl[2]);
            packhl(s[2 * ki + 1][2], s[2 * ki + 1][3], ph[3], pl[3]);
            #pragma unroll
            for (int nj = 0; nj < 8; nj++) {
                uint32_t va = vbase + (ki * 16 + v_row) * FROWB + nj * 32 + v_cb;
                uint32_t h0, h1, h2, h3, g0, g1, g2, g3;
                LDSM_X4T(h0, h1, h2, h3, va);
                LDSM_X4T(g0, g1, g2, g3, va + FKBYTES);
                uint32_t vh0[2] = {h0, h1}, vh1[2] = {h2, h3};
                uint32_t vl0[2] = {g0, g1}, vl1[2] = {g2, g3};
                mma16816(o[2 * nj], ph, vh0);
                mma16816(o[2 * nj], ph, vl0);
                mma16816(o[2 * nj], pl, vh0);
                mma16816(o[2 * nj + 1], ph, vh1);
                mma16816(o[2 * nj + 1], ph, vl1);
                mma16816(o[2 * nj + 1], pl, vh1);
            }
        }
        __syncthreads();   // protect KV buffer before next produce overwrites
    }

    // ---- epilogue: normalize + bf16 hi/lo write ----
    float il0 = 1.f / l0, il1 = 1.f / l1;
    int row0 = q0 + wq * 16 + er;
    #pragma unroll
    for (int j = 0; j < 16; j++) {
        int col = hh * 128 + j * 8 + ec2;
        uint32_t hp, lp;
        packhl(o[j][0] * il0, o[j][1] * il0, hp, lp);
        size_t off0 = ((size_t)b * S_ + row0) * D_ + col;
        *(uint32_t*)(oh_ + off0) = hp;
        *(uint32_t*)(ol_ + off0) = lp;
        packhl(o[j][2] * il1, o[j][3] * il1, hp, lp);
        size_t off1 = ((size_t)b * S_ + row0 + 8) * D_ + col;
        *(uint32_t*)(oh_ + off1) = hp;
        *(uint32_t*)(ol_ + off1) = lp;
    }
}

// ---------------------------------------------------------------------------
// Launch
// ---------------------------------------------------------------------------
extern "C" void kernel_launch(void* const* d_in, const int* in_sizes, int n_in,
                              void* d_out, int out_size)
{
    (void)in_sizes; (void)n_in; (void)out_size;
    const float* x    = (const float*)d_in[0];
    const float* Wqkv = (const float*)d_in[1];
    const float* bqkv = (const float*)d_in[2];
    const float* Wo   = (const float*)d_in[3];
    const float* bo   = (const float*)d_in[4];
    float* out = (float*)d_out;

    __nv_bfloat16 *xhi, *xlo, *w1hi, *w1lo, *w2hi, *w2lo;
    __nv_bfloat16 *qhi, *qlo, *khi, *klo, *vhi, *vlo, *ahi, *alo;
    cudaGetSymbolAddress((void**)&xhi, g_xhi);   cudaGetSymbolAddress((void**)&xlo, g_xlo);
    cudaGetSymbolAddress((void**)&w1hi, g_w1hi); cudaGetSymbolAddress((void**)&w1lo, g_w1lo);
    cudaGetSymbolAddress((void**)&w2hi, g_w2hi); cudaGetSymbolAddress((void**)&w2lo, g_w2lo);
    cudaGetSymbolAddress((void**)&qhi, g_qhi);   cudaGetSymbolAddress((void**)&qlo, g_qlo);
    cudaGetSymbolAddress((void**)&khi, g_khi);   cudaGetSymbolAddress((void**)&klo, g_klo);
    cudaGetSymbolAddress((void**)&vhi, g_vhi);   cudaGetSymbolAddress((void**)&vlo, g_vlo);
    cudaGetSymbolAddress((void**)&ahi, g_ahi);   cudaGetSymbolAddress((void**)&alo, g_alo);

    cudaFuncSetAttribute(gemm_bf16x3<0>,
                         cudaFuncAttributeMaxDynamicSharedMemorySize, GEMM_DYN_SMEM);
    cudaFuncSetAttribute(gemm_bf16x3<1>,
                         cudaFuncAttributeMaxDynamicSharedMemorySize, GEMM_DYN_SMEM);
    cudaFuncSetAttribute(flash_mma,
                         cudaFuncAttributeMaxDynamicSharedMemorySize, FLASH_DYN_SMEM);

    // 1) split x
    {
        int n4 = (M_ * D_) / 4;
        split_f32<<<(n4 + 255) / 256, 256>>>(x, xhi, xlo, n4);
    }
    // 2) transpose+split weights
    transpose_split<<<dim3((3 * D_) / 32, D_ / 32), dim3(32, 8)>>>(Wqkv, w1hi, w1lo, D_, 3 * D_);
    transpose_split<<<dim3(D_ / 32, D_ / 32), dim3(32, 8)>>>(Wo, w2hi, w2lo, D_, D_);

    // 3) QKV GEMM with fused bias+scale+split+scatter epilogue
    gemm_bf16x3<1><<<dim3((3 * D_) / 256, M_ / 128), 256, GEMM_DYN_SMEM>>>(
        xhi, xlo, w1hi, w1lo, bqkv, nullptr,
        qhi, qlo, khi, klo, vhi, vlo, M_, 3 * D_, D_);

    // 4) HMMA flash attention
    flash_mma<<<dim3(S_ / 128, H_, B_), 256, FLASH_DYN_SMEM>>>(
        qhi, qlo, khi, klo, vhi, vlo, ahi, alo);

    // 5) out = attn @ Wo + bo
    gemm_bf16x3<0><<<dim3(D_ / 256, M_ / 128), 256, GEMM_DYN_SMEM>>>(
        ahi, alo, w2hi, w2lo, bo, out,
        nullptr, nullptr, nullptr, nullptr, nullptr, nullptr, M_, D_, D_);
}

// round 7
// speedup vs baseline: 1.0115x; 1.0115x over previous
#include <cuda_runtime.h>
#include <cuda_bf16.h>
#include <cstdint>
#include <cstddef>

// ---------------------------------------------------------------------------
// Problem constants
// ---------------------------------------------------------------------------
#define B_  2
#define S_  2048
#define D_  2048
#define H_  16
#define HD_ 128
#define M_  (B_*S_)            // 4096 rows
#define K_  2048               // inner dim of BOTH gemms (compile-time)
#define SCALE_ 0.08838834764831845f

// ---------------------------------------------------------------------------
// Scratch (__device__ globals; no allocation allowed)
// ---------------------------------------------------------------------------
__device__ __nv_bfloat16 g_xhi[(size_t)M_ * D_];
__device__ __nv_bfloat16 g_xlo[(size_t)M_ * D_];
__device__ __nv_bfloat16 g_w1hi[(size_t)3 * D_ * D_];   // Wqkv^T [6144,2048]
__device__ __nv_bfloat16 g_w1lo[(size_t)3 * D_ * D_];
__device__ __nv_bfloat16 g_w2hi[(size_t)D_ * D_];       // Wo^T [2048,2048]
__device__ __nv_bfloat16 g_w2lo[(size_t)D_ * D_];
// q/k/v in [B,H,S,HD] bf16 hi/lo (q pre-scaled by 1/sqrt(HD))
__device__ __nv_bfloat16 g_qhi[(size_t)M_ * D_];
__device__ __nv_bfloat16 g_qlo[(size_t)M_ * D_];
__device__ __nv_bfloat16 g_khi[(size_t)M_ * D_];
__device__ __nv_bfloat16 g_klo[(size_t)M_ * D_];
__device__ __nv_bfloat16 g_vhi[(size_t)M_ * D_];
__device__ __nv_bfloat16 g_vlo[(size_t)M_ * D_];
// attention output [B,S,D] bf16 hi/lo
__device__ __nv_bfloat16 g_ahi[(size_t)M_ * D_];
__device__ __nv_bfloat16 g_alo[(size_t)M_ * D_];

// ---------------------------------------------------------------------------
// Portable PTX helpers (virtual arch compute_103: no tcgen05)
// ---------------------------------------------------------------------------
__device__ __forceinline__ uint32_t smem_u32(const void* p) {
    uint32_t a;
    asm("{ .reg .u64 t; cvta.to.shared.u64 t, %1; cvt.u32.u64 %0, t; }"
        : "=r"(a) : "l"(p));
    return a;
}

#define CP16(dst_u32, src_ptr) \
    asm volatile("cp.async.cg.shared.global [%0], [%1], 16;" \
                 :: "r"(dst_u32), "l"(src_ptr) : "memory")
#define CP_COMMIT() asm volatile("cp.async.commit_group;" ::: "memory")
#define CP_WAIT(n)  asm volatile("cp.async.wait_group %0;" :: "n"(n) : "memory")

#define LDSM_X4(r0, r1, r2, r3, addr) \
    asm volatile("ldmatrix.sync.aligned.m8n8.x4.shared.b16 {%0,%1,%2,%3}, [%4];" \
                 : "=r"(r0), "=r"(r1), "=r"(r2), "=r"(r3) : "r"(addr))
#define LDSM_X4T(r0, r1, r2, r3, addr) \
    asm volatile("ldmatrix.sync.aligned.m8n8.x4.trans.shared.b16 {%0,%1,%2,%3}, [%4];" \
                 : "=r"(r0), "=r"(r1), "=r"(r2), "=r"(r3) : "r"(addr))

__device__ __forceinline__ void mma16816(float* d, const uint32_t* a,
                                         const uint32_t* b) {
    asm volatile(
        "mma.sync.aligned.m16n8k16.row.col.f32.bf16.bf16.f32 "
        "{%0,%1,%2,%3}, {%4,%5,%6,%7}, {%8,%9}, {%0,%1,%2,%3};"
        : "+f"(d[0]), "+f"(d[1]), "+f"(d[2]), "+f"(d[3])
        : "r"(a[0]), "r"(a[1]), "r"(a[2]), "r"(a[3]), "r"(b[0]), "r"(b[1]));
}

__device__ __forceinline__ void split1(float v, __nv_bfloat16& h, __nv_bfloat16& l) {
    h = __float2bfloat16(v);
    l = __float2bfloat16(v - __bfloat162float(h));
}

// pack two floats -> bf16x2 hi + bf16x2 lo(residual)
__device__ __forceinline__ void packhl(float x, float y, uint32_t& hp, uint32_t& lp) {
    __nv_bfloat162 hv = __floats2bfloat162_rn(x, y);
    float rx = x - __bfloat162float(__low2bfloat16(hv));
    float ry = y - __bfloat162float(__high2bfloat16(hv));
    __nv_bfloat162 lv = __floats2bfloat162_rn(rx, ry);
    hp = *reinterpret_cast<uint32_t*>(&hv);
    lp = *reinterpret_cast<uint32_t*>(&lv);
}

// ---------------------------------------------------------------------------
// split / transpose-split pre-passes
// ---------------------------------------------------------------------------
__global__ void split_f32(const float* __restrict__ in,
                          __nv_bfloat16* __restrict__ hi,
                          __nv_bfloat16* __restrict__ lo, int n4) {
    int i = blockIdx.x * blockDim.x + threadIdx.x;
    if (i >= n4) return;
    float4 v = *(const float4*)(in + (size_t)i * 4);
    uint32_t h0, h1, l0, l1;
    packhl(v.x, v.y, h0, l0);
    packhl(v.z, v.w, h1, l1);
    uint32_t* hp = (uint32_t*)(hi + (size_t)i * 4);
    uint32_t* lp = (uint32_t*)(lo + (size_t)i * 4);
    hp[0] = h0; hp[1] = h1;
    lp[0] = l0; lp[1] = l1;
}

__global__ void transpose_split(const float* __restrict__ W,
                                __nv_bfloat16* __restrict__ Th,
                                __nv_bfloat16* __restrict__ Tl, int K, int N) {
    __shared__ float t[32][33];
    int n0 = blockIdx.x * 32, k0 = blockIdx.y * 32;
    int tx = threadIdx.x, ty = threadIdx.y;      // (32,8)
    #pragma unroll
    for (int j = 0; j < 32; j += 8)
        t[ty + j][tx] = W[(size_t)(k0 + ty + j) * N + n0 + tx];
    __syncthreads();
    #pragma unroll
    for (int j = 0; j < 32; j += 8) {
        float v = t[tx][ty + j];
        __nv_bfloat16 h, l; split1(v, h, l);
        size_t o = (size_t)(n0 + ty + j) * K + k0 + tx;
        Th[o] = h; Tl[o] = l;
    }
}

// ---------------------------------------------------------------------------
// HMMA bf16x3 GEMM:  C = A @ Bt^T + bias.   BM=128, BN=256, BK=32,
// 8 warps (2x4), warp tile 64x64, 4-stage cp.async, XOR-swizzled smem.
// M=4096, K=2048 compile-time; NN template.  MODE 0: fp32 C;  1: qkv scatter.
// ---------------------------------------------------------------------------
#define GBK 32
// 64B rows, chunk swizzle: chunk ^= (row>>1)&3  (conflict-free LDSM + stores)
#define GSWZ(r, c) ((uint32_t)(r) * 64u + ((((uint32_t)(c) ^ (((uint32_t)(r) >> 1) & 3u))) << 4))
#define OFF_AH 0
#define OFF_AL 8192                   // 128 rows * 64B
#define OFF_BH 16384
#define OFF_BL 32768                  // B: 256 rows * 64B
#define STAGEB 49152
#define NSTAGE 4
#define GEMM_DYN_SMEM (NSTAGE * STAGEB)   // 196608

template <int MODE, int NN>
__global__ __launch_bounds__(256, 1) void gemm_bf16x3(
    const __nv_bfloat16* __restrict__ Ah, const __nv_bfloat16* __restrict__ Al,
    const __nv_bfloat16* __restrict__ Bh, const __nv_bfloat16* __restrict__ Bl,
    const float* __restrict__ bias, float* __restrict__ C,
    __nv_bfloat16* __restrict__ qh, __nv_bfloat16* __restrict__ ql,
    __nv_bfloat16* __restrict__ kh, __nv_bfloat16* __restrict__ kl,
    __nv_bfloat16* __restrict__ vh, __nv_bfloat16* __restrict__ vl)
{
    extern __shared__ __align__(128) char sm[];
    const uint32_t sbase = smem_u32(sm);

    const int tid = threadIdx.x;
    const int wid = tid >> 5;
    const int lane = tid & 31;
    const int m0 = blockIdx.y * 128;
    const int n0 = blockIdx.x * 256;
    const int wm = (wid >> 2) * 64;      // 0 / 64
    const int wn = (wid & 3) * 64;       // 0/64/128/192

    // ---- producer: base offsets compile-time-strided (K_ constexpr) ----
    const int tr = tid >> 2;             // 0..63
    const int pc = tid & 3;              // chunk 0..3
    const __nv_bfloat16* pAh = Ah + (m0 + tr) * K_ + pc * 8;
    const __nv_bfloat16* pAl = Al + (m0 + tr) * K_ + pc * 8;
    const __nv_bfloat16* pBh = Bh + (n0 + tr) * K_ + pc * 8;
    const __nv_bfloat16* pBl = Bl + (n0 + tr) * K_ + pc * 8;
    const uint32_t dT0 = GSWZ(tr, pc);
    const uint32_t dT1 = GSWZ(tr + 64, pc);
    const uint32_t dT2 = GSWZ(tr + 128, pc);
    const uint32_t dT3 = GSWZ(tr + 192, pc);

    auto produce = [&](int stg, int kblk) {
        uint32_t s = sbase + stg * STAGEB;
        CP16(s + OFF_AH + dT0, pAh + kblk);
        CP16(s + OFF_AL + dT0, pAl + kblk);
        CP16(s + OFF_AH + dT1, pAh + 64 * K_ + kblk);
        CP16(s + OFF_AL + dT1, pAl + 64 * K_ + kblk);
        CP16(s + OFF_BH + dT0, pBh + kblk);
        CP16(s + OFF_BL + dT0, pBl + kblk);
        CP16(s + OFF_BH + dT1, pBh + 64 * K_ + kblk);
        CP16(s + OFF_BL + dT1, pBl + 64 * K_ + kblk);
        CP16(s + OFF_BH + dT2, pBh + 128 * K_ + kblk);
        CP16(s + OFF_BL + dT2, pBl + 128 * K_ + kblk);
        CP16(s + OFF_BH + dT3, pBh + 192 * K_ + kblk);
        CP16(s + OFF_BL + dT3, pBl + 192 * K_ + kblk);
    };

    float acc[4][8][4];
    #pragma unroll
    for (int i = 0; i < 4; i++)
        #pragma unroll
        for (int j = 0; j < 8; j++)
            #pragma unroll
            for (int r = 0; r < 4; r++) acc[i][j][r] = 0.f;

    // per-lane LDSM offsets for ks=0 only; ks=1 derived via ^0x20
    // (chunk c -> c+2 toggles bit1 of (c ^ swz) => offset bit5)
    uint32_t aoff[4], boff[4];
    #pragma unroll
    for (int ti = 0; ti < 4; ti++)
        aoff[ti] = GSWZ(wm + ti * 16 + (lane & 15), (lane >> 4));
    #pragma unroll
    for (int pj = 0; pj < 4; pj++)
        boff[pj] = GSWZ(wn + pj * 16 + (lane & 7) + ((lane >> 4) & 1) * 8,
                        ((lane >> 3) & 1));

    auto compute = [&](int stg) {
        uint32_t s = sbase + stg * STAGEB;
        #pragma unroll
        for (int ks = 0; ks < 2; ks++) {
            const uint32_t kx = ks ? 0x20u : 0u;
            uint32_t ah[4][4], al[4][4];
            #pragma unroll
            for (int ti = 0; ti < 4; ti++) {
                uint32_t ad = s + (aoff[ti] ^ kx);
                LDSM_X4(ah[ti][0], ah[ti][1], ah[ti][2], ah[ti][3], ad + OFF_AH);
                LDSM_X4(al[ti][0], al[ti][1], al[ti][2], al[ti][3], ad + OFF_AL);
            }
            #pragma unroll
            for (int pj = 0; pj < 4; pj++) {
                uint32_t bd = s + (boff[pj] ^ kx);
                uint32_t h0, h1, h2, h3, g0, g1, g2, g3;
                LDSM_X4(h0, h1, h2, h3, bd + OFF_BH);
                LDSM_X4(g0, g1, g2, g3, bd + OFF_BL);
                uint32_t bh0[2] = {h0, h1}, bh1[2] = {h2, h3};
                uint32_t bl0[2] = {g0, g1}, bl1[2] = {g2, g3};
                // term-major issue order: consecutive MMAs hit different accs
                #pragma unroll
                for (int ti = 0; ti < 4; ti++) {
                    mma16816(acc[ti][2 * pj],     ah[ti], bh0);
                    mma16816(acc[ti][2 * pj + 1], ah[ti], bh1);
                }
                #pragma unroll
                for (int ti = 0; ti < 4; ti++) {
                    mma16816(acc[ti][2 * pj],     ah[ti], bl0);
                    mma16816(acc[ti][2 * pj + 1], ah[ti], bl1);
                }
                #pragma unroll
                for (int ti = 0; ti < 4; ti++) {
                    mma16816(acc[ti][2 * pj],     al[ti], bh0);
                    mma16816(acc[ti][2 * pj + 1], al[ti], bh1);
                }
            }
        }
    };

    const int NK = K_ / GBK;             // 64
    produce(0, 0); CP_COMMIT();
    produce(1, GBK); CP_COMMIT();
    produce(2, 2 * GBK); CP_COMMIT();

    for (int it = 0; it < NK; ++it) {
        CP_WAIT(2);
        __syncthreads();
        compute(it & (NSTAGE - 1));
        if (it + 3 < NK) produce((it + 3) & (NSTAGE - 1), (it + 3) * GBK);
        CP_COMMIT();
    }

    // ---- epilogue ----
    const int er = lane >> 2;
    const int ec = (lane & 3) * 2;
    if (MODE == 0) {
        #pragma unroll
        for (int tj = 0; tj < 8; tj++) {
            int col = n0 + wn + tj * 8 + ec;
            float bx = bias[col], by = bias[col + 1];
            #pragma unroll
            for (int ti = 0; ti < 4; ti++) {
                int row = m0 + wm + ti * 16 + er;
                float2 v0 = { acc[ti][tj][0] + bx, acc[ti][tj][1] + by };
                float2 v1 = { acc[ti][tj][2] + bx, acc[ti][tj][3] + by };
                *(float2*)(C + (size_t)row * NN + col) = v0;
                *(float2*)(C + (size_t)(row + 8) * NN + col) = v1;
            }
        }
    } else {
        // scatter into q/k/v [B,H,S,HD] bf16 hi/lo (q scaled)
        #pragma unroll
        for (int tj = 0; tj < 8; tj++) {
            int col = n0 + wn + tj * 8 + ec;
            int hh = col / 384, rem = col % 384;
            int which = rem >> 7, hd = rem & 127;
            __nv_bfloat16* dh = which == 0 ? qh : (which == 1 ? kh : vh);
            __nv_bfloat16* dl = which == 0 ? ql : (which == 1 ? kl : vl);
            float sc = which == 0 ? SCALE_ : 1.0f;
            float bx = bias[col], by = bias[col + 1];
            #pragma unroll
            for (int ti = 0; ti < 4; ti++) {
                #pragma unroll
                for (int rr = 0; rr < 2; rr++) {
                    int row = m0 + wm + ti * 16 + er + rr * 8;
                    int bb = row >> 11, ss = row & 2047;
                    size_t off = (((size_t)(bb * H_ + hh)) * S_ + ss) * HD_ + hd;
                    float vx = (acc[ti][tj][rr * 2] + bx) * sc;
                    float vy = (acc[ti][tj][rr * 2 + 1] + by) * sc;
                    uint32_t hp, lp;
                    packhl(vx, vy, hp, lp);
                    *(uint32_t*)(dh + off) = hp;
                    *(uint32_t*)(dl + off) = lp;
                }
            }
        }
    }
}

// ---------------------------------------------------------------------------
// HMMA causal flash attention, bf16x3, FA2-style register softmax.
// BQ=128 (8 warps x 16 rows), BKV=64, HD=128. Double-buffered KV via cp.async.
// ---------------------------------------------------------------------------
#define FROWB 272                      // 128 bf16 + 8 pad = 136 elems
#define FQBYTES (128 * FROWB)          // per Q array
#define FKBYTES (64 * FROWB)           // per K/V array
#define FSTGB (4 * FKBYTES)            // kh,kl,vh,vl
#define FLASH_DYN_SMEM (2 * FQBYTES + 2 * FSTGB)   // 208896 B

__global__ __launch_bounds__(256, 1) void flash_mma(
    const __nv_bfloat16* __restrict__ qh_, const __nv_bfloat16* __restrict__ ql_,
    const __nv_bfloat16* __restrict__ kh_, const __nv_bfloat16* __restrict__ kl_,
    const __nv_bfloat16* __restrict__ vh_, const __nv_bfloat16* __restrict__ vl_,
    __nv_bfloat16* __restrict__ oh_, __nv_bfloat16* __restrict__ ol_)
{
    extern __shared__ __align__(128) char fsm[];
    const uint32_t sb = smem_u32(fsm);
    const int tid = threadIdx.x, wq = tid >> 5, lane = tid & 31;
    const int bi = (int)gridDim.x - 1 - (int)blockIdx.x;   // big blocks first
    const int hh = blockIdx.y, b = blockIdx.z;
    const int q0 = bi * 128;
    const size_t bh = ((size_t)b * H_ + hh) * S_;
    const uint32_t QH = sb, QL = sb + FQBYTES;
    const uint32_t KV0 = sb + 2 * FQBYTES;

    // Q tile load (both hi/lo)
    #pragma unroll
    for (int i = 0; i < 8; i++) {
        int id = tid + i * 256;
        int r = id >> 4, c = id & 15;
        size_t src = (bh + q0 + r) * HD_ + c * 8;
        CP16(QH + r * FROWB + c * 16, qh_ + src);
        CP16(QL + r * FROWB + c * 16, ql_ + src);
    }
    auto produce = [&](int stg, int kt) {
        uint32_t s = KV0 + stg * FSTGB;
        int k0 = kt * 64;
        #pragma unroll
        for (int i = 0; i < 4; i++) {
            int id = tid + i * 256;
            int r = id >> 4, c = id & 15;
            size_t src = (bh + k0 + r) * HD_ + c * 8;
            uint32_t d = r * FROWB + c * 16;
            CP16(s + d, kh_ + src);
            CP16(s + FKBYTES + d, kl_ + src);
            CP16(s + 2 * FKBYTES + d, vh_ + src);
            CP16(s + 3 * FKBYTES + d, vl_ + src);
        }
    };

    float o[16][4];
    #pragma unroll
    for (int j = 0; j < 16; j++)
        #pragma unroll
        for (int r = 0; r < 4; r++) o[j][r] = 0.f;
    float m0 = -1e30f, m1 = -1e30f, l0 = 0.f, l1 = 0.f;

    const int er = lane >> 2, ec2 = (lane & 3) * 2;
    const uint32_t a_row = wq * 16 + (lane & 15);
    const uint32_t a_kb  = (lane >> 4) * 16;
    const uint32_t b_row = (lane & 7) + ((lane >> 4) & 1) * 8;
    const uint32_t b_kb  = ((lane >> 3) & 1) * 16;
    const uint32_t v_row = (lane & 7) + ((lane >> 3) & 1) * 8;
    const uint32_t v_cb  = ((lane >> 4) & 1) * 16;

    const int nkt = 2 * bi + 2;
    produce(0, 0);
    CP_COMMIT();

    for (int kt = 0; kt < nkt; kt++) {
        if (kt + 1 < nkt) { produce((kt + 1) & 1, kt + 1); CP_COMMIT(); CP_WAIT(1); }
        else CP_WAIT(0);
        __syncthreads();
        const uint32_t kb = KV0 + (kt & 1) * FSTGB;

        // ---- phase 1: S = Q K^T (bf16x3) ----
        float s[8][4];
        #pragma unroll
        for (int j = 0; j < 8; j++)
            #pragma unroll
            for (int r = 0; r < 4; r++) s[j][r] = 0.f;

        #pragma unroll
        for (int ks = 0; ks < 8; ks++) {
            uint32_t ah[4], al[4];
            uint32_t qa = QH + a_row * FROWB + ks * 32 + a_kb;
            LDSM_X4(ah[0], ah[1], ah[2], ah[3], qa);
            LDSM_X4(al[0], al[1], al[2], al[3], qa + FQBYTES);
            #pragma unroll
            for (int bj = 0; bj < 4; bj++) {
                uint32_t ka = kb + (bj * 16 + b_row) * FROWB + ks * 32 + b_kb;
                uint32_t h0, h1, h2, h3, g0, g1, g2, g3;
                LDSM_X4(h0, h1, h2, h3, ka);
                LDSM_X4(g0, g1, g2, g3, ka + FKBYTES);
                uint32_t bhi0[2] = {h0, h1}, bhi1[2] = {h2, h3};
                uint32_t blo0[2] = {g0, g1}, blo1[2] = {g2, g3};
                mma16816(s[2 * bj], ah, bhi0);
                mma16816(s[2 * bj], ah, blo0);
                mma16816(s[2 * bj], al, bhi0);
                mma16816(s[2 * bj + 1], ah, bhi1);
                mma16816(s[2 * bj + 1], ah, blo1);
                mma16816(s[2 * bj + 1], al, bhi1);
            }
        }

        // ---- causal mask (only last two tiles) ----
        if (kt >= 2 * bi) {
            int row0 = q0 + wq * 16 + er, row1 = row0 + 8;
            int colb = kt * 64 + ec2;
            #pragma unroll
            for (int j = 0; j < 8; j++) {
                int c0 = colb + j * 8, c1 = c0 + 1;
                if (c0 > row0) s[j][0] = -1e30f;
                if (c1 > row0) s[j][1] = -1e30f;
                if (c0 > row1) s[j][2] = -1e30f;
                if (c1 > row1) s[j][3] = -1e30f;
            }
        }

        // ---- online softmax (rows er / er+8) ----
        float mx0 = -1e30f, mx1 = -1e30f;
        #pragma unroll
        for (int j = 0; j < 8; j++) {
            mx0 = fmaxf(mx0, fmaxf(s[j][0], s[j][1]));
            mx1 = fmaxf(mx1, fmaxf(s[j][2], s[j][3]));
        }
        mx0 = fmaxf(mx0, __shfl_xor_sync(0xffffffffu, mx0, 1));
        mx0 = fmaxf(mx0, __shfl_xor_sync(0xffffffffu, mx0, 2));
        mx1 = fmaxf(mx1, __shfl_xor_sync(0xffffffffu, mx1, 1));
        mx1 = fmaxf(mx1, __shfl_xor_sync(0xffffffffu, mx1, 2));
        float mn0 = fmaxf(m0, mx0), mn1 = fmaxf(m1, mx1);
        float al0 = __expf(m0 - mn0), al1 = __expf(m1 - mn1);
        m0 = mn0; m1 = mn1;
        float sm0 = 0.f, sm1 = 0.f;
        #pragma unroll
        for (int j = 0; j < 8; j++) {
            s[j][0] = __expf(s[j][0] - m0); sm0 += s[j][0];
            s[j][1] = __expf(s[j][1] - m0); sm0 += s[j][1];
            s[j][2] = __expf(s[j][2] - m1); sm1 += s[j][2];
            s[j][3] = __expf(s[j][3] - m1); sm1 += s[j][3];
        }
        sm0 += __shfl_xor_sync(0xffffffffu, sm0, 1);
        sm0 += __shfl_xor_sync(0xffffffffu, sm0, 2);
        sm1 += __shfl_xor_sync(0xffffffffu, sm1, 1);
        sm1 += __shfl_xor_sync(0xffffffffu, sm1, 2);
        l0 = l0 * al0 + sm0;
        l1 = l1 * al1 + sm1;
        #pragma unroll
        for (int j = 0; j < 16; j++) {
            o[j][0] *= al0; o[j][1] *= al0;
            o[j][2] *= al1; o[j][3] *= al1;
        }

        // ---- phase 2: O += P V (bf16x3; V via ldmatrix.trans) ----
        const uint32_t vbase = kb + 2 * FKBYTES;
        #pragma unroll
        for (int ki = 0; ki < 4; ki++) {
            uint32_t ph[4], pl[4];
            packhl(s[2 * ki][0],     s[2 * ki][1],     ph[0], pl[0]);
            packhl(s[2 * ki][2],     s[2 * ki][3],     ph[1], pl[1]);
            packhl(s[2 * ki + 1][0], s[2 * ki + 1][1], ph[2], pl[2]);
            packhl(s[2 * ki + 1][2], s[2 * ki + 1][3], ph[3], pl[3]);
            #pragma unroll
            for (int nj = 0; nj < 8; nj++) {
                uint32_t va = vbase + (ki * 16 + v_row) * FROWB + nj * 32 + v_cb;
                uint32_t h0, h1, h2, h3, g0, g1, g2, g3;
                LDSM_X4T(h0, h1, h2, h3, va);
                LDSM_X4T(g0, g1, g2, g3, va + FKBYTES);
                uint32_t vh0[2] = {h0, h1}, vh1[2] = {h2, h3};
                uint32_t vl0[2] = {g0, g1}, vl1[2] = {g2, g3};
                mma16816(o[2 * nj], ph, vh0);
                mma16816(o[2 * nj], ph, vl0);
                mma16816(o[2 * nj], pl, vh0);
                mma16816(o[2 * nj + 1], ph, vh1);
                mma16816(o[2 * nj + 1], ph, vl1);
                mma16816(o[2 * nj + 1], pl, vh1);
            }
        }
        __syncthreads();   // protect KV buffer before next produce overwrites
    }

    // ---- epilogue: normalize + bf16 hi/lo write ----
    float il0 = 1.f / l0, il1 = 1.f / l1;
    int row0 = q0 + wq * 16 + er;
    #pragma unroll
    for (int j = 0; j < 16; j++) {
        int col = hh * 128 + j * 8 + ec2;
        uint32_t hp, lp;
        packhl(o[j][0] * il0, o[j][1] * il0, hp, lp);
        size_t off0 = ((size_t)b * S_ + row0) * D_ + col;
        *(uint32_t*)(oh_ + off0) = hp;
        *(uint32_t*)(ol_ + off0) = lp;
        packhl(o[j][2] * il1, o[j][3] * il1, hp, lp);
        size_t off1 = ((size_t)b * S_ + row0 + 8) * D_ + col;
        *(uint32_t*)(oh_ + off1) = hp;
        *(uint32_t*)(ol_ + off1) = lp;
    }
}

// ---------------------------------------------------------------------------
// Launch
// ---------------------------------------------------------------------------
extern "C" void kernel_launch(void* const* d_in, const int* in_sizes, int n_in,
                              void* d_out, int out_size)
{
    (void)in_sizes; (void)n_in; (void)out_size;
    const float* x    = (const float*)d_in[0];
    const float* Wqkv = (const float*)d_in[1];
    const float* bqkv = (const float*)d_in[2];
    const float* Wo   = (const float*)d_in[3];
    const float* bo   = (const float*)d_in[4];
    float* out = (float*)d_out;

    __nv_bfloat16 *xhi, *xlo, *w1hi, *w1lo, *w2hi, *w2lo;
    __nv_bfloat16 *qhi, *qlo, *khi, *klo, *vhi, *vlo, *ahi, *alo;
    cudaGetSymbolAddress((void**)&xhi, g_xhi);   cudaGetSymbolAddress((void**)&xlo, g_xlo);
    cudaGetSymbolAddress((void**)&w1hi, g_w1hi); cudaGetSymbolAddress((void**)&w1lo, g_w1lo);
    cudaGetSymbolAddress((void**)&w2hi, g_w2hi); cudaGetSymbolAddress((void**)&w2lo, g_w2lo);
    cudaGetSymbolAddress((void**)&qhi, g_qhi);   cudaGetSymbolAddress((void**)&qlo, g_qlo);
    cudaGetSymbolAddress((void**)&khi, g_khi);   cudaGetSymbolAddress((void**)&klo, g_klo);
    cudaGetSymbolAddress((void**)&vhi, g_vhi);   cudaGetSymbolAddress((void**)&vlo, g_vlo);
    cudaGetSymbolAddress((void**)&ahi, g_ahi);   cudaGetSymbolAddress((void**)&alo, g_alo);

    cudaFuncSetAttribute((const void*)gemm_bf16x3<0, D_>,
                         cudaFuncAttributeMaxDynamicSharedMemorySize, GEMM_DYN_SMEM);
    cudaFuncSetAttribute((const void*)gemm_bf16x3<1, 3 * D_>,
                         cudaFuncAttributeMaxDynamicSharedMemorySize, GEMM_DYN_SMEM);
    cudaFuncSetAttribute(flash_mma,
                         cudaFuncAttributeMaxDynamicSharedMemorySize, FLASH_DYN_SMEM);

    // 1) split x
    {
        int n4 = (M_ * D_) / 4;
        split_f32<<<(n4 + 255) / 256, 256>>>(x, xhi, xlo, n4);
    }
    // 2) transpose+split weights
    transpose_split<<<dim3((3 * D_) / 32, D_ / 32), dim3(32, 8)>>>(Wqkv, w1hi, w1lo, D_, 3 * D_);
    transpose_split<<<dim3(D_ / 32, D_ / 32), dim3(32, 8)>>>(Wo, w2hi, w2lo, D_, D_);

    // 3) QKV GEMM with fused bias+scale+split+scatter epilogue
    gemm_bf16x3<1, 3 * D_><<<dim3((3 * D_) / 256, M_ / 128), 256, GEMM_DYN_SMEM>>>(
        xhi, xlo, w1hi, w1lo, bqkv, nullptr,
        qhi, qlo, khi, klo, vhi, vlo);

    // 4) HMMA flash attention
    flash_mma<<<dim3(S_ / 128, H_, B_), 256, FLASH_DYN_SMEM>>>(
        qhi, qlo, khi, klo, vhi, vlo, ahi, alo);

    // 5) out = attn @ Wo + bo
    gemm_bf16x3<0, D_><<<dim3(D_ / 256, M_ / 128), 256, GEMM_DYN_SMEM>>>(
        ahi, alo, w2hi, w2lo, bo, out,
        nullptr, nullptr, nullptr, nullptr, nullptr, nullptr);
}

// round 8
// speedup vs baseline: 1.1354x; 1.1224x over previous
#include <cuda_runtime.h>
#include <cuda_bf16.h>
#include <cuda_fp16.h>
#include <cstdint>
#include <cstddef>

// ---------------------------------------------------------------------------
// Problem constants
// ---------------------------------------------------------------------------
#define B_  2
#define S_  2048
#define D_  2048
#define H_  16
#define HD_ 128
#define M_  (B_*S_)            // 4096 rows
#define K_  2048               // inner dim of BOTH gemms (compile-time)
#define SCALE_ 0.08838834764831845f

// ---------------------------------------------------------------------------
// Scratch (__device__ globals; no allocation allowed)
// ---------------------------------------------------------------------------
__device__ __nv_bfloat16 g_xhi[(size_t)M_ * D_];
__device__ __nv_bfloat16 g_xlo[(size_t)M_ * D_];
__device__ __nv_bfloat16 g_w1hi[(size_t)3 * D_ * D_];   // Wqkv^T [6144,2048]
__device__ __nv_bfloat16 g_w1lo[(size_t)3 * D_ * D_];
__device__ __half        g_w2h[(size_t)D_ * D_];        // Wo^T [2048,2048] fp16
// q/k/v in [B,H,S,HD] bf16 hi/lo (q pre-scaled by 1/sqrt(HD))
__device__ __nv_bfloat16 g_qhi[(size_t)M_ * D_];
__device__ __nv_bfloat16 g_qlo[(size_t)M_ * D_];
__device__ __nv_bfloat16 g_khi[(size_t)M_ * D_];
__device__ __nv_bfloat16 g_klo[(size_t)M_ * D_];
__device__ __nv_bfloat16 g_vhi[(size_t)M_ * D_];
__device__ __nv_bfloat16 g_vlo[(size_t)M_ * D_];
// attention output [B,S,D] fp16 hi/lo (feeds fp16x2 proj)
__device__ __half g_ahi[(size_t)M_ * D_];
__device__ __half g_alo[(size_t)M_ * D_];

// ---------------------------------------------------------------------------
// Portable PTX helpers (virtual arch compute_103: no tcgen05)
// ---------------------------------------------------------------------------
__device__ __forceinline__ uint32_t smem_u32(const void* p) {
    uint32_t a;
    asm("{ .reg .u64 t; cvta.to.shared.u64 t, %1; cvt.u32.u64 %0, t; }"
        : "=r"(a) : "l"(p));
    return a;
}

#define CP16(dst_u32, src_ptr) \
    asm volatile("cp.async.cg.shared.global [%0], [%1], 16;" \
                 :: "r"(dst_u32), "l"(src_ptr) : "memory")
#define CP_COMMIT() asm volatile("cp.async.commit_group;" ::: "memory")
#define CP_WAIT(n)  asm volatile("cp.async.wait_group %0;" :: "n"(n) : "memory")

#define LDSM_X4(r0, r1, r2, r3, addr) \
    asm volatile("ldmatrix.sync.aligned.m8n8.x4.shared.b16 {%0,%1,%2,%3}, [%4];" \
                 : "=r"(r0), "=r"(r1), "=r"(r2), "=r"(r3) : "r"(addr))
#define LDSM_X4T(r0, r1, r2, r3, addr) \
    asm volatile("ldmatrix.sync.aligned.m8n8.x4.trans.shared.b16 {%0,%1,%2,%3}, [%4];" \
                 : "=r"(r0), "=r"(r1), "=r"(r2), "=r"(r3) : "r"(addr))

__device__ __forceinline__ void mma16816(float* d, const uint32_t* a,
                                         const uint32_t* b) {
    asm volatile(
        "mma.sync.aligned.m16n8k16.row.col.f32.bf16.bf16.f32 "
        "{%0,%1,%2,%3}, {%4,%5,%6,%7}, {%8,%9}, {%0,%1,%2,%3};"
        : "+f"(d[0]), "+f"(d[1]), "+f"(d[2]), "+f"(d[3])
        : "r"(a[0]), "r"(a[1]), "r"(a[2]), "r"(a[3]), "r"(b[0]), "r"(b[1]));
}
__device__ __forceinline__ void mma16816h(float* d, const uint32_t* a,
                                          const uint32_t* b) {
    asm volatile(
        "mma.sync.aligned.m16n8k16.row.col.f32.f16.f16.f32 "
        "{%0,%1,%2,%3}, {%4,%5,%6,%7}, {%8,%9}, {%0,%1,%2,%3};"
        : "+f"(d[0]), "+f"(d[1]), "+f"(d[2]), "+f"(d[3])
        : "r"(a[0]), "r"(a[1]), "r"(a[2]), "r"(a[3]), "r"(b[0]), "r"(b[1]));
}

__device__ __forceinline__ void split1(float v, __nv_bfloat16& h, __nv_bfloat16& l) {
    h = __float2bfloat16(v);
    l = __float2bfloat16(v - __bfloat162float(h));
}

// pack two floats -> bf16x2 hi + bf16x2 lo(residual)
__device__ __forceinline__ void packhl(float x, float y, uint32_t& hp, uint32_t& lp) {
    __nv_bfloat162 hv = __floats2bfloat162_rn(x, y);
    float rx = x - __bfloat162float(__low2bfloat16(hv));
    float ry = y - __bfloat162float(__high2bfloat16(hv));
    __nv_bfloat162 lv = __floats2bfloat162_rn(rx, ry);
    hp = *reinterpret_cast<uint32_t*>(&hv);
    lp = *reinterpret_cast<uint32_t*>(&lv);
}
// pack two floats -> fp16x2 hi + fp16x2 lo(residual)
__device__ __forceinline__ void packhl_h(float x, float y, uint32_t& hp, uint32_t& lp) {
    __half2 hv = __floats2half2_rn(x, y);
    float rx = x - __half2float(__low2half(hv));
    float ry = y - __half2float(__high2half(hv));
    __half2 lv = __floats2half2_rn(rx, ry);
    hp = *reinterpret_cast<uint32_t*>(&hv);
    lp = *reinterpret_cast<uint32_t*>(&lv);
}

// ---------------------------------------------------------------------------
// split / transpose pre-passes
// ---------------------------------------------------------------------------
__global__ void split_f32(const float* __restrict__ in,
                          __nv_bfloat16* __restrict__ hi,
                          __nv_bfloat16* __restrict__ lo, int n4) {
    int i = blockIdx.x * blockDim.x + threadIdx.x;
    if (i >= n4) return;
    float4 v = *(const float4*)(in + (size_t)i * 4);
    uint32_t h0, h1, l0, l1;
    packhl(v.x, v.y, h0, l0);
    packhl(v.z, v.w, h1, l1);
    uint32_t* hp = (uint32_t*)(hi + (size_t)i * 4);
    uint32_t* lp = (uint32_t*)(lo + (size_t)i * 4);
    hp[0] = h0; hp[1] = h1;
    lp[0] = l0; lp[1] = l1;
}

__global__ void transpose_split(const float* __restrict__ W,
                                __nv_bfloat16* __restrict__ Th,
                                __nv_bfloat16* __restrict__ Tl, int K, int N) {
    __shared__ float t[32][33];
    int n0 = blockIdx.x * 32, k0 = blockIdx.y * 32;
    int tx = threadIdx.x, ty = threadIdx.y;      // (32,8)
    #pragma unroll
    for (int j = 0; j < 32; j += 8)
        t[ty + j][tx] = W[(size_t)(k0 + ty + j) * N + n0 + tx];
    __syncthreads();
    #pragma unroll
    for (int j = 0; j < 32; j += 8) {
        float v = t[tx][ty + j];
        __nv_bfloat16 h, l; split1(v, h, l);
        size_t o = (size_t)(n0 + ty + j) * K + k0 + tx;
        Th[o] = h; Tl[o] = l;
    }
}

__global__ void transpose_h(const float* __restrict__ W,
                            __half* __restrict__ Th, int K, int N) {
    __shared__ float t[32][33];
    int n0 = blockIdx.x * 32, k0 = blockIdx.y * 32;
    int tx = threadIdx.x, ty = threadIdx.y;      // (32,8)
    #pragma unroll
    for (int j = 0; j < 32; j += 8)
        t[ty + j][tx] = W[(size_t)(k0 + ty + j) * N + n0 + tx];
    __syncthreads();
    #pragma unroll
    for (int j = 0; j < 32; j += 8)
        Th[(size_t)(n0 + ty + j) * K + k0 + tx] = __float2half(t[tx][ty + j]);
}

// ---------------------------------------------------------------------------
// shared swizzle: 64B rows, chunk ^= (row>>1)&3
// ---------------------------------------------------------------------------
#define GBK 32
#define GSWZ(r, c) ((uint32_t)(r) * 64u + ((((uint32_t)(c) ^ (((uint32_t)(r) >> 1) & 3u))) << 4))

// ---------------------------------------------------------------------------
// QKV GEMM (bf16x3):  BM=128, BN=192, BK=32, 8 warps (2x4), warp 64x48,
// 4-stage cp.async.  Epilogue: bias+scale+split+scatter into q/k/v.
// Grid 32x32 = 1024 CTAs -> 6.92 waves (98.8% wave util).
// ---------------------------------------------------------------------------
#define QOFF_AH 0
#define QOFF_AL 8192
#define QOFF_BH 16384
#define QOFF_BL 28672                 // B: 192 rows * 64B = 12288
#define QSTAGEB 40960
#define QNSTAGE 4
#define QKV_DYN_SMEM (QNSTAGE * QSTAGEB)   // 163840

__global__ __launch_bounds__(256, 1) void gemm_qkv(
    const __nv_bfloat16* __restrict__ Ah, const __nv_bfloat16* __restrict__ Al,
    const __nv_bfloat16* __restrict__ Bh, const __nv_bfloat16* __restrict__ Bl,
    const float* __restrict__ bias,
    __nv_bfloat16* __restrict__ qh, __nv_bfloat16* __restrict__ ql,
    __nv_bfloat16* __restrict__ kh, __nv_bfloat16* __restrict__ kl,
    __nv_bfloat16* __restrict__ vh, __nv_bfloat16* __restrict__ vl)
{
    extern __shared__ __align__(128) char sm[];
    const uint32_t sbase = smem_u32(sm);

    const int tid = threadIdx.x;
    const int wid = tid >> 5;
    const int lane = tid & 31;
    const int m0 = blockIdx.y * 128;
    const int n0 = blockIdx.x * 192;
    const int wm = (wid >> 2) * 64;      // 0 / 64
    const int wn = (wid & 3) * 48;       // 0/48/96/144

    const int tr = tid >> 2;             // 0..63
    const int pc = tid & 3;              // chunk 0..3
    const __nv_bfloat16* pAh = Ah + (m0 + tr) * K_ + pc * 8;
    const __nv_bfloat16* pAl = Al + (m0 + tr) * K_ + pc * 8;
    const __nv_bfloat16* pBh = Bh + (n0 + tr) * K_ + pc * 8;
    const __nv_bfloat16* pBl = Bl + (n0 + tr) * K_ + pc * 8;
    const uint32_t dT0 = GSWZ(tr, pc);
    const uint32_t dT1 = GSWZ(tr + 64, pc);
    const uint32_t dT2 = GSWZ(tr + 128, pc);

    auto produce = [&](int stg, int kblk) {
        uint32_t s = sbase + stg * QSTAGEB;
        CP16(s + QOFF_AH + dT0, pAh + kblk);
        CP16(s + QOFF_AL + dT0, pAl + kblk);
        CP16(s + QOFF_AH + dT1, pAh + 64 * K_ + kblk);
        CP16(s + QOFF_AL + dT1, pAl + 64 * K_ + kblk);
        CP16(s + QOFF_BH + dT0, pBh + kblk);
        CP16(s + QOFF_BL + dT0, pBl + kblk);
        CP16(s + QOFF_BH + dT1, pBh + 64 * K_ + kblk);
        CP16(s + QOFF_BL + dT1, pBl + 64 * K_ + kblk);
        CP16(s + QOFF_BH + dT2, pBh + 128 * K_ + kblk);
        CP16(s + QOFF_BL + dT2, pBl + 128 * K_ + kblk);
    };

    float acc[4][6][4];
    #pragma unroll
    for (int i = 0; i < 4; i++)
        #pragma unroll
        for (int j = 0; j < 6; j++)
            #pragma unroll
            for (int r = 0; r < 4; r++) acc[i][j][r] = 0.f;

    uint32_t aoff[4], boff[3];
    #pragma unroll
    for (int ti = 0; ti < 4; ti++)
        aoff[ti] = GSWZ(wm + ti * 16 + (lane & 15), (lane >> 4));
    #pragma unroll
    for (int pj = 0; pj < 3; pj++)
        boff[pj] = GSWZ(wn + pj * 16 + (lane & 7) + ((lane >> 4) & 1) * 8,
                        ((lane >> 3) & 1));

    auto compute = [&](int stg) {
        uint32_t s = sbase + stg * QSTAGEB;
        #pragma unroll
        for (int ks = 0; ks < 2; ks++) {
            const uint32_t kx = ks ? 0x20u : 0u;
            uint32_t ah[4][4], al[4][4];
            #pragma unroll
            for (int ti = 0; ti < 4; ti++) {
                uint32_t ad = s + (aoff[ti] ^ kx);
                LDSM_X4(ah[ti][0], ah[ti][1], ah[ti][2], ah[ti][3], ad + QOFF_AH);
                LDSM_X4(al[ti][0], al[ti][1], al[ti][2], al[ti][3], ad + QOFF_AL);
            }
            #pragma unroll
            for (int pj = 0; pj < 3; pj++) {
                uint32_t bd = s + (boff[pj] ^ kx);
                uint32_t h0, h1, h2, h3, g0, g1, g2, g3;
                LDSM_X4(h0, h1, h2, h3, bd + QOFF_BH);
                LDSM_X4(g0, g1, g2, g3, bd + QOFF_BL);
                uint32_t bh0[2] = {h0, h1}, bh1[2] = {h2, h3};
                uint32_t bl0[2] = {g0, g1}, bl1[2] = {g2, g3};
                #pragma unroll
                for (int ti = 0; ti < 4; ti++) {
                    mma16816(acc[ti][2 * pj],     ah[ti], bh0);
                    mma16816(acc[ti][2 * pj + 1], ah[ti], bh1);
                }
                #pragma unroll
                for (int ti = 0; ti < 4; ti++) {
                    mma16816(acc[ti][2 * pj],     ah[ti], bl0);
                    mma16816(acc[ti][2 * pj + 1], ah[ti], bl1);
                }
                #pragma unroll
                for (int ti = 0; ti < 4; ti++) {
                    mma16816(acc[ti][2 * pj],     al[ti], bh0);
                    mma16816(acc[ti][2 * pj + 1], al[ti], bh1);
                }
            }
        }
    };

    const int NK = K_ / GBK;             // 64
    produce(0, 0); CP_COMMIT();
    produce(1, GBK); CP_COMMIT();
    produce(2, 2 * GBK); CP_COMMIT();

    for (int it = 0; it < NK; ++it) {
        CP_WAIT(2);
        __syncthreads();
        compute(it & (QNSTAGE - 1));
        if (it + 3 < NK) produce((it + 3) & (QNSTAGE - 1), (it + 3) * GBK);
        CP_COMMIT();
    }

    // ---- epilogue: scatter into q/k/v [B,H,S,HD] bf16 hi/lo (q scaled) ----
    const int er = lane >> 2;
    const int ec = (lane & 3) * 2;
    #pragma unroll
    for (int tj = 0; tj < 6; tj++) {
        int col = n0 + wn + tj * 8 + ec;
        int hh = col / 384, rem = col % 384;
        int which = rem >> 7, hd = rem & 127;
        __nv_bfloat16* dh = which == 0 ? qh : (which == 1 ? kh : vh);
        __nv_bfloat16* dl = which == 0 ? ql : (which == 1 ? kl : vl);
        float sc = which == 0 ? SCALE_ : 1.0f;
        float bx = bias[col], by = bias[col + 1];
        #pragma unroll
        for (int ti = 0; ti < 4; ti++) {
            #pragma unroll
            for (int rr = 0; rr < 2; rr++) {
                int row = m0 + wm + ti * 16 + er + rr * 8;
                int bb = row >> 11, ss = row & 2047;
                size_t off = (((size_t)(bb * H_ + hh)) * S_ + ss) * HD_ + hd;
                float vx = (acc[ti][tj][rr * 2] + bx) * sc;
                float vy = (acc[ti][tj][rr * 2 + 1] + by) * sc;
                uint32_t hp, lp;
                packhl(vx, vy, hp, lp);
                *(uint32_t*)(dh + off) = hp;
                *(uint32_t*)(dl + off) = lp;
            }
        }
    }
}

// ---------------------------------------------------------------------------
// Proj GEMM (fp16x2):  C = A @ Bt^T + bias.  A fp16 hi/lo, B single fp16.
// BM=128, BN=256, BK=32, 8 warps (2x4), warp 64x64, 4-stage cp.async.
// 2 MMA terms per k-step (Ah*B + Al*B).
// ---------------------------------------------------------------------------
#define POFF_AH 0
#define POFF_AL 8192
#define POFF_B  16384                 // B: 256 rows * 64B = 16384
#define PSTAGEB 32768
#define PNSTAGE 4
#define PROJ_DYN_SMEM (PNSTAGE * PSTAGEB)   // 131072

__global__ __launch_bounds__(256, 1) void gemm_proj(
    const __half* __restrict__ Ah, const __half* __restrict__ Al,
    const __half* __restrict__ Bm,
    const float* __restrict__ bias, float* __restrict__ C)
{
    extern __shared__ __align__(128) char sm[];
    const uint32_t sbase = smem_u32(sm);

    const int tid = threadIdx.x;
    const int wid = tid >> 5;
    const int lane = tid & 31;
    const int m0 = blockIdx.y * 128;
    const int n0 = blockIdx.x * 256;
    const int wm = (wid >> 2) * 64;
    const int wn = (wid & 3) * 64;

    const int tr = tid >> 2;
    const int pc = tid & 3;
    const __half* pAh = Ah + (m0 + tr) * K_ + pc * 8;
    const __half* pAl = Al + (m0 + tr) * K_ + pc * 8;
    const __half* pB  = Bm + (n0 + tr) * K_ + pc * 8;
    const uint32_t dT0 = GSWZ(tr, pc);
    const uint32_t dT1 = GSWZ(tr + 64, pc);
    const uint32_t dT2 = GSWZ(tr + 128, pc);
    const uint32_t dT3 = GSWZ(tr + 192, pc);

    auto produce = [&](int stg, int kblk) {
        uint32_t s = sbase + stg * PSTAGEB;
        CP16(s + POFF_AH + dT0, pAh + kblk);
        CP16(s + POFF_AL + dT0, pAl + kblk);
        CP16(s + POFF_AH + dT1, pAh + 64 * K_ + kblk);
        CP16(s + POFF_AL + dT1, pAl + 64 * K_ + kblk);
        CP16(s + POFF_B + dT0, pB + kblk);
        CP16(s + POFF_B + dT1, pB + 64 * K_ + kblk);
        CP16(s + POFF_B + dT2, pB + 128 * K_ + kblk);
        CP16(s + POFF_B + dT3, pB + 192 * K_ + kblk);
    };

    float acc[4][8][4];
    #pragma unroll
    for (int i = 0; i < 4; i++)
        #pragma unroll
        for (int j = 0; j < 8; j++)
            #pragma unroll
            for (int r = 0; r < 4; r++) acc[i][j][r] = 0.f;

    uint32_t aoff[4], boff[4];
    #pragma unroll
    for (int ti = 0; ti < 4; ti++)
        aoff[ti] = GSWZ(wm + ti * 16 + (lane & 15), (lane >> 4));
    #pragma unroll
    for (int pj = 0; pj < 4; pj++)
        boff[pj] = GSWZ(wn + pj * 16 + (lane & 7) + ((lane >> 4) & 1) * 8,
                        ((lane >> 3) & 1));

    auto compute = [&](int stg) {
        uint32_t s = sbase + stg * PSTAGEB;
        #pragma unroll
        for (int ks = 0; ks < 2; ks++) {
            const uint32_t kx = ks ? 0x20u : 0u;
            uint32_t ah[4][4], al[4][4];
            #pragma unroll
            for (int ti = 0; ti < 4; ti++) {
                uint32_t ad = s + (aoff[ti] ^ kx);
                LDSM_X4(ah[ti][0], ah[ti][1], ah[ti][2], ah[ti][3], ad + POFF_AH);
                LDSM_X4(al[ti][0], al[ti][1], al[ti][2], al[ti][3], ad + POFF_AL);
            }
            #pragma unroll
            for (int pj = 0; pj < 4; pj++) {
                uint32_t bd = s + (boff[pj] ^ kx);
                uint32_t h0, h1, h2, h3;
                LDSM_X4(h0, h1, h2, h3, bd + POFF_B);
                uint32_t bh0[2] = {h0, h1}, bh1[2] = {h2, h3};
                #pragma unroll
                for (int ti = 0; ti < 4; ti++) {
                    mma16816h(acc[ti][2 * pj],     ah[ti], bh0);
                    mma16816h(acc[ti][2 * pj + 1], ah[ti], bh1);
                }
                #pragma unroll
                for (int ti = 0; ti < 4; ti++) {
                    mma16816h(acc[ti][2 * pj],     al[ti], bh0);
                    mma16816h(acc[ti][2 * pj + 1], al[ti], bh1);
                }
            }
        }
    };

    const int NK = K_ / GBK;
    produce(0, 0); CP_COMMIT();
    produce(1, GBK); CP_COMMIT();
    produce(2, 2 * GBK); CP_COMMIT();

    for (int it = 0; it < NK; ++it) {
        CP_WAIT(2);
        __syncthreads();
        compute(it & (PNSTAGE - 1));
        if (it + 3 < NK) produce((it + 3) & (PNSTAGE - 1), (it + 3) * GBK);
        CP_COMMIT();
    }

    const int er = lane >> 2;
    const int ec = (lane & 3) * 2;
    #pragma unroll
    for (int tj = 0; tj < 8; tj++) {
        int col = n0 + wn + tj * 8 + ec;
        float bx = bias[col], by = bias[col + 1];
        #pragma unroll
        for (int ti = 0; ti < 4; ti++) {
            int row = m0 + wm + ti * 16 + er;
            float2 v0 = { acc[ti][tj][0] + bx, acc[ti][tj][1] + by };
            float2 v1 = { acc[ti][tj][2] + bx, acc[ti][tj][3] + by };
            *(float2*)(C + (size_t)row * D_ + col) = v0;
            *(float2*)(C + (size_t)(row + 8) * D_ + col) = v1;
        }
    }
}

// ---------------------------------------------------------------------------
// HMMA causal flash attention, bf16x3, FA2-style register softmax.
// BQ=128 (8 warps x 16 rows), BKV=64, HD=128. Double-buffered KV via cp.async.
// Output written as fp16 hi/lo (feeds fp16x2 proj GEMM).
// ---------------------------------------------------------------------------
#define FROWB 272                      // 128 bf16 + 8 pad = 136 elems
#define FQBYTES (128 * FROWB)          // per Q array
#define FKBYTES (64 * FROWB)           // per K/V array
#define FSTGB (4 * FKBYTES)            // kh,kl,vh,vl
#define FLASH_DYN_SMEM (2 * FQBYTES + 2 * FSTGB)   // 208896 B

__global__ __launch_bounds__(256, 1) void flash_mma(
    const __nv_bfloat16* __restrict__ qh_, const __nv_bfloat16* __restrict__ ql_,
    const __nv_bfloat16* __restrict__ kh_, const __nv_bfloat16* __restrict__ kl_,
    const __nv_bfloat16* __restrict__ vh_, const __nv_bfloat16* __restrict__ vl_,
    __half* __restrict__ oh_, __half* __restrict__ ol_)
{
    extern __shared__ __align__(128) char fsm[];
    const uint32_t sb = smem_u32(fsm);
    const int tid = threadIdx.x, wq = tid >> 5, lane = tid & 31;
    const int bi = (int)gridDim.x - 1 - (int)blockIdx.x;   // big blocks first
    const int hh = blockIdx.y, b = blockIdx.z;
    const int q0 = bi * 128;
    const size_t bh = ((size_t)b * H_ + hh) * S_;
    const uint32_t QH = sb, QL = sb + FQBYTES;
    const uint32_t KV0 = sb + 2 * FQBYTES;

    // Q tile load (both hi/lo)
    #pragma unroll
    for (int i = 0; i < 8; i++) {
        int id = tid + i * 256;
        int r = id >> 4, c = id & 15;
        size_t src = (bh + q0 + r) * HD_ + c * 8;
        CP16(QH + r * FROWB + c * 16, qh_ + src);
        CP16(QL + r * FROWB + c * 16, ql_ + src);
    }
    auto produce = [&](int stg, int kt) {
        uint32_t s = KV0 + stg * FSTGB;
        int k0 = kt * 64;
        #pragma unroll
        for (int i = 0; i < 4; i++) {
            int id = tid + i * 256;
            int r = id >> 4, c = id & 15;
            size_t src = (bh + k0 + r) * HD_ + c * 8;
            uint32_t d = r * FROWB + c * 16;
            CP16(s + d, kh_ + src);
            CP16(s + FKBYTES + d, kl_ + src);
            CP16(s + 2 * FKBYTES + d, vh_ + src);
            CP16(s + 3 * FKBYTES + d, vl_ + src);
        }
    };

    float o[16][4];
    #pragma unroll
    for (int j = 0; j < 16; j++)
        #pragma unroll
        for (int r = 0; r < 4; r++) o[j][r] = 0.f;
    float m0 = -1e30f, m1 = -1e30f, l0 = 0.f, l1 = 0.f;

    const int er = lane >> 2, ec2 = (lane & 3) * 2;
    const uint32_t a_row = wq * 16 + (lane & 15);
    const uint32_t a_kb  = (lane >> 4) * 16;
    const uint32_t b_row = (lane & 7) + ((lane >> 4) & 1) * 8;
    const uint32_t b_kb  = ((lane >> 3) & 1) * 16;
    const uint32_t v_row = (lane & 7) + ((lane >> 3) & 1) * 8;
    const uint32_t v_cb  = ((lane >> 4) & 1) * 16;

    const int nkt = 2 * bi + 2;
    produce(0, 0);
    CP_COMMIT();

    for (int kt = 0; kt < nkt; kt++) {
        if (kt + 1 < nkt) { produce((kt + 1) & 1, kt + 1); CP_COMMIT(); CP_WAIT(1); }
        else CP_WAIT(0);
        __syncthreads();
        const uint32_t kb = KV0 + (kt & 1) * FSTGB;

        // ---- phase 1: S = Q K^T (bf16x3) ----
        float s[8][4];
        #pragma unroll
        for (int j = 0; j < 8; j++)
            #pragma unroll
            for (int r = 0; r < 4; r++) s[j][r] = 0.f;

        #pragma unroll
        for (int ks = 0; ks < 8; ks++) {
            uint32_t ah[4], al[4];
            uint32_t qa = QH + a_row * FROWB + ks * 32 + a_kb;
            LDSM_X4(ah[0], ah[1], ah[2], ah[3], qa);
            LDSM_X4(al[0], al[1], al[2], al[3], qa + FQBYTES);
            #pragma unroll
            for (int bj = 0; bj < 4; bj++) {
                uint32_t ka = kb + (bj * 16 + b_row) * FROWB + ks * 32 + b_kb;
                uint32_t h0, h1, h2, h3, g0, g1, g2, g3;
                LDSM_X4(h0, h1, h2, h3, ka);
                LDSM_X4(g0, g1, g2, g3, ka + FKBYTES);
                uint32_t bhi0[2] = {h0, h1}, bhi1[2] = {h2, h3};
                uint32_t blo0[2] = {g0, g1}, blo1[2] = {g2, g3};
                mma16816(s[2 * bj], ah, bhi0);
                mma16816(s[2 * bj], ah, blo0);
                mma16816(s[2 * bj], al, bhi0);
                mma16816(s[2 * bj + 1], ah, bhi1);
                mma16816(s[2 * bj + 1], ah, blo1);
                mma16816(s[2 * bj + 1], al, bhi1);
            }
        }

        // ---- causal mask (only last two tiles) ----
        if (kt >= 2 * bi) {
            int row0 = q0 + wq * 16 + er, row1 = row0 + 8;
            int colb = kt * 64 + ec2;
            #pragma unroll
            for (int j = 0; j < 8; j++) {
                int c0 = colb + j * 8, c1 = c0 + 1;
                if (c0 > row0) s[j][0] = -1e30f;
                if (c1 > row0) s[j][1] = -1e30f;
                if (c0 > row1) s[j][2] = -1e30f;
                if (c1 > row1) s[j][3] = -1e30f;
            }
        }

        // ---- online softmax (rows er / er+8) ----
        float mx0 = -1e30f, mx1 = -1e30f;
        #pragma unroll
        for (int j = 0; j < 8; j++) {
            mx0 = fmaxf(mx0, fmaxf(s[j][0], s[j][1]));
            mx1 = fmaxf(mx1, fmaxf(s[j][2], s[j][3]));
        }
        mx0 = fmaxf(mx0, __shfl_xor_sync(0xffffffffu, mx0, 1));
        mx0 = fmaxf(mx0, __shfl_xor_sync(0xffffffffu, mx0, 2));
        mx1 = fmaxf(mx1, __shfl_xor_sync(0xffffffffu, mx1, 1));
        mx1 = fmaxf(mx1, __shfl_xor_sync(0xffffffffu, mx1, 2));
        float mn0 = fmaxf(m0, mx0), mn1 = fmaxf(m1, mx1);
        float al0 = __expf(m0 - mn0), al1 = __expf(m1 - mn1);
        m0 = mn0; m1 = mn1;
        float sm0 = 0.f, sm1 = 0.f;
        #pragma unroll
        for (int j = 0; j < 8; j++) {
            s[j][0] = __expf(s[j][0] - m0); sm0 += s[j][0];
            s[j][1] = __expf(s[j][1] - m0); sm0 += s[j][1];
            s[j][2] = __expf(s[j][2] - m1); sm1 += s[j][2];
            s[j][3] = __expf(s[j][3] - m1); sm1 += s[j][3];
        }
        sm0 += __shfl_xor_sync(0xffffffffu, sm0, 1);
        sm0 += __shfl_xor_sync(0xffffffffu, sm0, 2);
        sm1 += __shfl_xor_sync(0xffffffffu, sm1, 1);
        sm1 += __shfl_xor_sync(0xffffffffu, sm1, 2);
        l0 = l0 * al0 + sm0;
        l1 = l1 * al1 + sm1;
        #pragma unroll
        for (int j = 0; j < 16; j++) {
            o[j][0] *= al0; o[j][1] *= al0;
            o[j][2] *= al1; o[j][3] *= al1;
        }

        // ---- phase 2: O += P V (bf16x3; V via ldmatrix.trans) ----
        const uint32_t vbase = kb + 2 * FKBYTES;
        #pragma unroll
        for (int ki = 0; ki < 4; ki++) {
            uint32_t ph[4], pl[4];
            packhl(s[2 * ki][0],     s[2 * ki][1],     ph[0], pl[0]);
            packhl(s[2 * ki][2],     s[2 * ki][3],     ph[1], pl[1]);
            packhl(s[2 * ki + 1][0], s[2 * ki + 1][1], ph[2], pl[2]);
            packhl(s[2 * ki + 1][2], s[2 * ki + 1][3], ph[3], pl[3]);
            #pragma unroll
            for (int nj = 0; nj < 8; nj++) {
                uint32_t va = vbase + (ki * 16 + v_row) * FROWB + nj * 32 + v_cb;
                uint32_t h0, h1, h2, h3, g0, g1, g2, g3;
                LDSM_X4T(h0, h1, h2, h3, va);
                LDSM_X4T(g0, g1, g2, g3, va + FKBYTES);
                uint32_t vh0[2] = {h0, h1}, vh1[2] = {h2, h3};
                uint32_t vl0[2] = {g0, g1}, vl1[2] = {g2, g3};
                mma16816(o[2 * nj], ph, vh0);
                mma16816(o[2 * nj], ph, vl0);
                mma16816(o[2 * nj], pl, vh0);
                mma16816(o[2 * nj + 1], ph, vh1);
                mma16816(o[2 * nj + 1], ph, vl1);
                mma16816(o[2 * nj + 1], pl, vh1);
            }
        }
        __syncthreads();   // protect KV buffer before next produce overwrites
    }

    // ---- epilogue: normalize + fp16 hi/lo write ----
    float il0 = 1.f / l0, il1 = 1.f / l1;
    int row0 = q0 + wq * 16 + er;
    #pragma unroll
    for (int j = 0; j < 16; j++) {
        int col = hh * 128 + j * 8 + ec2;
        uint32_t hp, lp;
        packhl_h(o[j][0] * il0, o[j][1] * il0, hp, lp);
        size_t off0 = ((size_t)b * S_ + row0) * D_ + col;
        *(uint32_t*)(oh_ + off0) = hp;
        *(uint32_t*)(ol_ + off0) = lp;
        packhl_h(o[j][2] * il1, o[j][3] * il1, hp, lp);
        size_t off1 = ((size_t)b * S_ + row0 + 8) * D_ + col;
        *(uint32_t*)(oh_ + off1) = hp;
        *(uint32_t*)(ol_ + off1) = lp;
    }
}

// ---------------------------------------------------------------------------
// Launch
// ---------------------------------------------------------------------------
extern "C" void kernel_launch(void* const* d_in, const int* in_sizes, int n_in,
                              void* d_out, int out_size)
{
    (void)in_sizes; (void)n_in; (void)out_size;
    const float* x    = (const float*)d_in[0];
    const float* Wqkv = (const float*)d_in[1];
    const float* bqkv = (const float*)d_in[2];
    const float* Wo   = (const float*)d_in[3];
    const float* bo   = (const float*)d_in[4];
    float* out = (float*)d_out;

    __nv_bfloat16 *xhi, *xlo, *w1hi, *w1lo;
    __nv_bfloat16 *qhi, *qlo, *khi, *klo, *vhi, *vlo;
    __half *w2h, *ahi, *alo;
    cudaGetSymbolAddress((void**)&xhi, g_xhi);   cudaGetSymbolAddress((void**)&xlo, g_xlo);
    cudaGetSymbolAddress((void**)&w1hi, g_w1hi); cudaGetSymbolAddress((void**)&w1lo, g_w1lo);
    cudaGetSymbolAddress((void**)&w2h, g_w2h);
    cudaGetSymbolAddress((void**)&qhi, g_qhi);   cudaGetSymbolAddress((void**)&qlo, g_qlo);
    cudaGetSymbolAddress((void**)&khi, g_khi);   cudaGetSymbolAddress((void**)&klo, g_klo);
    cudaGetSymbolAddress((void**)&vhi, g_vhi);   cudaGetSymbolAddress((void**)&vlo, g_vlo);
    cudaGetSymbolAddress((void**)&ahi, g_ahi);   cudaGetSymbolAddress((void**)&alo, g_alo);

    cudaFuncSetAttribute(gemm_qkv,
                         cudaFuncAttributeMaxDynamicSharedMemorySize, QKV_DYN_SMEM);
    cudaFuncSetAttribute(gemm_proj,
                         cudaFuncAttributeMaxDynamicSharedMemorySize, PROJ_DYN_SMEM);
    cudaFuncSetAttribute(flash_mma,
                         cudaFuncAttributeMaxDynamicSharedMemorySize, FLASH_DYN_SMEM);

    // 1) split x
    {
        int n4 = (M_ * D_) / 4;
        split_f32<<<(n4 + 255) / 256, 256>>>(x, xhi, xlo, n4);
    }
    // 2) transpose+split weights
    transpose_split<<<dim3((3 * D_) / 32, D_ / 32), dim3(32, 8)>>>(Wqkv, w1hi, w1lo, D_, 3 * D_);
    transpose_h<<<dim3(D_ / 32, D_ / 32), dim3(32, 8)>>>(Wo, w2h, D_, D_);

    // 3) QKV GEMM (bf16x3, BN=192 -> 1024 CTAs, 98.8% wave util)
    gemm_qkv<<<dim3((3 * D_) / 192, M_ / 128), 256, QKV_DYN_SMEM>>>(
        xhi, xlo, w1hi, w1lo, bqkv,
        qhi, qlo, khi, klo, vhi, vlo);

    // 4) HMMA flash attention (outputs fp16 hi/lo)
    flash_mma<<<dim3(S_ / 128, H_, B_), 256, FLASH_DYN_SMEM>>>(
        qhi, qlo, khi, klo, vhi, vlo, ahi, alo);

    // 5) out = attn @ Wo + bo  (fp16x2, 2 MMA terms)
    gemm_proj<<<dim3(D_ / 256, M_ / 128), 256, PROJ_DYN_SMEM>>>(
        ahi, alo, w2h, bo, out);
}

// round 9
// speedup vs baseline: 1.3604x; 1.1982x over previous
#include <cuda_runtime.h>
#include <cuda_bf16.h>
#include <cuda_fp16.h>
#include <cstdint>
#include <cstddef>

// ---------------------------------------------------------------------------
// Problem constants
// ---------------------------------------------------------------------------
#define B_  2
#define S_  2048
#define D_  2048
#define H_  16
#define HD_ 128
#define M_  (B_*S_)            // 4096 rows
#define K_  2048               // inner dim of BOTH gemms (compile-time)
#define SCALE_ 0.08838834764831845f

// ---------------------------------------------------------------------------
// Scratch (__device__ globals; no allocation allowed)
// ---------------------------------------------------------------------------
__device__ __half g_xhi[(size_t)M_ * D_];               // x fp16 hi/lo
__device__ __half g_xlo[(size_t)M_ * D_];
__device__ __half g_w1h[(size_t)3 * D_ * D_];           // Wqkv^T [6144,2048] fp16
__device__ __half g_w2h[(size_t)D_ * D_];               // Wo^T [2048,2048] fp16
// q/k/v in [B,H,S,HD] bf16 hi/lo (q pre-scaled by 1/sqrt(HD))
__device__ __nv_bfloat16 g_qhi[(size_t)M_ * D_];
__device__ __nv_bfloat16 g_qlo[(size_t)M_ * D_];
__device__ __nv_bfloat16 g_khi[(size_t)M_ * D_];
__device__ __nv_bfloat16 g_klo[(size_t)M_ * D_];
__device__ __nv_bfloat16 g_vhi[(size_t)M_ * D_];
__device__ __nv_bfloat16 g_vlo[(size_t)M_ * D_];
// attention output [B,S,D] fp16 hi/lo (feeds fp16x2 proj)
__device__ __half g_ahi[(size_t)M_ * D_];
__device__ __half g_alo[(size_t)M_ * D_];

// ---------------------------------------------------------------------------
// Portable PTX helpers (virtual arch compute_103: no tcgen05)
// ---------------------------------------------------------------------------
__device__ __forceinline__ uint32_t smem_u32(const void* p) {
    uint32_t a;
    asm("{ .reg .u64 t; cvta.to.shared.u64 t, %1; cvt.u32.u64 %0, t; }"
        : "=r"(a) : "l"(p));
    return a;
}

#define CP16(dst_u32, src_ptr) \
    asm volatile("cp.async.cg.shared.global [%0], [%1], 16;" \
                 :: "r"(dst_u32), "l"(src_ptr) : "memory")
#define CP_COMMIT() asm volatile("cp.async.commit_group;" ::: "memory")
#define CP_WAIT(n)  asm volatile("cp.async.wait_group %0;" :: "n"(n) : "memory")

#define LDSM_X4(r0, r1, r2, r3, addr) \
    asm volatile("ldmatrix.sync.aligned.m8n8.x4.shared.b16 {%0,%1,%2,%3}, [%4];" \
                 : "=r"(r0), "=r"(r1), "=r"(r2), "=r"(r3) : "r"(addr))
#define LDSM_X4T(r0, r1, r2, r3, addr) \
    asm volatile("ldmatrix.sync.aligned.m8n8.x4.trans.shared.b16 {%0,%1,%2,%3}, [%4];" \
                 : "=r"(r0), "=r"(r1), "=r"(r2), "=r"(r3) : "r"(addr))

__device__ __forceinline__ void mma16816(float* d, const uint32_t* a,
                                         const uint32_t* b) {
    asm volatile(
        "mma.sync.aligned.m16n8k16.row.col.f32.bf16.bf16.f32 "
        "{%0,%1,%2,%3}, {%4,%5,%6,%7}, {%8,%9}, {%0,%1,%2,%3};"
        : "+f"(d[0]), "+f"(d[1]), "+f"(d[2]), "+f"(d[3])
        : "r"(a[0]), "r"(a[1]), "r"(a[2]), "r"(a[3]), "r"(b[0]), "r"(b[1]));
}
__device__ __forceinline__ void mma16816h(float* d, const uint32_t* a,
                                          const uint32_t* b) {
    asm volatile(
        "mma.sync.aligned.m16n8k16.row.col.f32.f16.f16.f32 "
        "{%0,%1,%2,%3}, {%4,%5,%6,%7}, {%8,%9}, {%0,%1,%2,%3};"
        : "+f"(d[0]), "+f"(d[1]), "+f"(d[2]), "+f"(d[3])
        : "r"(a[0]), "r"(a[1]), "r"(a[2]), "r"(a[3]), "r"(b[0]), "r"(b[1]));
}

__device__ __forceinline__ void split1(float v, __nv_bfloat16& h, __nv_bfloat16& l) {
    h = __float2bfloat16(v);
    l = __float2bfloat16(v - __bfloat162float(h));
}

// pack two floats -> bf16x2 hi + bf16x2 lo(residual)
__device__ __forceinline__ void packhl(float x, float y, uint32_t& hp, uint32_t& lp) {
    __nv_bfloat162 hv = __floats2bfloat162_rn(x, y);
    float rx = x - __bfloat162float(__low2bfloat16(hv));
    float ry = y - __bfloat162float(__high2bfloat16(hv));
    __nv_bfloat162 lv = __floats2bfloat162_rn(rx, ry);
    hp = *reinterpret_cast<uint32_t*>(&hv);
    lp = *reinterpret_cast<uint32_t*>(&lv);
}
// pack two floats -> fp16x2 hi + fp16x2 lo(residual)
__device__ __forceinline__ void packhl_h(float x, float y, uint32_t& hp, uint32_t& lp) {
    __half2 hv = __floats2half2_rn(x, y);
    float rx = x - __half2float(__low2half(hv));
    float ry = y - __half2float(__high2half(hv));
    __half2 lv = __floats2half2_rn(rx, ry);
    hp = *reinterpret_cast<uint32_t*>(&hv);
    lp = *reinterpret_cast<uint32_t*>(&lv);
}

// ---------------------------------------------------------------------------
// split / transpose pre-passes
// ---------------------------------------------------------------------------
__global__ void split_f32_h(const float* __restrict__ in,
                            __half* __restrict__ hi,
                            __half* __restrict__ lo, int n4) {
    int i = blockIdx.x * blockDim.x + threadIdx.x;
    if (i >= n4) return;
    float4 v = *(const float4*)(in + (size_t)i * 4);
    uint32_t h0, h1, l0, l1;
    packhl_h(v.x, v.y, h0, l0);
    packhl_h(v.z, v.w, h1, l1);
    uint32_t* hp = (uint32_t*)(hi + (size_t)i * 4);
    uint32_t* lp = (uint32_t*)(lo + (size_t)i * 4);
    hp[0] = h0; hp[1] = h1;
    lp[0] = l0; lp[1] = l1;
}

__global__ void transpose_h(const float* __restrict__ W,
                            __half* __restrict__ Th, int K, int N) {
    __shared__ float t[32][33];
    int n0 = blockIdx.x * 32, k0 = blockIdx.y * 32;
    int tx = threadIdx.x, ty = threadIdx.y;      // (32,8)
    #pragma unroll
    for (int j = 0; j < 32; j += 8)
        t[ty + j][tx] = W[(size_t)(k0 + ty + j) * N + n0 + tx];
    __syncthreads();
    #pragma unroll
    for (int j = 0; j < 32; j += 8)
        Th[(size_t)(n0 + ty + j) * K + k0 + tx] = __float2half(t[tx][ty + j]);
}

// ---------------------------------------------------------------------------
// shared swizzle: 64B rows, chunk ^= (row>>1)&3
// ---------------------------------------------------------------------------
#define GBK 32
#define GSWZ(r, c) ((uint32_t)(r) * 64u + ((((uint32_t)(c) ^ (((uint32_t)(r) >> 1) & 3u))) << 4))

// ---------------------------------------------------------------------------
// QKV GEMM (fp16x2):  BM=128, BN=192, BK=32, 8 warps (2x4), warp 64x48,
// 4-stage cp.async.  A = x fp16 hi/lo, B = Wqkv^T single fp16.
// Epilogue: bias+scale+split+scatter into q/k/v (bf16 hi/lo, full precision).
// Grid 32x32 = 1024 CTAs -> 6.92 waves (98.8% wave util).
// ---------------------------------------------------------------------------
#define QOFF_AH 0
#define QOFF_AL 8192
#define QOFF_B  16384                 // B: 192 rows * 64B = 12288
#define QSTAGEB 28672
#define QNSTAGE 4
#define QKV_DYN_SMEM (QNSTAGE * QSTAGEB)   // 114688

__global__ __launch_bounds__(256, 1) void gemm_qkv(
    const __half* __restrict__ Ah, const __half* __restrict__ Al,
    const __half* __restrict__ Bm,
    const float* __restrict__ bias,
    __nv_bfloat16* __restrict__ qh, __nv_bfloat16* __restrict__ ql,
    __nv_bfloat16* __restrict__ kh, __nv_bfloat16* __restrict__ kl,
    __nv_bfloat16* __restrict__ vh, __nv_bfloat16* __restrict__ vl)
{
    extern __shared__ __align__(128) char sm[];
    const uint32_t sbase = smem_u32(sm);

    const int tid = threadIdx.x;
    const int wid = tid >> 5;
    const int lane = tid & 31;
    const int m0 = blockIdx.y * 128;
    const int n0 = blockIdx.x * 192;
    const int wm = (wid >> 2) * 64;      // 0 / 64
    const int wn = (wid & 3) * 48;       // 0/48/96/144

    const int tr = tid >> 2;             // 0..63
    const int pc = tid & 3;              // chunk 0..3
    const __half* pAh = Ah + (m0 + tr) * K_ + pc * 8;
    const __half* pAl = Al + (m0 + tr) * K_ + pc * 8;
    const __half* pB  = Bm + (n0 + tr) * K_ + pc * 8;
    const uint32_t dT0 = GSWZ(tr, pc);
    const uint32_t dT1 = GSWZ(tr + 64, pc);
    const uint32_t dT2 = GSWZ(tr + 128, pc);

    auto produce = [&](int stg, int kblk) {
        uint32_t s = sbase + stg * QSTAGEB;
        CP16(s + QOFF_AH + dT0, pAh + kblk);
        CP16(s + QOFF_AL + dT0, pAl + kblk);
        CP16(s + QOFF_AH + dT1, pAh + 64 * K_ + kblk);
        CP16(s + QOFF_AL + dT1, pAl + 64 * K_ + kblk);
        CP16(s + QOFF_B + dT0, pB + kblk);
        CP16(s + QOFF_B + dT1, pB + 64 * K_ + kblk);
        CP16(s + QOFF_B + dT2, pB + 128 * K_ + kblk);
    };

    float acc[4][6][4];
    #pragma unroll
    for (int i = 0; i < 4; i++)
        #pragma unroll
        for (int j = 0; j < 6; j++)
            #pragma unroll
            for (int r = 0; r < 4; r++) acc[i][j][r] = 0.f;

    uint32_t aoff[4], boff[3];
    #pragma unroll
    for (int ti = 0; ti < 4; ti++)
        aoff[ti] = GSWZ(wm + ti * 16 + (lane & 15), (lane >> 4));
    #pragma unroll
    for (int pj = 0; pj < 3; pj++)
        boff[pj] = GSWZ(wn + pj * 16 + (lane & 7) + ((lane >> 4) & 1) * 8,
                        ((lane >> 3) & 1));

    auto compute = [&](int stg) {
        uint32_t s = sbase + stg * QSTAGEB;
        #pragma unroll
        for (int ks = 0; ks < 2; ks++) {
            const uint32_t kx = ks ? 0x20u : 0u;
            uint32_t ah[4][4], al[4][4];
            #pragma unroll
            for (int ti = 0; ti < 4; ti++) {
                uint32_t ad = s + (aoff[ti] ^ kx);
                LDSM_X4(ah[ti][0], ah[ti][1], ah[ti][2], ah[ti][3], ad + QOFF_AH);
                LDSM_X4(al[ti][0], al[ti][1], al[ti][2], al[ti][3], ad + QOFF_AL);
            }
            #pragma unroll
            for (int pj = 0; pj < 3; pj++) {
                uint32_t bd = s + (boff[pj] ^ kx);
                uint32_t h0, h1, h2, h3;
                LDSM_X4(h0, h1, h2, h3, bd + QOFF_B);
                uint32_t bh0[2] = {h0, h1}, bh1[2] = {h2, h3};
                #pragma unroll
                for (int ti = 0; ti < 4; ti++) {
                    mma16816h(acc[ti][2 * pj],     ah[ti], bh0);
                    mma16816h(acc[ti][2 * pj + 1], ah[ti], bh1);
                }
                #pragma unroll
                for (int ti = 0; ti < 4; ti++) {
                    mma16816h(acc[ti][2 * pj],     al[ti], bh0);
                    mma16816h(acc[ti][2 * pj + 1], al[ti], bh1);
                }
            }
        }
    };

    const int NK = K_ / GBK;             // 64
    produce(0, 0); CP_COMMIT();
    produce(1, GBK); CP_COMMIT();
    produce(2, 2 * GBK); CP_COMMIT();

    for (int it = 0; it < NK; ++it) {
        CP_WAIT(2);
        __syncthreads();
        compute(it & (QNSTAGE - 1));
        if (it + 3 < NK) produce((it + 3) & (QNSTAGE - 1), (it + 3) * GBK);
        CP_COMMIT();
    }

    // ---- epilogue: scatter into q/k/v [B,H,S,HD] bf16 hi/lo (q scaled) ----
    const int er = lane >> 2;
    const int ec = (lane & 3) * 2;
    #pragma unroll
    for (int tj = 0; tj < 6; tj++) {
        int col = n0 + wn + tj * 8 + ec;
        int hh = col / 384, rem = col % 384;
        int which = rem >> 7, hd = rem & 127;
        __nv_bfloat16* dh = which == 0 ? qh : (which == 1 ? kh : vh);
        __nv_bfloat16* dl = which == 0 ? ql : (which == 1 ? kl : vl);
        float sc = which == 0 ? SCALE_ : 1.0f;
        float bx = bias[col], by = bias[col + 1];
        #pragma unroll
        for (int ti = 0; ti < 4; ti++) {
            #pragma unroll
            for (int rr = 0; rr < 2; rr++) {
                int row = m0 + wm + ti * 16 + er + rr * 8;
                int bb = row >> 11, ss = row & 2047;
                size_t off = (((size_t)(bb * H_ + hh)) * S_ + ss) * HD_ + hd;
                float vx = (acc[ti][tj][rr * 2] + bx) * sc;
                float vy = (acc[ti][tj][rr * 2 + 1] + by) * sc;
                uint32_t hp, lp;
                packhl(vx, vy, hp, lp);
                *(uint32_t*)(dh + off) = hp;
                *(uint32_t*)(dl + off) = lp;
            }
        }
    }
}

// ---------------------------------------------------------------------------
// Proj GEMM (fp16x2):  C = A @ Bt^T + bias.  A fp16 hi/lo, B single fp16.
// BM=128, BN=256, BK=32, 8 warps (2x4), warp 64x64, 4-stage cp.async.
// ---------------------------------------------------------------------------
#define POFF_AH 0
#define POFF_AL 8192
#define POFF_B  16384                 // B: 256 rows * 64B = 16384
#define PSTAGEB 32768
#define PNSTAGE 4
#define PROJ_DYN_SMEM (PNSTAGE * PSTAGEB)   // 131072

__global__ __launch_bounds__(256, 1) void gemm_proj(
    const __half* __restrict__ Ah, const __half* __restrict__ Al,
    const __half* __restrict__ Bm,
    const float* __restrict__ bias, float* __restrict__ C)
{
    extern __shared__ __align__(128) char sm[];
    const uint32_t sbase = smem_u32(sm);

    const int tid = threadIdx.x;
    const int wid = tid >> 5;
    const int lane = tid & 31;
    const int m0 = blockIdx.y * 128;
    const int n0 = blockIdx.x * 256;
    const int wm = (wid >> 2) * 64;
    const int wn = (wid & 3) * 64;

    const int tr = tid >> 2;
    const int pc = tid & 3;
    const __half* pAh = Ah + (m0 + tr) * K_ + pc * 8;
    const __half* pAl = Al + (m0 + tr) * K_ + pc * 8;
    const __half* pB  = Bm + (n0 + tr) * K_ + pc * 8;
    const uint32_t dT0 = GSWZ(tr, pc);
    const uint32_t dT1 = GSWZ(tr + 64, pc);
    const uint32_t dT2 = GSWZ(tr + 128, pc);
    const uint32_t dT3 = GSWZ(tr + 192, pc);

    auto produce = [&](int stg, int kblk) {
        uint32_t s = sbase + stg * PSTAGEB;
        CP16(s + POFF_AH + dT0, pAh + kblk);
        CP16(s + POFF_AL + dT0, pAl + kblk);
        CP16(s + POFF_AH + dT1, pAh + 64 * K_ + kblk);
        CP16(s + POFF_AL + dT1, pAl + 64 * K_ + kblk);
        CP16(s + POFF_B + dT0, pB + kblk);
        CP16(s + POFF_B + dT1, pB + 64 * K_ + kblk);
        CP16(s + POFF_B + dT2, pB + 128 * K_ + kblk);
        CP16(s + POFF_B + dT3, pB + 192 * K_ + kblk);
    };

    float acc[4][8][4];
    #pragma unroll
    for (int i = 0; i < 4; i++)
        #pragma unroll
        for (int j = 0; j < 8; j++)
            #pragma unroll
            for (int r = 0; r < 4; r++) acc[i][j][r] = 0.f;

    uint32_t aoff[4], boff[4];
    #pragma unroll
    for (int ti = 0; ti < 4; ti++)
        aoff[ti] = GSWZ(wm + ti * 16 + (lane & 15), (lane >> 4));
    #pragma unroll
    for (int pj = 0; pj < 4; pj++)
        boff[pj] = GSWZ(wn + pj * 16 + (lane & 7) + ((lane >> 4) & 1) * 8,
                        ((lane >> 3) & 1));

    auto compute = [&](int stg) {
        uint32_t s = sbase + stg * PSTAGEB;
        #pragma unroll
        for (int ks = 0; ks < 2; ks++) {
            const uint32_t kx = ks ? 0x20u : 0u;
            uint32_t ah[4][4], al[4][4];
            #pragma unroll
            for (int ti = 0; ti < 4; ti++) {
                uint32_t ad = s + (aoff[ti] ^ kx);
                LDSM_X4(ah[ti][0], ah[ti][1], ah[ti][2], ah[ti][3], ad + POFF_AH);
                LDSM_X4(al[ti][0], al[ti][1], al[ti][2], al[ti][3], ad + POFF_AL);
            }
            #pragma unroll
            for (int pj = 0; pj < 4; pj++) {
                uint32_t bd = s + (boff[pj] ^ kx);
                uint32_t h0, h1, h2, h3;
                LDSM_X4(h0, h1, h2, h3, bd + POFF_B);
                uint32_t bh0[2] = {h0, h1}, bh1[2] = {h2, h3};
                #pragma unroll
                for (int ti = 0; ti < 4; ti++) {
                    mma16816h(acc[ti][2 * pj],     ah[ti], bh0);
                    mma16816h(acc[ti][2 * pj + 1], ah[ti], bh1);
                }
                #pragma unroll
                for (int ti = 0; ti < 4; ti++) {
                    mma16816h(acc[ti][2 * pj],     al[ti], bh0);
                    mma16816h(acc[ti][2 * pj + 1], al[ti], bh1);
                }
            }
        }
    };

    const int NK = K_ / GBK;
    produce(0, 0); CP_COMMIT();
    produce(1, GBK); CP_COMMIT();
    produce(2, 2 * GBK); CP_COMMIT();

    for (int it = 0; it < NK; ++it) {
        CP_WAIT(2);
        __syncthreads();
        compute(it & (PNSTAGE - 1));
        if (it + 3 < NK) produce((it + 3) & (PNSTAGE - 1), (it + 3) * GBK);
        CP_COMMIT();
    }

    const int er = lane >> 2;
    const int ec = (lane & 3) * 2;
    #pragma unroll
    for (int tj = 0; tj < 8; tj++) {
        int col = n0 + wn + tj * 8 + ec;
        float bx = bias[col], by = bias[col + 1];
        #pragma unroll
        for (int ti = 0; ti < 4; ti++) {
            int row = m0 + wm + ti * 16 + er;
            float2 v0 = { acc[ti][tj][0] + bx, acc[ti][tj][1] + by };
            float2 v1 = { acc[ti][tj][2] + bx, acc[ti][tj][3] + by };
            *(float2*)(C + (size_t)row * D_ + col) = v0;
            *(float2*)(C + (size_t)(row + 8) * D_ + col) = v1;
        }
    }
}

// ---------------------------------------------------------------------------
// HMMA causal flash attention, bf16x3, FA2-style register softmax.
// BQ=128 (8 warps x 16 rows), BKV=64, HD=128. Double-buffered KV via cp.async.
// Output written as fp16 hi/lo (feeds fp16x2 proj GEMM).
// ---------------------------------------------------------------------------
#define FROWB 272                      // 128 bf16 + 8 pad = 136 elems
#define FQBYTES (128 * FROWB)          // per Q array
#define FKBYTES (64 * FROWB)           // per K/V array
#define FSTGB (4 * FKBYTES)            // kh,kl,vh,vl
#define FLASH_DYN_SMEM (2 * FQBYTES + 2 * FSTGB)   // 208896 B

__global__ __launch_bounds__(256, 1) void flash_mma(
    const __nv_bfloat16* __restrict__ qh_, const __nv_bfloat16* __restrict__ ql_,
    const __nv_bfloat16* __restrict__ kh_, const __nv_bfloat16* __restrict__ kl_,
    const __nv_bfloat16* __restrict__ vh_, const __nv_bfloat16* __restrict__ vl_,
    __half* __restrict__ oh_, __half* __restrict__ ol_)
{
    extern __shared__ __align__(128) char fsm[];
    const uint32_t sb = smem_u32(fsm);
    const int tid = threadIdx.x, wq = tid >> 5, lane = tid & 31;
    const int bi = (int)gridDim.x - 1 - (int)blockIdx.x;   // big blocks first
    const int hh = blockIdx.y, b = blockIdx.z;
    const int q0 = bi * 128;
    const size_t bh = ((size_t)b * H_ + hh) * S_;
    const uint32_t QH = sb, QL = sb + FQBYTES;
    const uint32_t KV0 = sb + 2 * FQBYTES;

    // Q tile load (both hi/lo)
    #pragma unroll
    for (int i = 0; i < 8; i++) {
        int id = tid + i * 256;
        int r = id >> 4, c = id & 15;
        size_t src = (bh + q0 + r) * HD_ + c * 8;
        CP16(QH + r * FROWB + c * 16, qh_ + src);
        CP16(QL + r * FROWB + c * 16, ql_ + src);
    }
    auto produce = [&](int stg, int kt) {
        uint32_t s = KV0 + stg * FSTGB;
        int k0 = kt * 64;
        #pragma unroll
        for (int i = 0; i < 4; i++) {
            int id = tid + i * 256;
            int r = id >> 4, c = id & 15;
            size_t src = (bh + k0 + r) * HD_ + c * 8;
            uint32_t d = r * FROWB + c * 16;
            CP16(s + d, kh_ + src);
            CP16(s + FKBYTES + d, kl_ + src);
            CP16(s + 2 * FKBYTES + d, vh_ + src);
            CP16(s + 3 * FKBYTES + d, vl_ + src);
        }
    };

    float o[16][4];
    #pragma unroll
    for (int j = 0; j < 16; j++)
        #pragma unroll
        for (int r = 0; r < 4; r++) o[j][r] = 0.f;
    float m0 = -1e30f, m1 = -1e30f, l0 = 0.f, l1 = 0.f;

    const int er = lane >> 2, ec2 = (lane & 3) * 2;
    const uint32_t a_row = wq * 16 + (lane & 15);
    const uint32_t a_kb  = (lane >> 4) * 16;
    const uint32_t b_row = (lane & 7) + ((lane >> 4) & 1) * 8;
    const uint32_t b_kb  = ((lane >> 3) & 1) * 16;
    const uint32_t v_row = (lane & 7) + ((lane >> 3) & 1) * 8;
    const uint32_t v_cb  = ((lane >> 4) & 1) * 16;

    const int nkt = 2 * bi + 2;
    produce(0, 0);
    CP_COMMIT();

    for (int kt = 0; kt < nkt; kt++) {
        if (kt + 1 < nkt) { produce((kt + 1) & 1, kt + 1); CP_COMMIT(); CP_WAIT(1); }
        else CP_WAIT(0);
        __syncthreads();
        const uint32_t kb = KV0 + (kt & 1) * FSTGB;

        // ---- phase 1: S = Q K^T (bf16x3) ----
        float s[8][4];
        #pragma unroll
        for (int j = 0; j < 8; j++)
            #pragma unroll
            for (int r = 0; r < 4; r++) s[j][r] = 0.f;

        #pragma unroll
        for (int ks = 0; ks < 8; ks++) {
            uint32_t ah[4], al[4];
            uint32_t qa = QH + a_row * FROWB + ks * 32 + a_kb;
            LDSM_X4(ah[0], ah[1], ah[2], ah[3], qa);
            LDSM_X4(al[0], al[1], al[2], al[3], qa + FQBYTES);
            #pragma unroll
            for (int bj = 0; bj < 4; bj++) {
                uint32_t ka = kb + (bj * 16 + b_row) * FROWB + ks * 32 + b_kb;
                uint32_t h0, h1, h2, h3, g0, g1, g2, g3;
                LDSM_X4(h0, h1, h2, h3, ka);
                LDSM_X4(g0, g1, g2, g3, ka + FKBYTES);
                uint32_t bhi0[2] = {h0, h1}, bhi1[2] = {h2, h3};
                uint32_t blo0[2] = {g0, g1}, blo1[2] = {g2, g3};
                mma16816(s[2 * bj], ah, bhi0);
                mma16816(s[2 * bj], ah, blo0);
                mma16816(s[2 * bj], al, bhi0);
                mma16816(s[2 * bj + 1], ah, bhi1);
                mma16816(s[2 * bj + 1], ah, blo1);
                mma16816(s[2 * bj + 1], al, bhi1);
            }
        }

        // ---- causal mask (only last two tiles) ----
        if (kt >= 2 * bi) {
            int row0 = q0 + wq * 16 + er, row1 = row0 + 8;
            int colb = kt * 64 + ec2;
            #pragma unroll
            for (int j = 0; j < 8; j++) {
                int c0 = colb + j * 8, c1 = c0 + 1;
                if (c0 > row0) s[j][0] = -1e30f;
                if (c1 > row0) s[j][1] = -1e30f;
                if (c0 > row1) s[j][2] = -1e30f;
                if (c1 > row1) s[j][3] = -1e30f;
            }
        }

        // ---- online softmax (rows er / er+8) ----
        float mx0 = -1e30f, mx1 = -1e30f;
        #pragma unroll
        for (int j = 0; j < 8; j++) {
            mx0 = fmaxf(mx0, fmaxf(s[j][0], s[j][1]));
            mx1 = fmaxf(mx1, fmaxf(s[j][2], s[j][3]));
        }
        mx0 = fmaxf(mx0, __shfl_xor_sync(0xffffffffu, mx0, 1));
        mx0 = fmaxf(mx0, __shfl_xor_sync(0xffffffffu, mx0, 2));
        mx1 = fmaxf(mx1, __shfl_xor_sync(0xffffffffu, mx1, 1));
        mx1 = fmaxf(mx1, __shfl_xor_sync(0xffffffffu, mx1, 2));
        float mn0 = fmaxf(m0, mx0), mn1 = fmaxf(m1, mx1);
        float al0 = __expf(m0 - mn0), al1 = __expf(m1 - mn1);
        m0 = mn0; m1 = mn1;
        float sm0 = 0.f, sm1 = 0.f;
        #pragma unroll
        for (int j = 0; j < 8; j++) {
            s[j][0] = __expf(s[j][0] - m0); sm0 += s[j][0];
            s[j][1] = __expf(s[j][1] - m0); sm0 += s[j][1];
            s[j][2] = __expf(s[j][2] - m1); sm1 += s[j][2];
            s[j][3] = __expf(s[j][3] - m1); sm1 += s[j][3];
        }
        sm0 += __shfl_xor_sync(0xffffffffu, sm0, 1);
        sm0 += __shfl_xor_sync(0xffffffffu, sm0, 2);
        sm1 += __shfl_xor_sync(0xffffffffu, sm1, 1);
        sm1 += __shfl_xor_sync(0xffffffffu, sm1, 2);
        l0 = l0 * al0 + sm0;
        l1 = l1 * al1 + sm1;
        #pragma unroll
        for (int j = 0; j < 16; j++) {
            o[j][0] *= al0; o[j][1] *= al0;
            o[j][2] *= al1; o[j][3] *= al1;
        }

        // ---- phase 2: O += P V (bf16x3; V via ldmatrix.trans) ----
        const uint32_t vbase = kb + 2 * FKBYTES;
        #pragma unroll
        for (int ki = 0; ki < 4; ki++) {
            uint32_t ph[4], pl[4];
            packhl(s[2 * ki][0],     s[2 * ki][1],     ph[0], pl[0]);
            packhl(s[2 * ki][2],     s[2 * ki][3],     ph[1], pl[1]);
            packhl(s[2 * ki + 1][0], s[2 * ki + 1][1], ph[2], pl[2]);
            packhl(s[2 * ki + 1][2], s[2 * ki + 1][3], ph[3], pl[3]);
            #pragma unroll
            for (int nj = 0; nj < 8; nj++) {
                uint32_t va = vbase + (ki * 16 + v_row) * FROWB + nj * 32 + v_cb;
                uint32_t h0, h1, h2, h3, g0, g1, g2, g3;
                LDSM_X4T(h0, h1, h2, h3, va);
                LDSM_X4T(g0, g1, g2, g3, va + FKBYTES);
                uint32_t vh0[2] = {h0, h1}, vh1[2] = {h2, h3};
                uint32_t vl0[2] = {g0, g1}, vl1[2] = {g2, g3};
                mma16816(o[2 * nj], ph, vh0);
                mma16816(o[2 * nj], ph, vl0);
                mma16816(o[2 * nj], pl, vh0);
                mma16816(o[2 * nj + 1], ph, vh1);
                mma16816(o[2 * nj + 1], ph, vl1);
                mma16816(o[2 * nj + 1], pl, vh1);
            }
        }
        __syncthreads();   // protect KV buffer before next produce overwrites
    }

    // ---- epilogue: normalize + fp16 hi/lo write ----
    float il0 = 1.f / l0, il1 = 1.f / l1;
    int row0 = q0 + wq * 16 + er;
    #pragma unroll
    for (int j = 0; j < 16; j++) {
        int col = hh * 128 + j * 8 + ec2;
        uint32_t hp, lp;
        packhl_h(o[j][0] * il0, o[j][1] * il0, hp, lp);
        size_t off0 = ((size_t)b * S_ + row0) * D_ + col;
        *(uint32_t*)(oh_ + off0) = hp;
        *(uint32_t*)(ol_ + off0) = lp;
        packhl_h(o[j][2] * il1, o[j][3] * il1, hp, lp);
        size_t off1 = ((size_t)b * S_ + row0 + 8) * D_ + col;
        *(uint32_t*)(oh_ + off1) = hp;
        *(uint32_t*)(ol_ + off1) = lp;
    }
}

// ---------------------------------------------------------------------------
// Launch
// ---------------------------------------------------------------------------
extern "C" void kernel_launch(void* const* d_in, const int* in_sizes, int n_in,
                              void* d_out, int out_size)
{
    (void)in_sizes; (void)n_in; (void)out_size;
    const float* x    = (const float*)d_in[0];
    const float* Wqkv = (const float*)d_in[1];
    const float* bqkv = (const float*)d_in[2];
    const float* Wo   = (const float*)d_in[3];
    const float* bo   = (const float*)d_in[4];
    float* out = (float*)d_out;

    __nv_bfloat16 *qhi, *qlo, *khi, *klo, *vhi, *vlo;
    __half *xhi, *xlo, *w1h, *w2h, *ahi, *alo;
    cudaGetSymbolAddress((void**)&xhi, g_xhi);   cudaGetSymbolAddress((void**)&xlo, g_xlo);
    cudaGetSymbolAddress((void**)&w1h, g_w1h);   cudaGetSymbolAddress((void**)&w2h, g_w2h);
    cudaGetSymbolAddress((void**)&qhi, g_qhi);   cudaGetSymbolAddress((void**)&qlo, g_qlo);
    cudaGetSymbolAddress((void**)&khi, g_khi);   cudaGetSymbolAddress((void**)&klo, g_klo);
    cudaGetSymbolAddress((void**)&vhi, g_vhi);   cudaGetSymbolAddress((void**)&vlo, g_vlo);
    cudaGetSymbolAddress((void**)&ahi, g_ahi);   cudaGetSymbolAddress((void**)&alo, g_alo);

    cudaFuncSetAttribute(gemm_qkv,
                         cudaFuncAttributeMaxDynamicSharedMemorySize, QKV_DYN_SMEM);
    cudaFuncSetAttribute(gemm_proj,
                         cudaFuncAttributeMaxDynamicSharedMemorySize, PROJ_DYN_SMEM);
    cudaFuncSetAttribute(flash_mma,
                         cudaFuncAttributeMaxDynamicSharedMemorySize, FLASH_DYN_SMEM);

    // 1) split x into fp16 hi/lo
    {
        int n4 = (M_ * D_) / 4;
        split_f32_h<<<(n4 + 255) / 256, 256>>>(x, xhi, xlo, n4);
    }
    // 2) transpose weights to [N,K] fp16
    transpose_h<<<dim3((3 * D_) / 32, D_ / 32), dim3(32, 8)>>>(Wqkv, w1h, D_, 3 * D_);
    transpose_h<<<dim3(D_ / 32, D_ / 32), dim3(32, 8)>>>(Wo, w2h, D_, D_);

    // 3) QKV GEMM (fp16x2, BN=192 -> 1024 CTAs)
    gemm_qkv<<<dim3((3 * D_) / 192, M_ / 128), 256, QKV_DYN_SMEM>>>(
        xhi, xlo, w1h, bqkv,
        qhi, qlo, khi, klo, vhi, vlo);

    // 4) HMMA flash attention (bf16x3 core, outputs fp16 hi/lo)
    flash_mma<<<dim3(S_ / 128, H_, B_), 256, FLASH_DYN_SMEM>>>(
        qhi, qlo, khi, klo, vhi, vlo, ahi, alo);

    // 5) out = attn @ Wo + bo  (fp16x2)
    gemm_proj<<<dim3(D_ / 256, M_ / 128), 256, PROJ_DYN_SMEM>>>(
        ahi, alo, w2h, bo, out);
}

// round 10
// speedup vs baseline: 1.5575x; 1.1449x over previous
#include <cuda_runtime.h>
#include <cuda_bf16.h>
#include <cuda_fp16.h>
#include <cstdint>
#include <cstddef>

// ---------------------------------------------------------------------------
// Problem constants
// ---------------------------------------------------------------------------
#define B_  2
#define S_  2048
#define D_  2048
#define H_  16
#define HD_ 128
#define M_  (B_*S_)            // 4096 rows
#define K_  2048               // inner dim of BOTH gemms (compile-time)
#define SCALE_ 0.08838834764831845f

// ---------------------------------------------------------------------------
// Scratch (__device__ globals; no allocation allowed)
// ---------------------------------------------------------------------------
__device__ __half g_xhi[(size_t)M_ * D_];               // x fp16 hi/lo
__device__ __half g_xlo[(size_t)M_ * D_];
__device__ __half g_w1h[(size_t)3 * D_ * D_];           // Wqkv^T [6144,2048] fp16
__device__ __half g_w2h[(size_t)D_ * D_];               // Wo^T [2048,2048] fp16
// q in fp16 hi/lo (pre-scaled by 1/sqrt(HD)); k/v single fp16.  [B,H,S,HD]
__device__ __half g_qhi[(size_t)M_ * D_];
__device__ __half g_qlo[(size_t)M_ * D_];
__device__ __half g_kh[(size_t)M_ * D_];
__device__ __half g_vh[(size_t)M_ * D_];
// attention output [B,S,D] fp16 hi/lo (feeds fp16x2 proj)
__device__ __half g_ahi[(size_t)M_ * D_];
__device__ __half g_alo[(size_t)M_ * D_];

// ---------------------------------------------------------------------------
// Portable PTX helpers (virtual arch compute_103: no tcgen05)
// ---------------------------------------------------------------------------
__device__ __forceinline__ uint32_t smem_u32(const void* p) {
    uint32_t a;
    asm("{ .reg .u64 t; cvta.to.shared.u64 t, %1; cvt.u32.u64 %0, t; }"
        : "=r"(a) : "l"(p));
    return a;
}

#define CP16(dst_u32, src_ptr) \
    asm volatile("cp.async.cg.shared.global [%0], [%1], 16;" \
                 :: "r"(dst_u32), "l"(src_ptr) : "memory")
#define CP_COMMIT() asm volatile("cp.async.commit_group;" ::: "memory")
#define CP_WAIT(n)  asm volatile("cp.async.wait_group %0;" :: "n"(n) : "memory")

#define LDSM_X4(r0, r1, r2, r3, addr) \
    asm volatile("ldmatrix.sync.aligned.m8n8.x4.shared.b16 {%0,%1,%2,%3}, [%4];" \
                 : "=r"(r0), "=r"(r1), "=r"(r2), "=r"(r3) : "r"(addr))
#define LDSM_X4T(r0, r1, r2, r3, addr) \
    asm volatile("ldmatrix.sync.aligned.m8n8.x4.trans.shared.b16 {%0,%1,%2,%3}, [%4];" \
                 : "=r"(r0), "=r"(r1), "=r"(r2), "=r"(r3) : "r"(addr))

__device__ __forceinline__ void mma16816h(float* d, const uint32_t* a,
                                          const uint32_t* b) {
    asm volatile(
        "mma.sync.aligned.m16n8k16.row.col.f32.f16.f16.f32 "
        "{%0,%1,%2,%3}, {%4,%5,%6,%7}, {%8,%9}, {%0,%1,%2,%3};"
        : "+f"(d[0]), "+f"(d[1]), "+f"(d[2]), "+f"(d[3])
        : "r"(a[0]), "r"(a[1]), "r"(a[2]), "r"(a[3]), "r"(b[0]), "r"(b[1]));
}

// pack two floats -> fp16x2 hi + fp16x2 lo(residual)
__device__ __forceinline__ void packhl_h(float x, float y, uint32_t& hp, uint32_t& lp) {
    __half2 hv = __floats2half2_rn(x, y);
    float rx = x - __half2float(__low2half(hv));
    float ry = y - __half2float(__high2half(hv));
    __half2 lv = __floats2half2_rn(rx, ry);
    hp = *reinterpret_cast<uint32_t*>(&hv);
    lp = *reinterpret_cast<uint32_t*>(&lv);
}

// ---------------------------------------------------------------------------
// split / transpose pre-passes
// ---------------------------------------------------------------------------
__global__ void split_f32_h(const float* __restrict__ in,
                            __half* __restrict__ hi,
                            __half* __restrict__ lo, int n4) {
    int i = blockIdx.x * blockDim.x + threadIdx.x;
    if (i >= n4) return;
    float4 v = *(const float4*)(in + (size_t)i * 4);
    uint32_t h0, h1, l0, l1;
    packhl_h(v.x, v.y, h0, l0);
    packhl_h(v.z, v.w, h1, l1);
    uint32_t* hp = (uint32_t*)(hi + (size_t)i * 4);
    uint32_t* lp = (uint32_t*)(lo + (size_t)i * 4);
    hp[0] = h0; hp[1] = h1;
    lp[0] = l0; lp[1] = l1;
}

__global__ void transpose_h(const float* __restrict__ W,
                            __half* __restrict__ Th, int K, int N) {
    __shared__ float t[32][33];
    int n0 = blockIdx.x * 32, k0 = blockIdx.y * 32;
    int tx = threadIdx.x, ty = threadIdx.y;      // (32,8)
    #pragma unroll
    for (int j = 0; j < 32; j += 8)
        t[ty + j][tx] = W[(size_t)(k0 + ty + j) * N + n0 + tx];
    __syncthreads();
    #pragma unroll
    for (int j = 0; j < 32; j += 8)
        Th[(size_t)(n0 + ty + j) * K + k0 + tx] = __float2half(t[tx][ty + j]);
}

// ---------------------------------------------------------------------------
// shared swizzle: 64B rows, chunk ^= (row>>1)&3
// ---------------------------------------------------------------------------
#define GBK 32
#define GSWZ(r, c) ((uint32_t)(r) * 64u + ((((uint32_t)(c) ^ (((uint32_t)(r) >> 1) & 3u))) << 4))

// ---------------------------------------------------------------------------
// QKV GEMM (fp16x2):  BM=128, BN=192, BK=32, 8 warps (2x4), warp 64x48,
// 4-stage cp.async.  A = x fp16 hi/lo, B = Wqkv^T single fp16.
// Epilogue: bias+scale; q -> fp16 hi/lo (scaled), k/v -> single fp16.
// Grid 32x32 = 1024 CTAs -> 6.92 waves (98.8% wave util).
// ---------------------------------------------------------------------------
#define QOFF_AH 0
#define QOFF_AL 8192
#define QOFF_B  16384                 // B: 192 rows * 64B = 12288
#define QSTAGEB 28672
#define QNSTAGE 4
#define QKV_DYN_SMEM (QNSTAGE * QSTAGEB)   // 114688

__global__ __launch_bounds__(256, 1) void gemm_qkv(
    const __half* __restrict__ Ah, const __half* __restrict__ Al,
    const __half* __restrict__ Bm,
    const float* __restrict__ bias,
    __half* __restrict__ qh, __half* __restrict__ ql,
    __half* __restrict__ kh, __half* __restrict__ vh)
{
    extern __shared__ __align__(128) char sm[];
    const uint32_t sbase = smem_u32(sm);

    const int tid = threadIdx.x;
    const int wid = tid >> 5;
    const int lane = tid & 31;
    const int m0 = blockIdx.y * 128;
    const int n0 = blockIdx.x * 192;
    const int wm = (wid >> 2) * 64;      // 0 / 64
    const int wn = (wid & 3) * 48;       // 0/48/96/144

    const int tr = tid >> 2;             // 0..63
    const int pc = tid & 3;              // chunk 0..3
    const __half* pAh = Ah + (m0 + tr) * K_ + pc * 8;
    const __half* pAl = Al + (m0 + tr) * K_ + pc * 8;
    const __half* pB  = Bm + (n0 + tr) * K_ + pc * 8;
    const uint32_t dT0 = GSWZ(tr, pc);
    const uint32_t dT1 = GSWZ(tr + 64, pc);
    const uint32_t dT2 = GSWZ(tr + 128, pc);

    auto produce = [&](int stg, int kblk) {
        uint32_t s = sbase + stg * QSTAGEB;
        CP16(s + QOFF_AH + dT0, pAh + kblk);
        CP16(s + QOFF_AL + dT0, pAl + kblk);
        CP16(s + QOFF_AH + dT1, pAh + 64 * K_ + kblk);
        CP16(s + QOFF_AL + dT1, pAl + 64 * K_ + kblk);
        CP16(s + QOFF_B + dT0, pB + kblk);
        CP16(s + QOFF_B + dT1, pB + 64 * K_ + kblk);
        CP16(s + QOFF_B + dT2, pB + 128 * K_ + kblk);
    };

    float acc[4][6][4];
    #pragma unroll
    for (int i = 0; i < 4; i++)
        #pragma unroll
        for (int j = 0; j < 6; j++)
            #pragma unroll
            for (int r = 0; r < 4; r++) acc[i][j][r] = 0.f;

    uint32_t aoff[4], boff[3];
    #pragma unroll
    for (int ti = 0; ti < 4; ti++)
        aoff[ti] = GSWZ(wm + ti * 16 + (lane & 15), (lane >> 4));
    #pragma unroll
    for (int pj = 0; pj < 3; pj++)
        boff[pj] = GSWZ(wn + pj * 16 + (lane & 7) + ((lane >> 4) & 1) * 8,
                        ((lane >> 3) & 1));

    auto compute = [&](int stg) {
        uint32_t s = sbase + stg * QSTAGEB;
        #pragma unroll
        for (int ks = 0; ks < 2; ks++) {
            const uint32_t kx = ks ? 0x20u : 0u;
            uint32_t ah[4][4], al[4][4];
            #pragma unroll
            for (int ti = 0; ti < 4; ti++) {
                uint32_t ad = s + (aoff[ti] ^ kx);
                LDSM_X4(ah[ti][0], ah[ti][1], ah[ti][2], ah[ti][3], ad + QOFF_AH);
                LDSM_X4(al[ti][0], al[ti][1], al[ti][2], al[ti][3], ad + QOFF_AL);
            }
            #pragma unroll
            for (int pj = 0; pj < 3; pj++) {
                uint32_t bd = s + (boff[pj] ^ kx);
                uint32_t h0, h1, h2, h3;
                LDSM_X4(h0, h1, h2, h3, bd + QOFF_B);
                uint32_t bh0[2] = {h0, h1}, bh1[2] = {h2, h3};
                #pragma unroll
                for (int ti = 0; ti < 4; ti++) {
                    mma16816h(acc[ti][2 * pj],     ah[ti], bh0);
                    mma16816h(acc[ti][2 * pj + 1], ah[ti], bh1);
                }
                #pragma unroll
                for (int ti = 0; ti < 4; ti++) {
                    mma16816h(acc[ti][2 * pj],     al[ti], bh0);
                    mma16816h(acc[ti][2 * pj + 1], al[ti], bh1);
                }
            }
        }
    };

    const int NK = K_ / GBK;             // 64
    produce(0, 0); CP_COMMIT();
    produce(1, GBK); CP_COMMIT();
    produce(2, 2 * GBK); CP_COMMIT();

    for (int it = 0; it < NK; ++it) {
        CP_WAIT(2);
        __syncthreads();
        compute(it & (QNSTAGE - 1));
        if (it + 3 < NK) produce((it + 3) & (QNSTAGE - 1), (it + 3) * GBK);
        CP_COMMIT();
    }

    // ---- epilogue: q -> fp16 hi/lo (scaled); k/v -> single fp16 ----
    const int er = lane >> 2;
    const int ec = (lane & 3) * 2;
    #pragma unroll
    for (int tj = 0; tj < 6; tj++) {
        int col = n0 + wn + tj * 8 + ec;
        int hh = col / 384, rem = col % 384;
        int which = rem >> 7, hd = rem & 127;
        float bx = bias[col], by = bias[col + 1];
        #pragma unroll
        for (int ti = 0; ti < 4; ti++) {
            #pragma unroll
            for (int rr = 0; rr < 2; rr++) {
                int row = m0 + wm + ti * 16 + er + rr * 8;
                int bb = row >> 11, ss = row & 2047;
                size_t off = (((size_t)(bb * H_ + hh)) * S_ + ss) * HD_ + hd;
                float vx = acc[ti][tj][rr * 2] + bx;
                float vy = acc[ti][tj][rr * 2 + 1] + by;
                if (which == 0) {
                    uint32_t hp, lp;
                    packhl_h(vx * SCALE_, vy * SCALE_, hp, lp);
                    *(uint32_t*)(qh + off) = hp;
                    *(uint32_t*)(ql + off) = lp;
                } else {
                    __half2 hv = __floats2half2_rn(vx, vy);
                    __half* dst = (which == 1) ? kh : vh;
                    *(__half2*)(dst + off) = hv;
                }
            }
        }
    }
}

// ---------------------------------------------------------------------------
// Proj GEMM (fp16x2):  C = A @ Bt^T + bias.  A fp16 hi/lo, B single fp16.
// BM=128, BN=256, BK=32, 8 warps (2x4), warp 64x64, 4-stage cp.async.
// ---------------------------------------------------------------------------
#define POFF_AH 0
#define POFF_AL 8192
#define POFF_B  16384                 // B: 256 rows * 64B = 16384
#define PSTAGEB 32768
#define PNSTAGE 4
#define PROJ_DYN_SMEM (PNSTAGE * PSTAGEB)   // 131072

__global__ __launch_bounds__(256, 1) void gemm_proj(
    const __half* __restrict__ Ah, const __half* __restrict__ Al,
    const __half* __restrict__ Bm,
    const float* __restrict__ bias, float* __restrict__ C)
{
    extern __shared__ __align__(128) char sm[];
    const uint32_t sbase = smem_u32(sm);

    const int tid = threadIdx.x;
    const int wid = tid >> 5;
    const int lane = tid & 31;
    const int m0 = blockIdx.y * 128;
    const int n0 = blockIdx.x * 256;
    const int wm = (wid >> 2) * 64;
    const int wn = (wid & 3) * 64;

    const int tr = tid >> 2;
    const int pc = tid & 3;
    const __half* pAh = Ah + (m0 + tr) * K_ + pc * 8;
    const __half* pAl = Al + (m0 + tr) * K_ + pc * 8;
    const __half* pB  = Bm + (n0 + tr) * K_ + pc * 8;
    const uint32_t dT0 = GSWZ(tr, pc);
    const uint32_t dT1 = GSWZ(tr + 64, pc);
    const uint32_t dT2 = GSWZ(tr + 128, pc);
    const uint32_t dT3 = GSWZ(tr + 192, pc);

    auto produce = [&](int stg, int kblk) {
        uint32_t s = sbase + stg * PSTAGEB;
        CP16(s + POFF_AH + dT0, pAh + kblk);
        CP16(s + POFF_AL + dT0, pAl + kblk);
        CP16(s + POFF_AH + dT1, pAh + 64 * K_ + kblk);
        CP16(s + POFF_AL + dT1, pAl + 64 * K_ + kblk);
        CP16(s + POFF_B + dT0, pB + kblk);
        CP16(s + POFF_B + dT1, pB + 64 * K_ + kblk);
        CP16(s + POFF_B + dT2, pB + 128 * K_ + kblk);
        CP16(s + POFF_B + dT3, pB + 192 * K_ + kblk);
    };

    float acc[4][8][4];
    #pragma unroll
    for (int i = 0; i < 4; i++)
        #pragma unroll
        for (int j = 0; j < 8; j++)
            #pragma unroll
            for (int r = 0; r < 4; r++) acc[i][j][r] = 0.f;

    uint32_t aoff[4], boff[4];
    #pragma unroll
    for (int ti = 0; ti < 4; ti++)
        aoff[ti] = GSWZ(wm + ti * 16 + (lane & 15), (lane >> 4));
    #pragma unroll
    for (int pj = 0; pj < 4; pj++)
        boff[pj] = GSWZ(wn + pj * 16 + (lane & 7) + ((lane >> 4) & 1) * 8,
                        ((lane >> 3) & 1));

    auto compute = [&](int stg) {
        uint32_t s = sbase + stg * PSTAGEB;
        #pragma unroll
        for (int ks = 0; ks < 2; ks++) {
            const uint32_t kx = ks ? 0x20u : 0u;
            uint32_t ah[4][4], al[4][4];
            #pragma unroll
            for (int ti = 0; ti < 4; ti++) {
                uint32_t ad = s + (aoff[ti] ^ kx);
                LDSM_X4(ah[ti][0], ah[ti][1], ah[ti][2], ah[ti][3], ad + POFF_AH);
                LDSM_X4(al[ti][0], al[ti][1], al[ti][2], al[ti][3], ad + POFF_AL);
            }
            #pragma unroll
            for (int pj = 0; pj < 4; pj++) {
                uint32_t bd = s + (boff[pj] ^ kx);
                uint32_t h0, h1, h2, h3;
                LDSM_X4(h0, h1, h2, h3, bd + POFF_B);
                uint32_t bh0[2] = {h0, h1}, bh1[2] = {h2, h3};
                #pragma unroll
                for (int ti = 0; ti < 4; ti++) {
                    mma16816h(acc[ti][2 * pj],     ah[ti], bh0);
                    mma16816h(acc[ti][2 * pj + 1], ah[ti], bh1);
                }
                #pragma unroll
                for (int ti = 0; ti < 4; ti++) {
                    mma16816h(acc[ti][2 * pj],     al[ti], bh0);
                    mma16816h(acc[ti][2 * pj + 1], al[ti], bh1);
                }
            }
        }
    };

    const int NK = K_ / GBK;
    produce(0, 0); CP_COMMIT();
    produce(1, GBK); CP_COMMIT();
    produce(2, 2 * GBK); CP_COMMIT();

    for (int it = 0; it < NK; ++it) {
        CP_WAIT(2);
        __syncthreads();
        compute(it & (PNSTAGE - 1));
        if (it + 3 < NK) produce((it + 3) & (PNSTAGE - 1), (it + 3) * GBK);
        CP_COMMIT();
    }

    const int er = lane >> 2;
    const int ec = (lane & 3) * 2;
    #pragma unroll
    for (int tj = 0; tj < 8; tj++) {
        int col = n0 + wn + tj * 8 + ec;
        float bx = bias[col], by = bias[col + 1];
        #pragma unroll
        for (int ti = 0; ti < 4; ti++) {
            int row = m0 + wm + ti * 16 + er;
            float2 v0 = { acc[ti][tj][0] + bx, acc[ti][tj][1] + by };
            float2 v1 = { acc[ti][tj][2] + bx, acc[ti][tj][3] + by };
            *(float2*)(C + (size_t)row * D_ + col) = v0;
            *(float2*)(C + (size_t)(row + 8) * D_ + col) = v1;
        }
    }
}

// ---------------------------------------------------------------------------
// HMMA causal flash attention (fp16x2): Q fp16 hi/lo x K single fp16 (2 terms),
// P fp16 hi/lo x V single fp16 (2 terms).  FA2 register softmax.
// BQ=128 (8 warps x 16 rows), BKV=64, HD=128. Double-buffered KV via cp.async.
// ---------------------------------------------------------------------------
#define FROWB 272                      // 128 fp16 + 8 pad = 136 elems
#define FQBYTES (128 * FROWB)          // per Q array
#define FKBYTES (64 * FROWB)           // per K/V array
#define FSTGB (2 * FKBYTES)            // k, v
#define FLASH_DYN_SMEM (2 * FQBYTES + 2 * FSTGB)   // 139264 B

__global__ __launch_bounds__(256, 1) void flash_mma(
    const __half* __restrict__ qh_, const __half* __restrict__ ql_,
    const __half* __restrict__ kh_, const __half* __restrict__ vh_,
    __half* __restrict__ oh_, __half* __restrict__ ol_)
{
    extern __shared__ __align__(128) char fsm[];
    const uint32_t sb = smem_u32(fsm);
    const int tid = threadIdx.x, wq = tid >> 5, lane = tid & 31;
    const int bi = (int)gridDim.x - 1 - (int)blockIdx.x;   // big blocks first
    const int hh = blockIdx.y, b = blockIdx.z;
    const int q0 = bi * 128;
    const size_t bh = ((size_t)b * H_ + hh) * S_;
    const uint32_t QH = sb, QL = sb + FQBYTES;
    const uint32_t KV0 = sb + 2 * FQBYTES;

    // Q tile load (both hi/lo)
    #pragma unroll
    for (int i = 0; i < 8; i++) {
        int id = tid + i * 256;
        int r = id >> 4, c = id & 15;
        size_t src = (bh + q0 + r) * HD_ + c * 8;
        CP16(QH + r * FROWB + c * 16, qh_ + src);
        CP16(QL + r * FROWB + c * 16, ql_ + src);
    }
    auto produce = [&](int stg, int kt) {
        uint32_t s = KV0 + stg * FSTGB;
        int k0 = kt * 64;
        #pragma unroll
        for (int i = 0; i < 4; i++) {
            int id = tid + i * 256;
            int r = id >> 4, c = id & 15;
            size_t src = (bh + k0 + r) * HD_ + c * 8;
            uint32_t d = r * FROWB + c * 16;
            CP16(s + d, kh_ + src);
            CP16(s + FKBYTES + d, vh_ + src);
        }
    };

    float o[16][4];
    #pragma unroll
    for (int j = 0; j < 16; j++)
        #pragma unroll
        for (int r = 0; r < 4; r++) o[j][r] = 0.f;
    float m0 = -1e30f, m1 = -1e30f, l0 = 0.f, l1 = 0.f;

    const int er = lane >> 2, ec2 = (lane & 3) * 2;
    const uint32_t a_row = wq * 16 + (lane & 15);
    const uint32_t a_kb  = (lane >> 4) * 16;
    const uint32_t b_row = (lane & 7) + ((lane >> 4) & 1) * 8;
    const uint32_t b_kb  = ((lane >> 3) & 1) * 16;
    const uint32_t v_row = (lane & 7) + ((lane >> 3) & 1) * 8;
    const uint32_t v_cb  = ((lane >> 4) & 1) * 16;

    const int nkt = 2 * bi + 2;
    produce(0, 0);
    CP_COMMIT();

    for (int kt = 0; kt < nkt; kt++) {
        if (kt + 1 < nkt) { produce((kt + 1) & 1, kt + 1); CP_COMMIT(); CP_WAIT(1); }
        else CP_WAIT(0);
        __syncthreads();
        const uint32_t kb = KV0 + (kt & 1) * FSTGB;

        // ---- phase 1: S = Q K^T (Q hi/lo x K single: 2 terms) ----
        float s[8][4];
        #pragma unroll
        for (int j = 0; j < 8; j++)
            #pragma unroll
            for (int r = 0; r < 4; r++) s[j][r] = 0.f;

        #pragma unroll
        for (int ks = 0; ks < 8; ks++) {
            uint32_t ah[4], al[4];
            uint32_t qa = QH + a_row * FROWB + ks * 32 + a_kb;
            LDSM_X4(ah[0], ah[1], ah[2], ah[3], qa);
            LDSM_X4(al[0], al[1], al[2], al[3], qa + FQBYTES);
            #pragma unroll
            for (int bj = 0; bj < 4; bj++) {
                uint32_t ka = kb + (bj * 16 + b_row) * FROWB + ks * 32 + b_kb;
                uint32_t h0, h1, h2, h3;
                LDSM_X4(h0, h1, h2, h3, ka);
                uint32_t bh0[2] = {h0, h1}, bh1[2] = {h2, h3};
                mma16816h(s[2 * bj],     ah, bh0);
                mma16816h(s[2 * bj + 1], ah, bh1);
                mma16816h(s[2 * bj],     al, bh0);
                mma16816h(s[2 * bj + 1], al, bh1);
            }
        }

        // ---- causal mask (only last two tiles) ----
        if (kt >= 2 * bi) {
            int row0 = q0 + wq * 16 + er, row1 = row0 + 8;
            int colb = kt * 64 + ec2;
            #pragma unroll
            for (int j = 0; j < 8; j++) {
                int c0 = colb + j * 8, c1 = c0 + 1;
                if (c0 > row0) s[j][0] = -1e30f;
                if (c1 > row0) s[j][1] = -1e30f;
                if (c0 > row1) s[j][2] = -1e30f;
                if (c1 > row1) s[j][3] = -1e30f;
            }
        }

        // ---- online softmax (rows er / er+8) ----
        float mx0 = -1e30f, mx1 = -1e30f;
        #pragma unroll
        for (int j = 0; j < 8; j++) {
            mx0 = fmaxf(mx0, fmaxf(s[j][0], s[j][1]));
            mx1 = fmaxf(mx1, fmaxf(s[j][2], s[j][3]));
        }
        mx0 = fmaxf(mx0, __shfl_xor_sync(0xffffffffu, mx0, 1));
        mx0 = fmaxf(mx0, __shfl_xor_sync(0xffffffffu, mx0, 2));
        mx1 = fmaxf(mx1, __shfl_xor_sync(0xffffffffu, mx1, 1));
        mx1 = fmaxf(mx1, __shfl_xor_sync(0xffffffffu, mx1, 2));
        float mn0 = fmaxf(m0, mx0), mn1 = fmaxf(m1, mx1);
        float al0 = __expf(m0 - mn0), al1 = __expf(m1 - mn1);
        m0 = mn0; m1 = mn1;
        float sm0 = 0.f, sm1 = 0.f;
        #pragma unroll
        for (int j = 0; j < 8; j++) {
            s[j][0] = __expf(s[j][0] - m0); sm0 += s[j][0];
            s[j][1] = __expf(s[j][1] - m0); sm0 += s[j][1];
            s[j][2] = __expf(s[j][2] - m1); sm1 += s[j][2];
            s[j][3] = __expf(s[j][3] - m1); sm1 += s[j][3];
        }
        sm0 += __shfl_xor_sync(0xffffffffu, sm0, 1);
        sm0 += __shfl_xor_sync(0xffffffffu, sm0, 2);
        sm1 += __shfl_xor_sync(0xffffffffu, sm1, 1);
        sm1 += __shfl_xor_sync(0xffffffffu, sm1, 2);
        l0 = l0 * al0 + sm0;
        l1 = l1 * al1 + sm1;
        #pragma unroll
        for (int j = 0; j < 16; j++) {
            o[j][0] *= al0; o[j][1] *= al0;
            o[j][2] *= al1; o[j][3] *= al1;
        }

        // ---- phase 2: O += P V (P hi/lo x V single: 2 terms; V trans) ----
        const uint32_t vbase = kb + FKBYTES;
        #pragma unroll
        for (int ki = 0; ki < 4; ki++) {
            uint32_t ph[4], pl[4];
            packhl_h(s[2 * ki][0],     s[2 * ki][1],     ph[0], pl[0]);
            packhl_h(s[2 * ki][2],     s[2 * ki][3],     ph[1], pl[1]);
            packhl_h(s[2 * ki + 1][0], s[2 * ki + 1][1], ph[2], pl[2]);
            packhl_h(s[2 * ki + 1][2], s[2 * ki + 1][3], ph[3], pl[3]);
            #pragma unroll
            for (int nj = 0; nj < 8; nj++) {
                uint32_t va = vbase + (ki * 16 + v_row) * FROWB + nj * 32 + v_cb;
                uint32_t h0, h1, h2, h3;
                LDSM_X4T(h0, h1, h2, h3, va);
                uint32_t vh0[2] = {h0, h1}, vh1[2] = {h2, h3};
                mma16816h(o[2 * nj],     ph, vh0);
                mma16816h(o[2 * nj + 1], ph, vh1);
                mma16816h(o[2 * nj],     pl, vh0);
                mma16816h(o[2 * nj + 1], pl, vh1);
            }
        }
        __syncthreads();   // protect KV buffer before next produce overwrites
    }

    // ---- epilogue: normalize + fp16 hi/lo write ----
    float il0 = 1.f / l0, il1 = 1.f / l1;
    int row0 = q0 + wq * 16 + er;
    #pragma unroll
    for (int j = 0; j < 16; j++) {
        int col = hh * 128 + j * 8 + ec2;
        uint32_t hp, lp;
        packhl_h(o[j][0] * il0, o[j][1] * il0, hp, lp);
        size_t off0 = ((size_t)b * S_ + row0) * D_ + col;
        *(uint32_t*)(oh_ + off0) = hp;
        *(uint32_t*)(ol_ + off0) = lp;
        packhl_h(o[j][2] * il1, o[j][3] * il1, hp, lp);
        size_t off1 = ((size_t)b * S_ + row0 + 8) * D_ + col;
        *(uint32_t*)(oh_ + off1) = hp;
        *(uint32_t*)(ol_ + off1) = lp;
    }
}

// ---------------------------------------------------------------------------
// Launch
// ---------------------------------------------------------------------------
extern "C" void kernel_launch(void* const* d_in, const int* in_sizes, int n_in,
                              void* d_out, int out_size)
{
    (void)in_sizes; (void)n_in; (void)out_size;
    const float* x    = (const float*)d_in[0];
    const float* Wqkv = (const float*)d_in[1];
    const float* bqkv = (const float*)d_in[2];
    const float* Wo   = (const float*)d_in[3];
    const float* bo   = (const float*)d_in[4];
    float* out = (float*)d_out;

    __half *xhi, *xlo, *w1h, *w2h;
    __half *qhi, *qlo, *khh, *vhh, *ahi, *alo;
    cudaGetSymbolAddress((void**)&xhi, g_xhi);   cudaGetSymbolAddress((void**)&xlo, g_xlo);
    cudaGetSymbolAddress((void**)&w1h, g_w1h);   cudaGetSymbolAddress((void**)&w2h, g_w2h);
    cudaGetSymbolAddress((void**)&qhi, g_qhi);   cudaGetSymbolAddress((void**)&qlo, g_qlo);
    cudaGetSymbolAddress((void**)&khh, g_kh);    cudaGetSymbolAddress((void**)&vhh, g_vh);
    cudaGetSymbolAddress((void**)&ahi, g_ahi);   cudaGetSymbolAddress((void**)&alo, g_alo);

    cudaFuncSetAttribute(gemm_qkv,
                         cudaFuncAttributeMaxDynamicSharedMemorySize, QKV_DYN_SMEM);
    cudaFuncSetAttribute(gemm_proj,
                         cudaFuncAttributeMaxDynamicSharedMemorySize, PROJ_DYN_SMEM);
    cudaFuncSetAttribute(flash_mma,
                         cudaFuncAttributeMaxDynamicSharedMemorySize, FLASH_DYN_SMEM);

    // 1) split x into fp16 hi/lo
    {
        int n4 = (M_ * D_) / 4;
        split_f32_h<<<(n4 + 255) / 256, 256>>>(x, xhi, xlo, n4);
    }
    // 2) transpose weights to [N,K] fp16
    transpose_h<<<dim3((3 * D_) / 32, D_ / 32), dim3(32, 8)>>>(Wqkv, w1h, D_, 3 * D_);
    transpose_h<<<dim3(D_ / 32, D_ / 32), dim3(32, 8)>>>(Wo, w2h, D_, D_);

    // 3) QKV GEMM (fp16x2, BN=192 -> 1024 CTAs)
    gemm_qkv<<<dim3((3 * D_) / 192, M_ / 128), 256, QKV_DYN_SMEM>>>(
        xhi, xlo, w1h, bqkv, qhi, qlo, khh, vhh);

    // 4) HMMA flash attention (fp16x2 core, outputs fp16 hi/lo)
    flash_mma<<<dim3(S_ / 128, H_, B_), 256, FLASH_DYN_SMEM>>>(
        qhi, qlo, khh, vhh, ahi, alo);

    // 5) out = attn @ Wo + bo  (fp16x2)
    gemm_proj<<<dim3(D_ / 256, M_ / 128), 256, PROJ_DYN_SMEM>>>(
        ahi, alo, w2h, bo, out);
}

// round 11
// speedup vs baseline: 2.0648x; 1.3257x over previous
#include <cuda_runtime.h>
#include <cuda_bf16.h>
#include <cuda_fp16.h>
#include <cstdint>
#include <cstddef>

// ---------------------------------------------------------------------------
// Problem constants
// ---------------------------------------------------------------------------
#define B_  2
#define S_  2048
#define D_  2048
#define H_  16
#define HD_ 128
#define M_  (B_*S_)            // 4096 rows
#define K_  2048               // inner dim of BOTH gemms (compile-time)
#define SCALE_ 0.08838834764831845f

// ---------------------------------------------------------------------------
// Scratch (__device__ globals; no allocation allowed)
// ---------------------------------------------------------------------------
__device__ __half g_xh[(size_t)M_ * D_];                // x single fp16
__device__ __half g_w1h[(size_t)3 * D_ * D_];           // Wqkv^T [6144,2048] fp16
__device__ __half g_w2h[(size_t)D_ * D_];               // Wo^T [2048,2048] fp16
// q in fp16 hi/lo (pre-scaled by 1/sqrt(HD)); k/v single fp16.  [B,H,S,HD]
__device__ __half g_qhi[(size_t)M_ * D_];
__device__ __half g_qlo[(size_t)M_ * D_];
__device__ __half g_kh[(size_t)M_ * D_];
__device__ __half g_vh[(size_t)M_ * D_];
// attention output [B,S,D] fp16 hi/lo (feeds fp16x2 proj)
__device__ __half g_ahi[(size_t)M_ * D_];
__device__ __half g_alo[(size_t)M_ * D_];

// ---------------------------------------------------------------------------
// Portable PTX helpers (virtual arch compute_103: no tcgen05)
// ---------------------------------------------------------------------------
__device__ __forceinline__ uint32_t smem_u32(const void* p) {
    uint32_t a;
    asm("{ .reg .u64 t; cvta.to.shared.u64 t, %1; cvt.u32.u64 %0, t; }"
        : "=r"(a) : "l"(p));
    return a;
}

#define CP16(dst_u32, src_ptr) \
    asm volatile("cp.async.cg.shared.global [%0], [%1], 16;" \
                 :: "r"(dst_u32), "l"(src_ptr) : "memory")
#define CP_COMMIT() asm volatile("cp.async.commit_group;" ::: "memory")
#define CP_WAIT(n)  asm volatile("cp.async.wait_group %0;" :: "n"(n) : "memory")

#define LDSM_X4(r0, r1, r2, r3, addr) \
    asm volatile("ldmatrix.sync.aligned.m8n8.x4.shared.b16 {%0,%1,%2,%3}, [%4];" \
                 : "=r"(r0), "=r"(r1), "=r"(r2), "=r"(r3) : "r"(addr))
#define LDSM_X4T(r0, r1, r2, r3, addr) \
    asm volatile("ldmatrix.sync.aligned.m8n8.x4.trans.shared.b16 {%0,%1,%2,%3}, [%4];" \
                 : "=r"(r0), "=r"(r1), "=r"(r2), "=r"(r3) : "r"(addr))

__device__ __forceinline__ void mma16816h(float* d, const uint32_t* a,
                                          const uint32_t* b) {
    asm volatile(
        "mma.sync.aligned.m16n8k16.row.col.f32.f16.f16.f32 "
        "{%0,%1,%2,%3}, {%4,%5,%6,%7}, {%8,%9}, {%0,%1,%2,%3};"
        : "+f"(d[0]), "+f"(d[1]), "+f"(d[2]), "+f"(d[3])
        : "r"(a[0]), "r"(a[1]), "r"(a[2]), "r"(a[3]), "r"(b[0]), "r"(b[1]));
}

// pack two floats -> fp16x2 hi + fp16x2 lo(residual)
__device__ __forceinline__ void packhl_h(float x, float y, uint32_t& hp, uint32_t& lp) {
    __half2 hv = __floats2half2_rn(x, y);
    float rx = x - __half2float(__low2half(hv));
    float ry = y - __half2float(__high2half(hv));
    __half2 lv = __floats2half2_rn(rx, ry);
    hp = *reinterpret_cast<uint32_t*>(&hv);
    lp = *reinterpret_cast<uint32_t*>(&lv);
}

// ---------------------------------------------------------------------------
// convert / transpose pre-passes
// ---------------------------------------------------------------------------
__global__ void convert_f32_h(const float* __restrict__ in,
                              __half* __restrict__ out, int n4) {
    int i = blockIdx.x * blockDim.x + threadIdx.x;
    if (i >= n4) return;
    float4 v = *(const float4*)(in + (size_t)i * 4);
    __half2 a = __floats2half2_rn(v.x, v.y);
    __half2 b = __floats2half2_rn(v.z, v.w);
    __half2* op = (__half2*)(out + (size_t)i * 4);
    op[0] = a; op[1] = b;
}

__global__ void transpose_h(const float* __restrict__ W,
                            __half* __restrict__ Th, int K, int N) {
    __shared__ float t[32][33];
    int n0 = blockIdx.x * 32, k0 = blockIdx.y * 32;
    int tx = threadIdx.x, ty = threadIdx.y;      // (32,8)
    #pragma unroll
    for (int j = 0; j < 32; j += 8)
        t[ty + j][tx] = W[(size_t)(k0 + ty + j) * N + n0 + tx];
    __syncthreads();
    #pragma unroll
    for (int j = 0; j < 32; j += 8)
        Th[(size_t)(n0 + ty + j) * K + k0 + tx] = __float2half(t[tx][ty + j]);
}

// ---------------------------------------------------------------------------
// shared swizzle: 64B rows, chunk ^= (row>>1)&3
// ---------------------------------------------------------------------------
#define GBK 32
#define GSWZ(r, c) ((uint32_t)(r) * 64u + ((((uint32_t)(c) ^ (((uint32_t)(r) >> 1) & 3u))) << 4))

// ---------------------------------------------------------------------------
// QKV GEMM (fp16x1):  BM=128, BN=192, BK=32, 8 warps (2x4), warp 64x48,
// 4-stage cp.async.  A = x single fp16, B = Wqkv^T single fp16.
// Epilogue: bias+scale; q -> fp16 hi/lo (scaled), k/v -> single fp16.
// Grid 32x32 = 1024 CTAs -> 6.92 waves (98.8% wave util).
// ---------------------------------------------------------------------------
#define QOFF_A 0
#define QOFF_B 8192                   // A: 128 rows * 64B = 8192
#define QSTAGEB 20480                 // + B: 192 rows * 64B = 12288
#define QNSTAGE 4
#define QKV_DYN_SMEM (QNSTAGE * QSTAGEB)   // 81920

__global__ __launch_bounds__(256, 1) void gemm_qkv(
    const __half* __restrict__ Am, const __half* __restrict__ Bm,
    const float* __restrict__ bias,
    __half* __restrict__ qh, __half* __restrict__ ql,
    __half* __restrict__ kh, __half* __restrict__ vh)
{
    extern __shared__ __align__(128) char sm[];
    const uint32_t sbase = smem_u32(sm);

    const int tid = threadIdx.x;
    const int wid = tid >> 5;
    const int lane = tid & 31;
    const int m0 = blockIdx.y * 128;
    const int n0 = blockIdx.x * 192;
    const int wm = (wid >> 2) * 64;      // 0 / 64
    const int wn = (wid & 3) * 48;       // 0/48/96/144

    const int tr = tid >> 2;             // 0..63
    const int pc = tid & 3;              // chunk 0..3
    const __half* pA = Am + (m0 + tr) * K_ + pc * 8;
    const __half* pB = Bm + (n0 + tr) * K_ + pc * 8;
    const uint32_t dT0 = GSWZ(tr, pc);
    const uint32_t dT1 = GSWZ(tr + 64, pc);
    const uint32_t dT2 = GSWZ(tr + 128, pc);

    auto produce = [&](int stg, int kblk) {
        uint32_t s = sbase + stg * QSTAGEB;
        CP16(s + QOFF_A + dT0, pA + kblk);
        CP16(s + QOFF_A + dT1, pA + 64 * K_ + kblk);
        CP16(s + QOFF_B + dT0, pB + kblk);
        CP16(s + QOFF_B + dT1, pB + 64 * K_ + kblk);
        CP16(s + QOFF_B + dT2, pB + 128 * K_ + kblk);
    };

    float acc[4][6][4];
    #pragma unroll
    for (int i = 0; i < 4; i++)
        #pragma unroll
        for (int j = 0; j < 6; j++)
            #pragma unroll
            for (int r = 0; r < 4; r++) acc[i][j][r] = 0.f;

    uint32_t aoff[4], boff[3];
    #pragma unroll
    for (int ti = 0; ti < 4; ti++)
        aoff[ti] = GSWZ(wm + ti * 16 + (lane & 15), (lane >> 4));
    #pragma unroll
    for (int pj = 0; pj < 3; pj++)
        boff[pj] = GSWZ(wn + pj * 16 + (lane & 7) + ((lane >> 4) & 1) * 8,
                        ((lane >> 3) & 1));

    auto compute = [&](int stg) {
        uint32_t s = sbase + stg * QSTAGEB;
        #pragma unroll
        for (int ks = 0; ks < 2; ks++) {
            const uint32_t kx = ks ? 0x20u : 0u;
            uint32_t ah[4][4];
            #pragma unroll
            for (int ti = 0; ti < 4; ti++) {
                uint32_t ad = s + QOFF_A + (aoff[ti] ^ kx);
                LDSM_X4(ah[ti][0], ah[ti][1], ah[ti][2], ah[ti][3], ad);
            }
            #pragma unroll
            for (int pj = 0; pj < 3; pj++) {
                uint32_t bd = s + QOFF_B + (boff[pj] ^ kx);
                uint32_t h0, h1, h2, h3;
                LDSM_X4(h0, h1, h2, h3, bd);
                uint32_t bh0[2] = {h0, h1}, bh1[2] = {h2, h3};
                #pragma unroll
                for (int ti = 0; ti < 4; ti++) {
                    mma16816h(acc[ti][2 * pj],     ah[ti], bh0);
                    mma16816h(acc[ti][2 * pj + 1], ah[ti], bh1);
                }
            }
        }
    };

    const int NK = K_ / GBK;             // 64
    produce(0, 0); CP_COMMIT();
    produce(1, GBK); CP_COMMIT();
    produce(2, 2 * GBK); CP_COMMIT();

    for (int it = 0; it < NK; ++it) {
        CP_WAIT(2);
        __syncthreads();
        compute(it & (QNSTAGE - 1));
        if (it + 3 < NK) produce((it + 3) & (QNSTAGE - 1), (it + 3) * GBK);
        CP_COMMIT();
    }

    // ---- epilogue: q -> fp16 hi/lo (scaled); k/v -> single fp16 ----
    const int er = lane >> 2;
    const int ec = (lane & 3) * 2;
    #pragma unroll
    for (int tj = 0; tj < 6; tj++) {
        int col = n0 + wn + tj * 8 + ec;
        int hh = col / 384, rem = col % 384;
        int which = rem >> 7, hd = rem & 127;
        float bx = bias[col], by = bias[col + 1];
        #pragma unroll
        for (int ti = 0; ti < 4; ti++) {
            #pragma unroll
            for (int rr = 0; rr < 2; rr++) {
                int row = m0 + wm + ti * 16 + er + rr * 8;
                int bb = row >> 11, ss = row & 2047;
                size_t off = (((size_t)(bb * H_ + hh)) * S_ + ss) * HD_ + hd;
                float vx = acc[ti][tj][rr * 2] + bx;
                float vy = acc[ti][tj][rr * 2 + 1] + by;
                if (which == 0) {
                    uint32_t hp, lp;
                    packhl_h(vx * SCALE_, vy * SCALE_, hp, lp);
                    *(uint32_t*)(qh + off) = hp;
                    *(uint32_t*)(ql + off) = lp;
                } else {
                    __half2 hv = __floats2half2_rn(vx, vy);
                    __half* dst = (which == 1) ? kh : vh;
                    *(__half2*)(dst + off) = hv;
                }
            }
        }
    }
}

// ---------------------------------------------------------------------------
// Proj GEMM (fp16x2):  C = A @ Bt^T + bias.  A fp16 hi/lo, B single fp16.
// BM=128, BN=256, BK=32, 8 warps (2x4), warp 64x64, 4-stage cp.async.
// ---------------------------------------------------------------------------
#define POFF_AH 0
#define POFF_AL 8192
#define POFF_B  16384                 // B: 256 rows * 64B = 16384
#define PSTAGEB 32768
#define PNSTAGE 4
#define PROJ_DYN_SMEM (PNSTAGE * PSTAGEB)   // 131072

__global__ __launch_bounds__(256, 1) void gemm_proj(
    const __half* __restrict__ Ah, const __half* __restrict__ Al,
    const __half* __restrict__ Bm,
    const float* __restrict__ bias, float* __restrict__ C)
{
    extern __shared__ __align__(128) char sm[];
    const uint32_t sbase = smem_u32(sm);

    const int tid = threadIdx.x;
    const int wid = tid >> 5;
    const int lane = tid & 31;
    const int m0 = blockIdx.y * 128;
    const int n0 = blockIdx.x * 256;
    const int wm = (wid >> 2) * 64;
    const int wn = (wid & 3) * 64;

    const int tr = tid >> 2;
    const int pc = tid & 3;
    const __half* pAh = Ah + (m0 + tr) * K_ + pc * 8;
    const __half* pAl = Al + (m0 + tr) * K_ + pc * 8;
    const __half* pB  = Bm + (n0 + tr) * K_ + pc * 8;
    const uint32_t dT0 = GSWZ(tr, pc);
    const uint32_t dT1 = GSWZ(tr + 64, pc);
    const uint32_t dT2 = GSWZ(tr + 128, pc);
    const uint32_t dT3 = GSWZ(tr + 192, pc);

    auto produce = [&](int stg, int kblk) {
        uint32_t s = sbase + stg * PSTAGEB;
        CP16(s + POFF_AH + dT0, pAh + kblk);
        CP16(s + POFF_AL + dT0, pAl + kblk);
        CP16(s + POFF_AH + dT1, pAh + 64 * K_ + kblk);
        CP16(s + POFF_AL + dT1, pAl + 64 * K_ + kblk);
        CP16(s + POFF_B + dT0, pB + kblk);
        CP16(s + POFF_B + dT1, pB + 64 * K_ + kblk);
        CP16(s + POFF_B + dT2, pB + 128 * K_ + kblk);
        CP16(s + POFF_B + dT3, pB + 192 * K_ + kblk);
    };

    float acc[4][8][4];
    #pragma unroll
    for (int i = 0; i < 4; i++)
        #pragma unroll
        for (int j = 0; j < 8; j++)
            #pragma unroll
            for (int r = 0; r < 4; r++) acc[i][j][r] = 0.f;

    uint32_t aoff[4], boff[4];
    #pragma unroll
    for (int ti = 0; ti < 4; ti++)
        aoff[ti] = GSWZ(wm + ti * 16 + (lane & 15), (lane >> 4));
    #pragma unroll
    for (int pj = 0; pj < 4; pj++)
        boff[pj] = GSWZ(wn + pj * 16 + (lane & 7) + ((lane >> 4) & 1) * 8,
                        ((lane >> 3) & 1));

    auto compute = [&](int stg) {
        uint32_t s = sbase + stg * PSTAGEB;
        #pragma unroll
        for (int ks = 0; ks < 2; ks++) {
            const uint32_t kx = ks ? 0x20u : 0u;
            uint32_t ah[4][4], al[4][4];
            #pragma unroll
            for (int ti = 0; ti < 4; ti++) {
                uint32_t ad = s + (aoff[ti] ^ kx);
                LDSM_X4(ah[ti][0], ah[ti][1], ah[ti][2], ah[ti][3], ad + POFF_AH);
                LDSM_X4(al[ti][0], al[ti][1], al[ti][2], al[ti][3], ad + POFF_AL);
            }
            #pragma unroll
            for (int pj = 0; pj < 4; pj++) {
                uint32_t bd = s + (boff[pj] ^ kx);
                uint32_t h0, h1, h2, h3;
                LDSM_X4(h0, h1, h2, h3, bd + POFF_B);
                uint32_t bh0[2] = {h0, h1}, bh1[2] = {h2, h3};
                #pragma unroll
                for (int ti = 0; ti < 4; ti++) {
                    mma16816h(acc[ti][2 * pj],     ah[ti], bh0);
                    mma16816h(acc[ti][2 * pj + 1], ah[ti], bh1);
                }
                #pragma unroll
                for (int ti = 0; ti < 4; ti++) {
                    mma16816h(acc[ti][2 * pj],     al[ti], bh0);
                    mma16816h(acc[ti][2 * pj + 1], al[ti], bh1);
                }
            }
        }
    };

    const int NK = K_ / GBK;
    produce(0, 0); CP_COMMIT();
    produce(1, GBK); CP_COMMIT();
    produce(2, 2 * GBK); CP_COMMIT();

    for (int it = 0; it < NK; ++it) {
        CP_WAIT(2);
        __syncthreads();
        compute(it & (PNSTAGE - 1));
        if (it + 3 < NK) produce((it + 3) & (PNSTAGE - 1), (it + 3) * GBK);
        CP_COMMIT();
    }

    const int er = lane >> 2;
    const int ec = (lane & 3) * 2;
    #pragma unroll
    for (int tj = 0; tj < 8; tj++) {
        int col = n0 + wn + tj * 8 + ec;
        float bx = bias[col], by = bias[col + 1];
        #pragma unroll
        for (int ti = 0; ti < 4; ti++) {
            int row = m0 + wm + ti * 16 + er;
            float2 v0 = { acc[ti][tj][0] + bx, acc[ti][tj][1] + by };
            float2 v1 = { acc[ti][tj][2] + bx, acc[ti][tj][3] + by };
            *(float2*)(C + (size_t)row * D_ + col) = v0;
            *(float2*)(C + (size_t)(row + 8) * D_ + col) = v1;
        }
    }
}

// ---------------------------------------------------------------------------
// HMMA causal flash attention (fp16x2): Q fp16 hi/lo x K single fp16 (2 terms),
// P fp16 hi/lo x V single fp16 (2 terms).  FA2 register softmax.
// BQ=128 (8 warps x 16 rows), BKV=64, HD=128. Double-buffered KV via cp.async.
// ---------------------------------------------------------------------------
#define FROWB 272                      // 128 fp16 + 8 pad = 136 elems
#define FQBYTES (128 * FROWB)          // per Q array
#define FKBYTES (64 * FROWB)           // per K/V array
#define FSTGB (2 * FKBYTES)            // k, v
#define FLASH_DYN_SMEM (2 * FQBYTES + 2 * FSTGB)   // 139264 B

__global__ __launch_bounds__(256, 1) void flash_mma(
    const __half* __restrict__ qh_, const __half* __restrict__ ql_,
    const __half* __restrict__ kh_, const __half* __restrict__ vh_,
    __half* __restrict__ oh_, __half* __restrict__ ol_)
{
    extern __shared__ __align__(128) char fsm[];
    const uint32_t sb = smem_u32(fsm);
    const int tid = threadIdx.x, wq = tid >> 5, lane = tid & 31;
    const int bi = (int)gridDim.x - 1 - (int)blockIdx.x;   // big blocks first
    const int hh = blockIdx.y, b = blockIdx.z;
    const int q0 = bi * 128;
    const size_t bh = ((size_t)b * H_ + hh) * S_;
    const uint32_t QH = sb, QL = sb + FQBYTES;
    const uint32_t KV0 = sb + 2 * FQBYTES;

    // Q tile load (both hi/lo)
    #pragma unroll
    for (int i = 0; i < 8; i++) {
        int id = tid + i * 256;
        int r = id >> 4, c = id & 15;
        size_t src = (bh + q0 + r) * HD_ + c * 8;
        CP16(QH + r * FROWB + c * 16, qh_ + src);
        CP16(QL + r * FROWB + c * 16, ql_ + src);
    }
    auto produce = [&](int stg, int kt) {
        uint32_t s = KV0 + stg * FSTGB;
        int k0 = kt * 64;
        #pragma unroll
        for (int i = 0; i < 4; i++) {
            int id = tid + i * 256;
            int r = id >> 4, c = id & 15;
            size_t src = (bh + k0 + r) * HD_ + c * 8;
            uint32_t d = r * FROWB + c * 16;
            CP16(s + d, kh_ + src);
            CP16(s + FKBYTES + d, vh_ + src);
        }
    };

    float o[16][4];
    #pragma unroll
    for (int j = 0; j < 16; j++)
        #pragma unroll
        for (int r = 0; r < 4; r++) o[j][r] = 0.f;
    float m0 = -1e30f, m1 = -1e30f, l0 = 0.f, l1 = 0.f;

    const int er = lane >> 2, ec2 = (lane & 3) * 2;
    const uint32_t a_row = wq * 16 + (lane & 15);
    const uint32_t a_kb  = (lane >> 4) * 16;
    const uint32_t b_row = (lane & 7) + ((lane >> 4) & 1) * 8;
    const uint32_t b_kb  = ((lane >> 3) & 1) * 16;
    const uint32_t v_row = (lane & 7) + ((lane >> 3) & 1) * 8;
    const uint32_t v_cb  = ((lane >> 4) & 1) * 16;

    const int nkt = 2 * bi + 2;
    produce(0, 0);
    CP_COMMIT();

    for (int kt = 0; kt < nkt; kt++) {
        if (kt + 1 < nkt) { produce((kt + 1) & 1, kt + 1); CP_COMMIT(); CP_WAIT(1); }
        else CP_WAIT(0);
        __syncthreads();
        const uint32_t kb = KV0 + (kt & 1) * FSTGB;

        // ---- phase 1: S = Q K^T (Q hi/lo x K single: 2 terms) ----
        float s[8][4];
        #pragma unroll
        for (int j = 0; j < 8; j++)
            #pragma unroll
            for (int r = 0; r < 4; r++) s[j][r] = 0.f;

        #pragma unroll
        for (int ks = 0; ks < 8; ks++) {
            uint32_t ah[4], al[4];
            uint32_t qa = QH + a_row * FROWB + ks * 32 + a_kb;
            LDSM_X4(ah[0], ah[1], ah[2], ah[3], qa);
            LDSM_X4(al[0], al[1], al[2], al[3], qa + FQBYTES);
            #pragma unroll
            for (int bj = 0; bj < 4; bj++) {
                uint32_t ka = kb + (bj * 16 + b_row) * FROWB + ks * 32 + b_kb;
                uint32_t h0, h1, h2, h3;
                LDSM_X4(h0, h1, h2, h3, ka);
                uint32_t bh0[2] = {h0, h1}, bh1[2] = {h2, h3};
                mma16816h(s[2 * bj],     ah, bh0);
                mma16816h(s[2 * bj + 1], ah, bh1);
                mma16816h(s[2 * bj],     al, bh0);
                mma16816h(s[2 * bj + 1], al, bh1);
            }
        }

        // ---- causal mask (only last two tiles) ----
        if (kt >= 2 * bi) {
            int row0 = q0 + wq * 16 + er, row1 = row0 + 8;
            int colb = kt * 64 + ec2;
            #pragma unroll
            for (int j = 0; j < 8; j++) {
                int c0 = colb + j * 8, c1 = c0 + 1;
                if (c0 > row0) s[j][0] = -1e30f;
                if (c1 > row0) s[j][1] = -1e30f;
                if (c0 > row1) s[j][2] = -1e30f;
                if (c1 > row1) s[j][3] = -1e30f;
            }
        }

        // ---- online softmax (rows er / er+8) ----
        float mx0 = -1e30f, mx1 = -1e30f;
        #pragma unroll
        for (int j = 0; j < 8; j++) {
            mx0 = fmaxf(mx0, fmaxf(s[j][0], s[j][1]));
            mx1 = fmaxf(mx1, fmaxf(s[j][2], s[j][3]));
        }
        mx0 = fmaxf(mx0, __shfl_xor_sync(0xffffffffu, mx0, 1));
        mx0 = fmaxf(mx0, __shfl_xor_sync(0xffffffffu, mx0, 2));
        mx1 = fmaxf(mx1, __shfl_xor_sync(0xffffffffu, mx1, 1));
        mx1 = fmaxf(mx1, __shfl_xor_sync(0xffffffffu, mx1, 2));
        float mn0 = fmaxf(m0, mx0), mn1 = fmaxf(m1, mx1);
        float al0 = __expf(m0 - mn0), al1 = __expf(m1 - mn1);
        m0 = mn0; m1 = mn1;
        float sm0 = 0.f, sm1 = 0.f;
        #pragma unroll
        for (int j = 0; j < 8; j++) {
            s[j][0] = __expf(s[j][0] - m0); sm0 += s[j][0];
            s[j][1] = __expf(s[j][1] - m0); sm0 += s[j][1];
            s[j][2] = __expf(s[j][2] - m1); sm1 += s[j][2];
            s[j][3] = __expf(s[j][3] - m1); sm1 += s[j][3];
        }
        sm0 += __shfl_xor_sync(0xffffffffu, sm0, 1);
        sm0 += __shfl_xor_sync(0xffffffffu, sm0, 2);
        sm1 += __shfl_xor_sync(0xffffffffu, sm1, 1);
        sm1 += __shfl_xor_sync(0xffffffffu, sm1, 2);
        l0 = l0 * al0 + sm0;
        l1 = l1 * al1 + sm1;
        #pragma unroll
        for (int j = 0; j < 16; j++) {
            o[j][0] *= al0; o[j][1] *= al0;
            o[j][2] *= al1; o[j][3] *= al1;
        }

        // ---- phase 2: O += P V (P hi/lo x V single: 2 terms; V trans) ----
        const uint32_t vbase = kb + FKBYTES;
        #pragma unroll
        for (int ki = 0; ki < 4; ki++) {
            uint32_t ph[4], pl[4];
            packhl_h(s[2 * ki][0],     s[2 * ki][1],     ph[0], pl[0]);
            packhl_h(s[2 * ki][2],     s[2 * ki][3],     ph[1], pl[1]);
            packhl_h(s[2 * ki + 1][0], s[2 * ki + 1][1], ph[2], pl[2]);
            packhl_h(s[2 * ki + 1][2], s[2 * ki + 1][3], ph[3], pl[3]);
            #pragma unroll
            for (int nj = 0; nj < 8; nj++) {
                uint32_t va = vbase + (ki * 16 + v_row) * FROWB + nj * 32 + v_cb;
                uint32_t h0, h1, h2, h3;
                LDSM_X4T(h0, h1, h2, h3, va);
                uint32_t vh0[2] = {h0, h1}, vh1[2] = {h2, h3};
                mma16816h(o[2 * nj],     ph, vh0);
                mma16816h(o[2 * nj + 1], ph, vh1);
                mma16816h(o[2 * nj],     pl, vh0);
                mma16816h(o[2 * nj + 1], pl, vh1);
            }
        }
        __syncthreads();   // protect KV buffer before next produce overwrites
    }

    // ---- epilogue: normalize + fp16 hi/lo write ----
    float il0 = 1.f / l0, il1 = 1.f / l1;
    int row0 = q0 + wq * 16 + er;
    #pragma unroll
    for (int j = 0; j < 16; j++) {
        int col = hh * 128 + j * 8 + ec2;
        uint32_t hp, lp;
        packhl_h(o[j][0] * il0, o[j][1] * il0, hp, lp);
        size_t off0 = ((size_t)b * S_ + row0) * D_ + col;
        *(uint32_t*)(oh_ + off0) = hp;
        *(uint32_t*)(ol_ + off0) = lp;
        packhl_h(o[j][2] * il1, o[j][3] * il1, hp, lp);
        size_t off1 = ((size_t)b * S_ + row0 + 8) * D_ + col;
        *(uint32_t*)(oh_ + off1) = hp;
        *(uint32_t*)(ol_ + off1) = lp;
    }
}

// ---------------------------------------------------------------------------
// Launch
// ---------------------------------------------------------------------------
extern "C" void kernel_launch(void* const* d_in, const int* in_sizes, int n_in,
                              void* d_out, int out_size)
{
    (void)in_sizes; (void)n_in; (void)out_size;
    const float* x    = (const float*)d_in[0];
    const float* Wqkv = (const float*)d_in[1];
    const float* bqkv = (const float*)d_in[2];
    const float* Wo   = (const float*)d_in[3];
    const float* bo   = (const float*)d_in[4];
    float* out = (float*)d_out;

    __half *xh, *w1h, *w2h;
    __half *qhi, *qlo, *khh, *vhh, *ahi, *alo;
    cudaGetSymbolAddress((void**)&xh, g_xh);
    cudaGetSymbolAddress((void**)&w1h, g_w1h);   cudaGetSymbolAddress((void**)&w2h, g_w2h);
    cudaGetSymbolAddress((void**)&qhi, g_qhi);   cudaGetSymbolAddress((void**)&qlo, g_qlo);
    cudaGetSymbolAddress((void**)&khh, g_kh);    cudaGetSymbolAddress((void**)&vhh, g_vh);
    cudaGetSymbolAddress((void**)&ahi, g_ahi);   cudaGetSymbolAddress((void**)&alo, g_alo);

    cudaFuncSetAttribute(gemm_qkv,
                         cudaFuncAttributeMaxDynamicSharedMemorySize, QKV_DYN_SMEM);
    cudaFuncSetAttribute(gemm_proj,
                         cudaFuncAttributeMaxDynamicSharedMemorySize, PROJ_DYN_SMEM);
    cudaFuncSetAttribute(flash_mma,
                         cudaFuncAttributeMaxDynamicSharedMemorySize, FLASH_DYN_SMEM);

    // 1) convert x to single fp16
    {
        int n4 = (M_ * D_) / 4;
        convert_f32_h<<<(n4 + 255) / 256, 256>>>(x, xh, n4);
    }
    // 2) transpose weights to [N,K] fp16
    transpose_h<<<dim3((3 * D_) / 32, D_ / 32), dim3(32, 8)>>>(Wqkv, w1h, D_, 3 * D_);
    transpose_h<<<dim3(D_ / 32, D_ / 32), dim3(32, 8)>>>(Wo, w2h, D_, D_);

    // 3) QKV GEMM (fp16x1, BN=192 -> 1024 CTAs)
    gemm_qkv<<<dim3((3 * D_) / 192, M_ / 128), 256, QKV_DYN_SMEM>>>(
        xh, w1h, bqkv, qhi, qlo, khh, vhh);

    // 4) HMMA flash attention (fp16x2 core, outputs fp16 hi/lo)
    flash_mma<<<dim3(S_ / 128, H_, B_), 256, FLASH_DYN_SMEM>>>(
        qhi, qlo, khh, vhh, ahi, alo);

    // 5) out = attn @ Wo + bo  (fp16x2)
    gemm_proj<<<dim3(D_ / 256, M_ / 128), 256, PROJ_DYN_SMEM>>>(
        ahi, alo, w2h, bo, out);
}

// round 12
// speedup vs baseline: 2.3867x; 1.1559x over previous
#include <cuda_runtime.h>
#include <cuda_fp16.h>
#include <cstdint>
#include <cstddef>

// ---------------------------------------------------------------------------
// Problem constants
// ---------------------------------------------------------------------------
#define B_  2
#define S_  2048
#define D_  2048
#define H_  16
#define HD_ 128
#define M_  (B_*S_)            // 4096 rows
#define K_  2048               // inner dim of BOTH gemms (compile-time)
#define SCALE_ 0.08838834764831845f

// ---------------------------------------------------------------------------
// Scratch (__device__ globals; no allocation allowed)
// ---------------------------------------------------------------------------
__device__ __half g_xh[(size_t)M_ * D_];                // x single fp16
__device__ __half g_w1h[(size_t)3 * D_ * D_];           // Wqkv^T [6144,2048] fp16
__device__ __half g_w2h[(size_t)D_ * D_];               // Wo^T [2048,2048] fp16
// q (pre-scaled), k, v single fp16.  [B,H,S,HD]
__device__ __half g_qh[(size_t)M_ * D_];
__device__ __half g_kh[(size_t)M_ * D_];
__device__ __half g_vh[(size_t)M_ * D_];
// attention output [B,S,D] single fp16 (feeds proj)
__device__ __half g_ah[(size_t)M_ * D_];

// ---------------------------------------------------------------------------
// Portable PTX helpers (virtual arch compute_103: no tcgen05)
// ---------------------------------------------------------------------------
__device__ __forceinline__ uint32_t smem_u32(const void* p) {
    uint32_t a;
    asm("{ .reg .u64 t; cvta.to.shared.u64 t, %1; cvt.u32.u64 %0, t; }"
        : "=r"(a) : "l"(p));
    return a;
}

#define CP16(dst_u32, src_ptr) \
    asm volatile("cp.async.cg.shared.global [%0], [%1], 16;" \
                 :: "r"(dst_u32), "l"(src_ptr) : "memory")
#define CP_COMMIT() asm volatile("cp.async.commit_group;" ::: "memory")
#define CP_WAIT(n)  asm volatile("cp.async.wait_group %0;" :: "n"(n) : "memory")

#define LDSM_X4(r0, r1, r2, r3, addr) \
    asm volatile("ldmatrix.sync.aligned.m8n8.x4.shared.b16 {%0,%1,%2,%3}, [%4];" \
                 : "=r"(r0), "=r"(r1), "=r"(r2), "=r"(r3) : "r"(addr))
#define LDSM_X4T(r0, r1, r2, r3, addr) \
    asm volatile("ldmatrix.sync.aligned.m8n8.x4.trans.shared.b16 {%0,%1,%2,%3}, [%4];" \
                 : "=r"(r0), "=r"(r1), "=r"(r2), "=r"(r3) : "r"(addr))

__device__ __forceinline__ void mma16816h(float* d, const uint32_t* a,
                                          const uint32_t* b) {
    asm volatile(
        "mma.sync.aligned.m16n8k16.row.col.f32.f16.f16.f32 "
        "{%0,%1,%2,%3}, {%4,%5,%6,%7}, {%8,%9}, {%0,%1,%2,%3};"
        : "+f"(d[0]), "+f"(d[1]), "+f"(d[2]), "+f"(d[3])
        : "r"(a[0]), "r"(a[1]), "r"(a[2]), "r"(a[3]), "r"(b[0]), "r"(b[1]));
}

// pack two floats -> fp16x2 hi + fp16x2 lo(residual)
__device__ __forceinline__ void packhl_h(float x, float y, uint32_t& hp, uint32_t& lp) {
    __half2 hv = __floats2half2_rn(x, y);
    float rx = x - __half2float(__low2half(hv));
    float ry = y - __half2float(__high2half(hv));
    __half2 lv = __floats2half2_rn(rx, ry);
    hp = *reinterpret_cast<uint32_t*>(&hv);
    lp = *reinterpret_cast<uint32_t*>(&lv);
}

// ---------------------------------------------------------------------------
// convert / transpose pre-passes
// ---------------------------------------------------------------------------
__global__ void convert_f32_h(const float* __restrict__ in,
                              __half* __restrict__ out, int n4) {
    int i = blockIdx.x * blockDim.x + threadIdx.x;
    if (i >= n4) return;
    float4 v = *(const float4*)(in + (size_t)i * 4);
    __half2 a = __floats2half2_rn(v.x, v.y);
    __half2 b = __floats2half2_rn(v.z, v.w);
    __half2* op = (__half2*)(out + (size_t)i * 4);
    op[0] = a; op[1] = b;
}

__global__ void transpose_h(const float* __restrict__ W,
                            __half* __restrict__ Th, int K, int N) {
    __shared__ float t[32][33];
    int n0 = blockIdx.x * 32, k0 = blockIdx.y * 32;
    int tx = threadIdx.x, ty = threadIdx.y;      // (32,8)
    #pragma unroll
    for (int j = 0; j < 32; j += 8)
        t[ty + j][tx] = W[(size_t)(k0 + ty + j) * N + n0 + tx];
    __syncthreads();
    #pragma unroll
    for (int j = 0; j < 32; j += 8)
        Th[(size_t)(n0 + ty + j) * K + k0 + tx] = __float2half(t[tx][ty + j]);
}

// ---------------------------------------------------------------------------
// shared swizzle: 64B rows, chunk ^= (row>>1)&3
// ---------------------------------------------------------------------------
#define GBK 32
#define GSWZ(r, c) ((uint32_t)(r) * 64u + ((((uint32_t)(c) ^ (((uint32_t)(r) >> 1) & 3u))) << 4))

// ---------------------------------------------------------------------------
// QKV GEMM (fp16x1):  BM=128, BN=192, BK=32, 8 warps (2x4), warp 64x48,
// 4-stage cp.async.  Epilogue: bias (+scale for q); single fp16 q/k/v.
// Grid 32x32 = 1024 CTAs -> 6.92 waves (98.8% wave util).
// ---------------------------------------------------------------------------
#define QOFF_A 0
#define QOFF_B 8192                   // A: 128 rows * 64B = 8192
#define QSTAGEB 20480                 // + B: 192 rows * 64B = 12288
#define QNSTAGE 4
#define QKV_DYN_SMEM (QNSTAGE * QSTAGEB)   // 81920

__global__ __launch_bounds__(256, 1) void gemm_qkv(
    const __half* __restrict__ Am, const __half* __restrict__ Bm,
    const float* __restrict__ bias,
    __half* __restrict__ qh, __half* __restrict__ kh, __half* __restrict__ vh)
{
    extern __shared__ __align__(128) char sm[];
    const uint32_t sbase = smem_u32(sm);

    const int tid = threadIdx.x;
    const int wid = tid >> 5;
    const int lane = tid & 31;
    const int m0 = blockIdx.y * 128;
    const int n0 = blockIdx.x * 192;
    const int wm = (wid >> 2) * 64;      // 0 / 64
    const int wn = (wid & 3) * 48;       // 0/48/96/144

    const int tr = tid >> 2;             // 0..63
    const int pc = tid & 3;              // chunk 0..3
    const __half* pA = Am + (m0 + tr) * K_ + pc * 8;
    const __half* pB = Bm + (n0 + tr) * K_ + pc * 8;
    const uint32_t dT0 = GSWZ(tr, pc);
    const uint32_t dT1 = GSWZ(tr + 64, pc);
    const uint32_t dT2 = GSWZ(tr + 128, pc);

    auto produce = [&](int stg, int kblk) {
        uint32_t s = sbase + stg * QSTAGEB;
        CP16(s + QOFF_A + dT0, pA + kblk);
        CP16(s + QOFF_A + dT1, pA + 64 * K_ + kblk);
        CP16(s + QOFF_B + dT0, pB + kblk);
        CP16(s + QOFF_B + dT1, pB + 64 * K_ + kblk);
        CP16(s + QOFF_B + dT2, pB + 128 * K_ + kblk);
    };

    float acc[4][6][4];
    #pragma unroll
    for (int i = 0; i < 4; i++)
        #pragma unroll
        for (int j = 0; j < 6; j++)
            #pragma unroll
            for (int r = 0; r < 4; r++) acc[i][j][r] = 0.f;

    uint32_t aoff[4], boff[3];
    #pragma unroll
    for (int ti = 0; ti < 4; ti++)
        aoff[ti] = GSWZ(wm + ti * 16 + (lane & 15), (lane >> 4));
    #pragma unroll
    for (int pj = 0; pj < 3; pj++)
        boff[pj] = GSWZ(wn + pj * 16 + (lane & 7) + ((lane >> 4) & 1) * 8,
                        ((lane >> 3) & 1));

    auto compute = [&](int stg) {
        uint32_t s = sbase + stg * QSTAGEB;
        #pragma unroll
        for (int ks = 0; ks < 2; ks++) {
            const uint32_t kx = ks ? 0x20u : 0u;
            uint32_t ah[4][4];
            #pragma unroll
            for (int ti = 0; ti < 4; ti++) {
                uint32_t ad = s + QOFF_A + (aoff[ti] ^ kx);
                LDSM_X4(ah[ti][0], ah[ti][1], ah[ti][2], ah[ti][3], ad);
            }
            #pragma unroll
            for (int pj = 0; pj < 3; pj++) {
                uint32_t bd = s + QOFF_B + (boff[pj] ^ kx);
                uint32_t h0, h1, h2, h3;
                LDSM_X4(h0, h1, h2, h3, bd);
                uint32_t bh0[2] = {h0, h1}, bh1[2] = {h2, h3};
                #pragma unroll
                for (int ti = 0; ti < 4; ti++) {
                    mma16816h(acc[ti][2 * pj],     ah[ti], bh0);
                    mma16816h(acc[ti][2 * pj + 1], ah[ti], bh1);
                }
            }
        }
    };

    const int NK = K_ / GBK;             // 64
    produce(0, 0); CP_COMMIT();
    produce(1, GBK); CP_COMMIT();
    produce(2, 2 * GBK); CP_COMMIT();

    for (int it = 0; it < NK; ++it) {
        CP_WAIT(2);
        __syncthreads();
        compute(it & (QNSTAGE - 1));
        if (it + 3 < NK) produce((it + 3) & (QNSTAGE - 1), (it + 3) * GBK);
        CP_COMMIT();
    }

    // ---- epilogue: single fp16 q (scaled) / k / v ----
    const int er = lane >> 2;
    const int ec = (lane & 3) * 2;
    #pragma unroll
    for (int tj = 0; tj < 6; tj++) {
        int col = n0 + wn + tj * 8 + ec;
        int hh = col / 384, rem = col % 384;
        int which = rem >> 7, hd = rem & 127;
        __half* dst = which == 0 ? qh : (which == 1 ? kh : vh);
        float sc = which == 0 ? SCALE_ : 1.0f;
        float bx = bias[col], by = bias[col + 1];
        #pragma unroll
        for (int ti = 0; ti < 4; ti++) {
            #pragma unroll
            for (int rr = 0; rr < 2; rr++) {
                int row = m0 + wm + ti * 16 + er + rr * 8;
                int bb = row >> 11, ss = row & 2047;
                size_t off = (((size_t)(bb * H_ + hh)) * S_ + ss) * HD_ + hd;
                float vx = (acc[ti][tj][rr * 2] + bx) * sc;
                float vy = (acc[ti][tj][rr * 2 + 1] + by) * sc;
                *(__half2*)(dst + off) = __floats2half2_rn(vx, vy);
            }
        }
    }
}

// ---------------------------------------------------------------------------
// Proj GEMM (fp16x1):  C = A @ Bt^T + bias.  A single fp16, B single fp16.
// BM=128, BN=256, BK=32, 8 warps (2x4), warp 64x64, 4-stage cp.async.
// ---------------------------------------------------------------------------
#define POFF_A 0
#define POFF_B 8192                   // A: 128 rows * 64B
#define PSTAGEB 24576                 // + B: 256 rows * 64B = 16384
#define PNSTAGE 4
#define PROJ_DYN_SMEM (PNSTAGE * PSTAGEB)   // 98304

__global__ __launch_bounds__(256, 1) void gemm_proj(
    const __half* __restrict__ Am, const __half* __restrict__ Bm,
    const float* __restrict__ bias, float* __restrict__ C)
{
    extern __shared__ __align__(128) char sm[];
    const uint32_t sbase = smem_u32(sm);

    const int tid = threadIdx.x;
    const int wid = tid >> 5;
    const int lane = tid & 31;
    const int m0 = blockIdx.y * 128;
    const int n0 = blockIdx.x * 256;
    const int wm = (wid >> 2) * 64;
    const int wn = (wid & 3) * 64;

    const int tr = tid >> 2;
    const int pc = tid & 3;
    const __half* pA = Am + (m0 + tr) * K_ + pc * 8;
    const __half* pB = Bm + (n0 + tr) * K_ + pc * 8;
    const uint32_t dT0 = GSWZ(tr, pc);
    const uint32_t dT1 = GSWZ(tr + 64, pc);
    const uint32_t dT2 = GSWZ(tr + 128, pc);
    const uint32_t dT3 = GSWZ(tr + 192, pc);

    auto produce = [&](int stg, int kblk) {
        uint32_t s = sbase + stg * PSTAGEB;
        CP16(s + POFF_A + dT0, pA + kblk);
        CP16(s + POFF_A + dT1, pA + 64 * K_ + kblk);
        CP16(s + POFF_B + dT0, pB + kblk);
        CP16(s + POFF_B + dT1, pB + 64 * K_ + kblk);
        CP16(s + POFF_B + dT2, pB + 128 * K_ + kblk);
        CP16(s + POFF_B + dT3, pB + 192 * K_ + kblk);
    };

    float acc[4][8][4];
    #pragma unroll
    for (int i = 0; i < 4; i++)
        #pragma unroll
        for (int j = 0; j < 8; j++)
            #pragma unroll
            for (int r = 0; r < 4; r++) acc[i][j][r] = 0.f;

    uint32_t aoff[4], boff[4];
    #pragma unroll
    for (int ti = 0; ti < 4; ti++)
        aoff[ti] = GSWZ(wm + ti * 16 + (lane & 15), (lane >> 4));
    #pragma unroll
    for (int pj = 0; pj < 4; pj++)
        boff[pj] = GSWZ(wn + pj * 16 + (lane & 7) + ((lane >> 4) & 1) * 8,
                        ((lane >> 3) & 1));

    auto compute = [&](int stg) {
        uint32_t s = sbase + stg * PSTAGEB;
        #pragma unroll
        for (int ks = 0; ks < 2; ks++) {
            const uint32_t kx = ks ? 0x20u : 0u;
            uint32_t ah[4][4];
            #pragma unroll
            for (int ti = 0; ti < 4; ti++) {
                uint32_t ad = s + POFF_A + (aoff[ti] ^ kx);
                LDSM_X4(ah[ti][0], ah[ti][1], ah[ti][2], ah[ti][3], ad);
            }
            #pragma unroll
            for (int pj = 0; pj < 4; pj++) {
                uint32_t bd = s + POFF_B + (boff[pj] ^ kx);
                uint32_t h0, h1, h2, h3;
                LDSM_X4(h0, h1, h2, h3, bd);
                uint32_t bh0[2] = {h0, h1}, bh1[2] = {h2, h3};
                #pragma unroll
                for (int ti = 0; ti < 4; ti++) {
                    mma16816h(acc[ti][2 * pj],     ah[ti], bh0);
                    mma16816h(acc[ti][2 * pj + 1], ah[ti], bh1);
                }
            }
        }
    };

    const int NK = K_ / GBK;
    produce(0, 0); CP_COMMIT();
    produce(1, GBK); CP_COMMIT();
    produce(2, 2 * GBK); CP_COMMIT();

    for (int it = 0; it < NK; ++it) {
        CP_WAIT(2);
        __syncthreads();
        compute(it & (PNSTAGE - 1));
        if (it + 3 < NK) produce((it + 3) & (PNSTAGE - 1), (it + 3) * GBK);
        CP_COMMIT();
    }

    const int er = lane >> 2;
    const int ec = (lane & 3) * 2;
    #pragma unroll
    for (int tj = 0; tj < 8; tj++) {
        int col = n0 + wn + tj * 8 + ec;
        float bx = bias[col], by = bias[col + 1];
        #pragma unroll
        for (int ti = 0; ti < 4; ti++) {
            int row = m0 + wm + ti * 16 + er;
            float2 v0 = { acc[ti][tj][0] + bx, acc[ti][tj][1] + by };
            float2 v1 = { acc[ti][tj][2] + bx, acc[ti][tj][3] + by };
            *(float2*)(C + (size_t)row * D_ + col) = v0;
            *(float2*)(C + (size_t)(row + 8) * D_ + col) = v1;
        }
    }
}

// ---------------------------------------------------------------------------
// HMMA causal flash attention: Q single fp16 x K single fp16 (1 term),
// P fp16 hi/lo x V single fp16 (2 terms).  FA2 register softmax.
// BQ=128 (8 warps x 16 rows), BKV=64, HD=128. Double-buffered KV via cp.async.
// Output: single fp16.
// ---------------------------------------------------------------------------
#define FROWB 272                      // 128 fp16 + 8 pad = 136 elems
#define FQBYTES (128 * FROWB)          // Q tile: 34816
#define FKBYTES (64 * FROWB)           // per K/V array: 17408
#define FSTGB (2 * FKBYTES)            // k, v: 34816
#define FLASH_DYN_SMEM (FQBYTES + 2 * FSTGB)   // 104448 B

__global__ __launch_bounds__(256, 1) void flash_mma(
    const __half* __restrict__ qh_,
    const __half* __restrict__ kh_, const __half* __restrict__ vh_,
    __half* __restrict__ oh_)
{
    extern __shared__ __align__(128) char fsm[];
    const uint32_t sb = smem_u32(fsm);
    const int tid = threadIdx.x, wq = tid >> 5, lane = tid & 31;
    const int bi = (int)gridDim.x - 1 - (int)blockIdx.x;   // big blocks first
    const int hh = blockIdx.y, b = blockIdx.z;
    const int q0 = bi * 128;
    const size_t bh = ((size_t)b * H_ + hh) * S_;
    const uint32_t QH = sb;
    const uint32_t KV0 = sb + FQBYTES;

    // Q tile load
    #pragma unroll
    for (int i = 0; i < 8; i++) {
        int id = tid + i * 256;
        int r = id >> 4, c = id & 15;
        size_t src = (bh + q0 + r) * HD_ + c * 8;
        CP16(QH + r * FROWB + c * 16, qh_ + src);
    }
    auto produce = [&](int stg, int kt) {
        uint32_t s = KV0 + stg * FSTGB;
        int k0 = kt * 64;
        #pragma unroll
        for (int i = 0; i < 4; i++) {
            int id = tid + i * 256;
            int r = id >> 4, c = id & 15;
            size_t src = (bh + k0 + r) * HD_ + c * 8;
            uint32_t d = r * FROWB + c * 16;
            CP16(s + d, kh_ + src);
            CP16(s + FKBYTES + d, vh_ + src);
        }
    };

    float o[16][4];
    #pragma unroll
    for (int j = 0; j < 16; j++)
        #pragma unroll
        for (int r = 0; r < 4; r++) o[j][r] = 0.f;
    float m0 = -1e30f, m1 = -1e30f, l0 = 0.f, l1 = 0.f;

    const int er = lane >> 2, ec2 = (lane & 3) * 2;
    const uint32_t a_row = wq * 16 + (lane & 15);
    const uint32_t a_kb  = (lane >> 4) * 16;
    const uint32_t b_row = (lane & 7) + ((lane >> 4) & 1) * 8;
    const uint32_t b_kb  = ((lane >> 3) & 1) * 16;
    const uint32_t v_row = (lane & 7) + ((lane >> 3) & 1) * 8;
    const uint32_t v_cb  = ((lane >> 4) & 1) * 16;

    const int nkt = 2 * bi + 2;
    produce(0, 0);
    CP_COMMIT();

    for (int kt = 0; kt < nkt; kt++) {
        if (kt + 1 < nkt) { produce((kt + 1) & 1, kt + 1); CP_COMMIT(); CP_WAIT(1); }
        else CP_WAIT(0);
        __syncthreads();
        const uint32_t kb = KV0 + (kt & 1) * FSTGB;

        // ---- phase 1: S = Q K^T (single x single: 1 term) ----
        float s[8][4];
        #pragma unroll
        for (int j = 0; j < 8; j++)
            #pragma unroll
            for (int r = 0; r < 4; r++) s[j][r] = 0.f;

        #pragma unroll
        for (int ks = 0; ks < 8; ks++) {
            uint32_t ah[4];
            uint32_t qa = QH + a_row * FROWB + ks * 32 + a_kb;
            LDSM_X4(ah[0], ah[1], ah[2], ah[3], qa);
            #pragma unroll
            for (int bj = 0; bj < 4; bj++) {
                uint32_t ka = kb + (bj * 16 + b_row) * FROWB + ks * 32 + b_kb;
                uint32_t h0, h1, h2, h3;
                LDSM_X4(h0, h1, h2, h3, ka);
                uint32_t bh0[2] = {h0, h1}, bh1[2] = {h2, h3};
                mma16816h(s[2 * bj],     ah, bh0);
                mma16816h(s[2 * bj + 1], ah, bh1);
            }
        }

        // ---- causal mask (only last two tiles) ----
        if (kt >= 2 * bi) {
            int row0 = q0 + wq * 16 + er, row1 = row0 + 8;
            int colb = kt * 64 + ec2;
            #pragma unroll
            for (int j = 0; j < 8; j++) {
                int c0 = colb + j * 8, c1 = c0 + 1;
                if (c0 > row0) s[j][0] = -1e30f;
                if (c1 > row0) s[j][1] = -1e30f;
                if (c0 > row1) s[j][2] = -1e30f;
                if (c1 > row1) s[j][3] = -1e30f;
            }
        }

        // ---- online softmax (rows er / er+8) ----
        float mx0 = -1e30f, mx1 = -1e30f;
        #pragma unroll
        for (int j = 0; j < 8; j++) {
            mx0 = fmaxf(mx0, fmaxf(s[j][0], s[j][1]));
            mx1 = fmaxf(mx1, fmaxf(s[j][2], s[j][3]));
        }
        mx0 = fmaxf(mx0, __shfl_xor_sync(0xffffffffu, mx0, 1));
        mx0 = fmaxf(mx0, __shfl_xor_sync(0xffffffffu, mx0, 2));
        mx1 = fmaxf(mx1, __shfl_xor_sync(0xffffffffu, mx1, 1));
        mx1 = fmaxf(mx1, __shfl_xor_sync(0xffffffffu, mx1, 2));
        float mn0 = fmaxf(m0, mx0), mn1 = fmaxf(m1, mx1);
        float al0 = __expf(m0 - mn0), al1 = __expf(m1 - mn1);
        m0 = mn0; m1 = mn1;
        float sm0 = 0.f, sm1 = 0.f;
        #pragma unroll
        for (int j = 0; j < 8; j++) {
            s[j][0] = __expf(s[j][0] - m0); sm0 += s[j][0];
            s[j][1] = __expf(s[j][1] - m0); sm0 += s[j][1];
            s[j][2] = __expf(s[j][2] - m1); sm1 += s[j][2];
            s[j][3] = __expf(s[j][3] - m1); sm1 += s[j][3];
        }
        sm0 += __shfl_xor_sync(0xffffffffu, sm0, 1);
        sm0 += __shfl_xor_sync(0xffffffffu, sm0, 2);
        sm1 += __shfl_xor_sync(0xffffffffu, sm1, 1);
        sm1 += __shfl_xor_sync(0xffffffffu, sm1, 2);
        l0 = l0 * al0 + sm0;
        l1 = l1 * al1 + sm1;
        #pragma unroll
        for (int j = 0; j < 16; j++) {
            o[j][0] *= al0; o[j][1] *= al0;
            o[j][2] *= al1; o[j][3] *= al1;
        }

        // ---- phase 2: O += P V (P hi/lo x V single: 2 terms; V trans) ----
        const uint32_t vbase = kb + FKBYTES;
        #pragma unroll
        for (int ki = 0; ki < 4; ki++) {
            uint32_t ph[4], pl[4];
            packhl_h(s[2 * ki][0],     s[2 * ki][1],     ph[0], pl[0]);
            packhl_h(s[2 * ki][2],     s[2 * ki][3],     ph[1], pl[1]);
            packhl_h(s[2 * ki + 1][0], s[2 * ki + 1][1], ph[2], pl[2]);
            packhl_h(s[2 * ki + 1][2], s[2 * ki + 1][3], ph[3], pl[3]);
            #pragma unroll
            for (int nj = 0; nj < 8; nj++) {
                uint32_t va = vbase + (ki * 16 + v_row) * FROWB + nj * 32 + v_cb;
                uint32_t h0, h1, h2, h3;
                LDSM_X4T(h0, h1, h2, h3, va);
                uint32_t vh0[2] = {h0, h1}, vh1[2] = {h2, h3};
                mma16816h(o[2 * nj],     ph, vh0);
                mma16816h(o[2 * nj + 1], ph, vh1);
                mma16816h(o[2 * nj],     pl, vh0);
                mma16816h(o[2 * nj + 1], pl, vh1);
            }
        }
        __syncthreads();   // protect KV buffer before next produce overwrites
    }

    // ---- epilogue: normalize + single fp16 write ----
    float il0 = 1.f / l0, il1 = 1.f / l1;
    int row0 = q0 + wq * 16 + er;
    #pragma unroll
    for (int j = 0; j < 16; j++) {
        int col = hh * 128 + j * 8 + ec2;
        size_t off0 = ((size_t)b * S_ + row0) * D_ + col;
        size_t off1 = ((size_t)b * S_ + row0 + 8) * D_ + col;
        *(__half2*)(oh_ + off0) = __floats2half2_rn(o[j][0] * il0, o[j][1] * il0);
        *(__half2*)(oh_ + off1) = __floats2half2_rn(o[j][2] * il1, o[j][3] * il1);
    }
}

// ---------------------------------------------------------------------------
// Launch
// ---------------------------------------------------------------------------
extern "C" void kernel_launch(void* const* d_in, const int* in_sizes, int n_in,
                              void* d_out, int out_size)
{
    (void)in_sizes; (void)n_in; (void)out_size;
    const float* x    = (const float*)d_in[0];
    const float* Wqkv = (const float*)d_in[1];
    const float* bqkv = (const float*)d_in[2];
    const float* Wo   = (const float*)d_in[3];
    const float* bo   = (const float*)d_in[4];
    float* out = (float*)d_out;

    __half *xh, *w1h, *w2h, *qh, *kh, *vh, *ah;
    cudaGetSymbolAddress((void**)&xh, g_xh);
    cudaGetSymbolAddress((void**)&w1h, g_w1h);   cudaGetSymbolAddress((void**)&w2h, g_w2h);
    cudaGetSymbolAddress((void**)&qh, g_qh);
    cudaGetSymbolAddress((void**)&kh, g_kh);     cudaGetSymbolAddress((void**)&vh, g_vh);
    cudaGetSymbolAddress((void**)&ah, g_ah);

    cudaFuncSetAttribute(gemm_qkv,
                         cudaFuncAttributeMaxDynamicSharedMemorySize, QKV_DYN_SMEM);
    cudaFuncSetAttribute(gemm_proj,
                         cudaFuncAttributeMaxDynamicSharedMemorySize, PROJ_DYN_SMEM);
    cudaFuncSetAttribute(flash_mma,
                         cudaFuncAttributeMaxDynamicSharedMemorySize, FLASH_DYN_SMEM);

    // 1) convert x to single fp16
    {
        int n4 = (M_ * D_) / 4;
        convert_f32_h<<<(n4 + 255) / 256, 256>>>(x, xh, n4);
    }
    // 2) transpose weights to [N,K] fp16
    transpose_h<<<dim3((3 * D_) / 32, D_ / 32), dim3(32, 8)>>>(Wqkv, w1h, D_, 3 * D_);
    transpose_h<<<dim3(D_ / 32, D_ / 32), dim3(32, 8)>>>(Wo, w2h, D_, D_);

    // 3) QKV GEMM (fp16x1, BN=192 -> 1024 CTAs)
    gemm_qkv<<<dim3((3 * D_) / 192, M_ / 128), 256, QKV_DYN_SMEM>>>(
        xh, w1h, bqkv, qh, kh, vh);

    // 4) HMMA flash attention (Q/K single, P hi/lo x V single)
    flash_mma<<<dim3(S_ / 128, H_, B_), 256, FLASH_DYN_SMEM>>>(
        qh, kh, vh, ah);

    // 5) out = attn @ Wo + bo  (fp16x1)
    gemm_proj<<<dim3(D_ / 256, M_ / 128), 256, PROJ_DYN_SMEM>>>(
        ah, w2h, bo, out);
}